// round 1
// baseline (speedup 1.0000x reference)
#include <cuda_runtime.h>
#include <math.h>

#define N_EMB 12544
#define M_BANK 16384
#define DIM 1536
#define BATCH 16
#define PPI 784
#define KNN 9

// ---------------- scratch (static device allocations; no runtime alloc) -------------
__device__ unsigned long long g_minpack[N_EMB];   // (ordered-float-key << 32) | col index
__device__ float g_xnorm[N_EMB];
__device__ float g_ynorm[M_BANK];
__device__ float g_score[BATCH];
__device__ int   g_maxrow[BATCH];
__device__ int   g_nnidx[BATCH];
__device__ float g_d2[BATCH * M_BANK];
__device__ int   g_support[BATCH * KNN];

// order-preserving float <-> uint key (monotone: a<b => key(a)<key(b) unsigned)
__device__ __forceinline__ unsigned fkey(float f) {
    unsigned u = __float_as_uint(f);
    return (u & 0x80000000u) ? ~u : (u | 0x80000000u);
}
__device__ __forceinline__ float unkey(unsigned k) {
    unsigned u = (k & 0x80000000u) ? (k ^ 0x80000000u) : ~k;
    return __uint_as_float(u);
}

// ---------------- row norms for embedding + memory bank ----------------
__global__ void norms_kernel(const float* __restrict__ E, const float* __restrict__ Mb) {
    int row = blockIdx.x;
    const float* p = (row < N_EMB) ? (E + (size_t)row * DIM)
                                   : (Mb + (size_t)(row - N_EMB) * DIM);
    float s = 0.f;
    for (int i = threadIdx.x; i < DIM / 4; i += blockDim.x) {
        float4 v = ((const float4*)p)[i];
        s += v.x * v.x + v.y * v.y + v.z * v.z + v.w * v.w;
    }
#pragma unroll
    for (int o = 16; o; o >>= 1) s += __shfl_down_sync(0xffffffffu, s, o);
    __shared__ float ws[4];
    if ((threadIdx.x & 31) == 0) ws[threadIdx.x >> 5] = s;
    __syncthreads();
    if (threadIdx.x == 0) {
        float t = ws[0] + ws[1] + ws[2] + ws[3];
        if (row < N_EMB) g_xnorm[row] = t;
        else             g_ynorm[row - N_EMB] = t;
    }
}

__global__ void init_kernel() {
    int i = blockIdx.x * 256 + threadIdx.x;
    if (i < N_EMB) g_minpack[i] = 0xFFFFFFFFFFFFFFFFull;
}

// ---------------- Phase A: fused dist-min GEMM ----------------
// Block: 128 rows x (4096-col chunk, iterated in 128-col tiles), K-tiled by 16.
// 256 threads, 8x8 microtile each. Running per-row (min,argmin) in registers,
// merged via packed-u64 atomicMin (ties -> lowest index, matching jax top_k).
__global__ void __launch_bounds__(256) distmin_kernel(const float* __restrict__ E,
                                                      const float* __restrict__ Mb) {
    __shared__ float As[16][128];
    __shared__ float Bs[16][128];
    const int tid = threadIdx.x;
    const int tx = tid & 15, ty = tid >> 4;
    const int rowBase = blockIdx.x * 128;
    const int chunkBase = blockIdx.y * 4096;

    float best[8]; int bestj[8];
#pragma unroll
    for (int i = 0; i < 8; i++) { best[i] = __int_as_float(0x7f800000); bestj[i] = 0x7fffffff; }

    for (int ct = 0; ct < 32; ct++) {
        const int colBase = chunkBase + ct * 128;
        float acc[8][8];
#pragma unroll
        for (int i = 0; i < 8; i++)
#pragma unroll
            for (int j = 0; j < 8; j++) acc[i][j] = 0.f;

        for (int kt = 0; kt < DIM; kt += 16) {
#pragma unroll
            for (int u = 0; u < 2; u++) {
                int f = tid + u * 256;
                int r = f >> 2, kq = (f & 3) << 2;
                float4 v = *(const float4*)(E + (size_t)(rowBase + r) * DIM + kt + kq);
                As[kq + 0][r] = v.x; As[kq + 1][r] = v.y;
                As[kq + 2][r] = v.z; As[kq + 3][r] = v.w;
                float4 w = *(const float4*)(Mb + (size_t)(colBase + r) * DIM + kt + kq);
                Bs[kq + 0][r] = w.x; Bs[kq + 1][r] = w.y;
                Bs[kq + 2][r] = w.z; Bs[kq + 3][r] = w.w;
            }
            __syncthreads();
#pragma unroll
            for (int kk = 0; kk < 16; kk++) {
                float a[8], b[8];
                *(float4*)&a[0] = *(const float4*)&As[kk][ty * 8];
                *(float4*)&a[4] = *(const float4*)&As[kk][ty * 8 + 4];
                *(float4*)&b[0] = *(const float4*)&Bs[kk][tx * 8];
                *(float4*)&b[4] = *(const float4*)&Bs[kk][tx * 8 + 4];
#pragma unroll
                for (int i = 0; i < 8; i++)
#pragma unroll
                    for (int j = 0; j < 8; j++) acc[i][j] = fmaf(a[i], b[j], acc[i][j]);
            }
            __syncthreads();
        }
        // epilogue: q = y^2 - 2*dot (x^2 is row-constant; added later)
        float yn[8];
#pragma unroll
        for (int j = 0; j < 8; j++) yn[j] = g_ynorm[colBase + tx * 8 + j];
#pragma unroll
        for (int i = 0; i < 8; i++) {
#pragma unroll
            for (int j = 0; j < 8; j++) {
                float q = fmaf(-2.f, acc[i][j], yn[j]);
                int c = colBase + tx * 8 + j;
                if (q < best[i] || (q == best[i] && c < bestj[i])) { best[i] = q; bestj[i] = c; }
            }
        }
    }
    // reduce (min, idx) across the 16 lanes sharing each row group, then global merge
#pragma unroll
    for (int i = 0; i < 8; i++) {
        float v = best[i]; int j = bestj[i];
#pragma unroll
        for (int off = 8; off; off >>= 1) {
            float ov = __shfl_down_sync(0xffffffffu, v, off, 16);
            int   oj = __shfl_down_sync(0xffffffffu, j, off, 16);
            if (ov < v || (ov == v && oj < j)) { v = ov; j = oj; }
        }
        if (tx == 0) {
            unsigned long long pk = ((unsigned long long)fkey(v) << 32) | (unsigned)j;
            atomicMin(&g_minpack[rowBase + ty * 8 + i], pk);
        }
    }
}

// ---------------- Phase B: per-image argmax of patch scores ----------------
__global__ void reduce_b_kernel() {
    int b = blockIdx.x;
    __shared__ float sv[256];
    __shared__ int   sp[256];
    float bv = -1.f; int bp = 0x7fffffff;
    for (int p = threadIdx.x; p < PPI; p += 256) {
        int r = b * PPI + p;
        unsigned long long pk = g_minpack[r];
        float q = unkey((unsigned)(pk >> 32));
        float sc = sqrtf(fmaxf(g_xnorm[r] + q, 0.f));
        if (sc > bv || (sc == bv && p < bp)) { bv = sc; bp = p; }
    }
    sv[threadIdx.x] = bv; sp[threadIdx.x] = bp;
    __syncthreads();
    for (int s = 128; s; s >>= 1) {
        if (threadIdx.x < s) {
            float ov = sv[threadIdx.x + s]; int op = sp[threadIdx.x + s];
            if (ov > sv[threadIdx.x] || (ov == sv[threadIdx.x] && op < sp[threadIdx.x])) {
                sv[threadIdx.x] = ov; sp[threadIdx.x] = op;
            }
        }
        __syncthreads();
    }
    if (threadIdx.x == 0) {
        int r = b * PPI + sp[0];
        unsigned long long pk = g_minpack[r];
        g_nnidx[b]  = (int)(pk & 0xffffffffull);
        g_maxrow[b] = r;
        g_score[b]  = sv[0];
    }
}

// ---------------- Phase C1: d^2 from 16 nn_samples to all memory rows ----------------
__global__ void knn_dist_kernel(const float* __restrict__ Mb) {
    __shared__ float Qs[16 * 384];
    __shared__ int   nn[16];
    __shared__ float qn[16];
    int tid = threadIdx.x;
    if (tid < 16) { nn[tid] = g_nnidx[tid]; qn[tid] = g_ynorm[g_nnidx[tid]]; }
    __syncthreads();
    int row = blockIdx.x * 128 + tid;
    float acc[16];
#pragma unroll
    for (int q = 0; q < 16; q++) acc[q] = 0.f;
    for (int c = 0; c < 4; c++) {
        for (int i = tid; i < 1536; i += 128) {        // i indexes float4 of the chunk
            int q = i / 96, d4 = i % 96;
            *(float4*)&Qs[q * 384 + d4 * 4] =
                *(const float4*)(Mb + (size_t)nn[q] * DIM + c * 384 + d4 * 4);
        }
        __syncthreads();
        const float4* rp = (const float4*)(Mb + (size_t)row * DIM + c * 384);
#pragma unroll 4
        for (int d4 = 0; d4 < 96; d4++) {
            float4 v = rp[d4];
#pragma unroll
            for (int q = 0; q < 16; q++) {
                float4 u = *(const float4*)&Qs[q * 384 + d4 * 4];
                acc[q] = fmaf(v.x, u.x, fmaf(v.y, u.y, fmaf(v.z, u.z, fmaf(v.w, u.w, acc[q]))));
            }
        }
        __syncthreads();
    }
    float yn = g_ynorm[row];
#pragma unroll
    for (int q = 0; q < 16; q++)
        g_d2[q * M_BANK + row] = qn[q] + yn - 2.f * acc[q];
}

// ---------------- Phase C2: stable top-9 smallest per query ----------------
__global__ void top9_kernel() {
    int b = blockIdx.x;
    float v[9]; int id[9];
#pragma unroll
    for (int k = 0; k < 9; k++) { v[k] = __int_as_float(0x7f800000); id[k] = 0x7fffffff; }
    for (int j = threadIdx.x; j < M_BANK; j += 128) {
        float d = g_d2[b * M_BANK + j];
        if (d < v[8] || (d == v[8] && j < id[8])) {
            int k = 8;
            while (k > 0 && (d < v[k - 1] || (d == v[k - 1] && j < id[k - 1]))) {
                v[k] = v[k - 1]; id[k] = id[k - 1]; k--;
            }
            v[k] = d; id[k] = j;
        }
    }
    __shared__ float svv[128 * 9];
    __shared__ int   sid[128 * 9];
#pragma unroll
    for (int k = 0; k < 9; k++) { svv[threadIdx.x * 9 + k] = v[k]; sid[threadIdx.x * 9 + k] = id[k]; }
    __syncthreads();
    if (threadIdx.x == 0) {
        float fv[9]; int fid[9];
#pragma unroll
        for (int k = 0; k < 9; k++) { fv[k] = __int_as_float(0x7f800000); fid[k] = 0x7fffffff; }
        for (int t = 0; t < 128; t++) {
            for (int k = 0; k < 9; k++) {
                float d = svv[t * 9 + k]; int j = sid[t * 9 + k];
                if (d > fv[8] || (d == fv[8] && j >= fid[8])) break;  // per-thread lists sorted
                int m = 8;
                while (m > 0 && (d < fv[m - 1] || (d == fv[m - 1] && j < fid[m - 1]))) {
                    fv[m] = fv[m - 1]; fid[m] = fid[m - 1]; m--;
                }
                fv[m] = d; fid[m] = j;
            }
        }
        for (int k = 0; k < 9; k++) g_support[b * 9 + k] = fid[k];
    }
}

// ---------------- Phase D: softmax re-weighting ----------------
__global__ void final_kernel(const float* __restrict__ E, const float* __restrict__ Mb,
                             float* __restrict__ out) {
    int b = blockIdx.x;
    int w = threadIdx.x >> 5, lane = threadIdx.x & 31;
    __shared__ float ds[9];
    const float4* x = (const float4*)(E + (size_t)g_maxrow[b] * DIM);
    const float4* y = (const float4*)(Mb + (size_t)g_support[b * 9 + w] * DIM);
    float s = 0.f;
    for (int i = lane; i < 384; i += 32) {
        float4 xv = x[i], yv = y[i];
        float dx = xv.x - yv.x, dy = xv.y - yv.y, dz = xv.z - yv.z, dw = xv.w - yv.w;
        s += dx * dx + dy * dy + dz * dz + dw * dw;
    }
#pragma unroll
    for (int o = 16; o; o >>= 1) s += __shfl_down_sync(0xffffffffu, s, o);
    if (lane == 0) ds[w] = sqrtf(fmaxf(s, 0.f));
    __syncthreads();
    if (threadIdx.x == 0) {
        float m = ds[0];
        for (int k = 1; k < 9; k++) m = fmaxf(m, ds[k]);
        float sum = 0.f, e0 = 0.f;
        for (int k = 0; k < 9; k++) {
            float e = expf(ds[k] - m);
            if (k == 0) e0 = e;
            sum += e;
        }
        out[b] = (1.f - e0 / sum) * g_score[b];
    }
}

// ---------------- launch ----------------
extern "C" void kernel_launch(void* const* d_in, const int* in_sizes, int n_in,
                              void* d_out, int out_size) {
    const float* E  = (const float*)d_in[0];
    const float* Mb = (const float*)d_in[1];
    float* out = (float*)d_out;

    norms_kernel<<<N_EMB + M_BANK, 128>>>(E, Mb);
    init_kernel<<<(N_EMB + 255) / 256, 256>>>();
    distmin_kernel<<<dim3(N_EMB / 128, 4), 256>>>(E, Mb);
    reduce_b_kernel<<<BATCH, 256>>>();
    knn_dist_kernel<<<M_BANK / 128, 128>>>(Mb);
    top9_kernel<<<BATCH, 128>>>();
    final_kernel<<<BATCH, 288>>>(E, Mb, out);
}

// round 2
// speedup vs baseline: 4.3484x; 4.3484x over previous
#include <cuda_runtime.h>
#include <math.h>
#include <stdint.h>

#define N_EMB 12544
#define M_BANK 16384
#define DIM 1536
#define BATCH 16
#define PPI 784
#define KNN 9

#define BM 128
#define BN 256
#define BK 16
#define STRIDE 20                   // padded floats per row (80B, 16B-aligned, ldmatrix conflict-free)
#define KTILES (DIM / BK)           // 96
#define AS_STAGE (BM * STRIDE)      // floats
#define BS_STAGE (BN * STRIDE)
#define SMEM_BYTES ((2 * AS_STAGE + 2 * BS_STAGE) * 4)   // 61440

// ---------------- scratch ----------------
__device__ unsigned long long g_minpack[N_EMB];
__device__ float g_xnorm[N_EMB];
__device__ float g_ynorm[M_BANK];
__device__ float g_pscore[N_EMB];
__device__ int   g_ploc[N_EMB];
__device__ float g_score[BATCH];
__device__ int   g_maxrow[BATCH];
__device__ int   g_nnidx[BATCH];
__device__ float g_d2[BATCH * M_BANK];
__device__ int   g_support[BATCH * KNN];

__device__ __forceinline__ unsigned fkey(float f) {
    unsigned u = __float_as_uint(f);
    return (u & 0x80000000u) ? ~u : (u | 0x80000000u);
}

__device__ __forceinline__ void cpasync16(uint32_t dst, const float* src) {
    asm volatile("cp.async.cg.shared.global [%0], [%1], 16;" :: "r"(dst), "l"(src));
}
__device__ __forceinline__ void ldsm4(uint32_t* r, uint32_t addr) {
    asm volatile("ldmatrix.sync.aligned.m8n8.x4.shared.b16 {%0,%1,%2,%3}, [%4];"
                 : "=r"(r[0]), "=r"(r[1]), "=r"(r[2]), "=r"(r[3]) : "r"(addr));
}
__device__ __forceinline__ void mma_tf32(float* c, const uint32_t* a, uint32_t b0, uint32_t b1) {
    asm volatile("mma.sync.aligned.m16n8k8.row.col.f32.tf32.tf32.f32 "
                 "{%0,%1,%2,%3}, {%4,%5,%6,%7}, {%8,%9}, {%0,%1,%2,%3};"
                 : "+f"(c[0]), "+f"(c[1]), "+f"(c[2]), "+f"(c[3])
                 : "r"(a[0]), "r"(a[1]), "r"(a[2]), "r"(a[3]), "r"(b0), "r"(b1));
}

// ---------------- norms ----------------
__global__ void norms_kernel(const float* __restrict__ E, const float* __restrict__ Mb) {
    int row = blockIdx.x;
    const float* p = (row < N_EMB) ? (E + (size_t)row * DIM)
                                   : (Mb + (size_t)(row - N_EMB) * DIM);
    float s = 0.f;
    for (int i = threadIdx.x; i < DIM / 4; i += blockDim.x) {
        float4 v = ((const float4*)p)[i];
        s += v.x * v.x + v.y * v.y + v.z * v.z + v.w * v.w;
    }
#pragma unroll
    for (int o = 16; o; o >>= 1) s += __shfl_down_sync(0xffffffffu, s, o);
    __shared__ float ws[4];
    if ((threadIdx.x & 31) == 0) ws[threadIdx.x >> 5] = s;
    __syncthreads();
    if (threadIdx.x == 0) {
        float t = ws[0] + ws[1] + ws[2] + ws[3];
        if (row < N_EMB) g_xnorm[row] = t;
        else             g_ynorm[row - N_EMB] = t;
    }
}

__global__ void init_kernel() {
    int i = blockIdx.x * 256 + threadIdx.x;
    if (i < N_EMB) g_minpack[i] = 0xFFFFFFFFFFFFFFFFull;
}

// ---------------- Phase A: tf32 tensor-core dist-argmin GEMM ----------------
__global__ void __launch_bounds__(512) distmin_tc(const float* __restrict__ E,
                                                  const float* __restrict__ Mb) {
    extern __shared__ float smem[];
    float* As = smem;
    float* Bs = smem + 2 * AS_STAGE;
    const int tid = threadIdx.x;
    const int lane = tid & 31, warp = tid >> 5;
    const int wr = warp & 3, wc = warp >> 2;
    const int rowBase = blockIdx.x * BM;
    const int colBase = blockIdx.y * BN;

    uint32_t sA = (uint32_t)__cvta_generic_to_shared(As);
    uint32_t sB = (uint32_t)__cvta_generic_to_shared(Bs);

    // global->smem mapping (one 16B for A, two for B, per thread per k-tile)
    const int gr = tid >> 2, gkq = (tid & 3) * 4;
    const float* agp  = E  + (size_t)(rowBase + gr) * DIM + gkq;
    const float* bgp0 = Mb + (size_t)(colBase + gr) * DIM + gkq;
    const float* bgp1 = Mb + (size_t)(colBase + 128 + gr) * DIM + gkq;
    const uint32_t adst  = sA + (gr * STRIDE + gkq) * 4;
    const uint32_t bdst0 = sB + (gr * STRIDE + gkq) * 4;
    const uint32_t bdst1 = sB + ((128 + gr) * STRIDE + gkq) * 4;

    // ldmatrix lane addressing
    const int arow = (lane & 7) + ((lane >> 3) & 1) * 8;
    const int akad = (lane >> 4) * 4;
    uint32_t aAddr[2];
#pragma unroll
    for (int m = 0; m < 2; m++)
        aAddr[m] = sA + (((wr * 32 + m * 16 + arow) * STRIDE) + akad) * 4;
    const int brow = (lane & 7) + (lane >> 4) * 8;
    const int bkad = ((lane >> 3) & 1) * 4;
    uint32_t bAddr[4];
#pragma unroll
    for (int g = 0; g < 4; g++)
        bAddr[g] = sB + (((wc * 64 + g * 16 + brow) * STRIDE) + bkad) * 4;

    float acc[2][8][4];
#pragma unroll
    for (int m = 0; m < 2; m++)
#pragma unroll
        for (int t = 0; t < 8; t++)
#pragma unroll
            for (int c = 0; c < 4; c++) acc[m][t][c] = 0.f;

    // prologue
    {
        cpasync16(adst, agp);
        cpasync16(bdst0, bgp0);
        cpasync16(bdst1, bgp1);
        asm volatile("cp.async.commit_group;");
    }

    for (int kt = 0; kt < KTILES; kt++) {
        const int st = kt & 1;
        asm volatile("cp.async.wait_group 0;");
        __syncthreads();
        if (kt + 1 < KTILES) {
            const int ko = (kt + 1) * BK;
            const uint32_t ao = ((kt + 1) & 1) * (AS_STAGE * 4);
            const uint32_t bo = ((kt + 1) & 1) * (BS_STAGE * 4);
            cpasync16(adst + ao, agp + ko);
            cpasync16(bdst0 + bo, bgp0 + ko);
            cpasync16(bdst1 + bo, bgp1 + ko);
            asm volatile("cp.async.commit_group;");
        }
        const uint32_t aoff = st * (AS_STAGE * 4);
        const uint32_t boff = st * (BS_STAGE * 4);
#pragma unroll
        for (int s = 0; s < 2; s++) {
            uint32_t af[2][4], bf[4][4];
#pragma unroll
            for (int m = 0; m < 2; m++) ldsm4(af[m], aAddr[m] + aoff + s * 32);
#pragma unroll
            for (int g = 0; g < 4; g++) ldsm4(bf[g], bAddr[g] + boff + s * 32);
#pragma unroll
            for (int m = 0; m < 2; m++)
#pragma unroll
                for (int t = 0; t < 8; t++)
                    mma_tf32(acc[m][t], af[m], bf[t >> 1][(t & 1) * 2], bf[t >> 1][(t & 1) * 2 + 1]);
        }
        __syncthreads();
    }

    // epilogue: q = y^2 - 2*dot ; argmin per row
    const int gid = lane >> 2, qid = lane & 3;
    unsigned long long* red = (unsigned long long*)smem;   // [4][128], reuses tile smem
#pragma unroll
    for (int m = 0; m < 2; m++)
#pragma unroll
        for (int h = 0; h < 2; h++) {
            float bv = __int_as_float(0x7f800000);
            int bj = 0x7fffffff;
#pragma unroll
            for (int t = 0; t < 8; t++)
#pragma unroll
                for (int c = 0; c < 2; c++) {
                    int col = colBase + wc * 64 + t * 8 + qid * 2 + c;
                    float q = fmaf(-2.f, acc[m][t][h * 2 + c], g_ynorm[col]);
                    if (q < bv || (q == bv && col < bj)) { bv = q; bj = col; }
                }
#pragma unroll
            for (int off = 1; off < 4; off <<= 1) {
                float ov = __shfl_xor_sync(0xffffffffu, bv, off, 4);
                int   oj = __shfl_xor_sync(0xffffffffu, bj, off, 4);
                if (ov < bv || (ov == bv && oj < bj)) { bv = ov; bj = oj; }
            }
            if (qid == 0) {
                int rloc = wr * 32 + m * 16 + h * 8 + gid;
                red[wc * 128 + rloc] = ((unsigned long long)fkey(bv) << 32) | (unsigned)bj;
            }
        }
    __syncthreads();
    if (tid < 128) {
        unsigned long long p = red[tid];
        unsigned long long q1 = red[128 + tid]; if (q1 < p) p = q1;
        unsigned long long q2 = red[256 + tid]; if (q2 < p) p = q2;
        unsigned long long q3 = red[384 + tid]; if (q3 < p) p = q3;
        atomicMin(&g_minpack[rowBase + tid], p);
    }
}

// ---------------- exact fp32 rescore of the selected candidate ----------------
__global__ void rescore_kernel(const float* __restrict__ E, const float* __restrict__ Mb) {
    int warp = threadIdx.x >> 5, lane = threadIdx.x & 31;
    int row = blockIdx.x * 8 + warp;
    int col = (int)(g_minpack[row] & 0xffffffffull);
    const float4* x = (const float4*)(E + (size_t)row * DIM);
    const float4* y = (const float4*)(Mb + (size_t)col * DIM);
    float s = 0.f;
    for (int i = lane; i < DIM / 4; i += 32) {
        float4 a = x[i], b = y[i];
        s += a.x * b.x + a.y * b.y + a.z * b.z + a.w * b.w;
    }
#pragma unroll
    for (int o = 16; o; o >>= 1) s += __shfl_down_sync(0xffffffffu, s, o);
    if (lane == 0) {
        float d2 = g_xnorm[row] + g_ynorm[col] - 2.f * s;
        g_pscore[row] = sqrtf(fmaxf(d2, 0.f));
        g_ploc[row] = col;
    }
}

// ---------------- Phase B ----------------
__global__ void reduce_b_kernel() {
    int b = blockIdx.x;
    __shared__ float sv[256];
    __shared__ int   sp[256];
    float bv = -1.f; int bp = 0x7fffffff;
    for (int p = threadIdx.x; p < PPI; p += 256) {
        int r = b * PPI + p;
        float sc = g_pscore[r];
        if (sc > bv || (sc == bv && p < bp)) { bv = sc; bp = p; }
    }
    sv[threadIdx.x] = bv; sp[threadIdx.x] = bp;
    __syncthreads();
    for (int s = 128; s; s >>= 1) {
        if (threadIdx.x < s) {
            float ov = sv[threadIdx.x + s]; int op = sp[threadIdx.x + s];
            if (ov > sv[threadIdx.x] || (ov == sv[threadIdx.x] && op < sp[threadIdx.x])) {
                sv[threadIdx.x] = ov; sp[threadIdx.x] = op;
            }
        }
        __syncthreads();
    }
    if (threadIdx.x == 0) {
        int r = b * PPI + sp[0];
        g_nnidx[b]  = g_ploc[r];
        g_maxrow[b] = r;
        g_score[b]  = sv[0];
    }
}

// ---------------- Phase C1 ----------------
__global__ void knn_dist_kernel(const float* __restrict__ Mb) {
    __shared__ float Qs[16 * 384];
    __shared__ int   nn[16];
    __shared__ float qn[16];
    int tid = threadIdx.x;
    if (tid < 16) { nn[tid] = g_nnidx[tid]; qn[tid] = g_ynorm[g_nnidx[tid]]; }
    __syncthreads();
    int row = blockIdx.x * 128 + tid;
    float acc[16];
#pragma unroll
    for (int q = 0; q < 16; q++) acc[q] = 0.f;
    for (int c = 0; c < 4; c++) {
        for (int i = tid; i < 1536; i += 128) {
            int q = i / 96, d4 = i % 96;
            *(float4*)&Qs[q * 384 + d4 * 4] =
                *(const float4*)(Mb + (size_t)nn[q] * DIM + c * 384 + d4 * 4);
        }
        __syncthreads();
        const float4* rp = (const float4*)(Mb + (size_t)row * DIM + c * 384);
#pragma unroll 4
        for (int d4 = 0; d4 < 96; d4++) {
            float4 v = rp[d4];
#pragma unroll
            for (int q = 0; q < 16; q++) {
                float4 u = *(const float4*)&Qs[q * 384 + d4 * 4];
                acc[q] = fmaf(v.x, u.x, fmaf(v.y, u.y, fmaf(v.z, u.z, fmaf(v.w, u.w, acc[q]))));
            }
        }
        __syncthreads();
    }
    float yn = g_ynorm[row];
#pragma unroll
    for (int q = 0; q < 16; q++)
        g_d2[q * M_BANK + row] = qn[q] + yn - 2.f * acc[q];
}

// ---------------- Phase C2 ----------------
__global__ void top9_kernel() {
    int b = blockIdx.x;
    float v[9]; int id[9];
#pragma unroll
    for (int k = 0; k < 9; k++) { v[k] = __int_as_float(0x7f800000); id[k] = 0x7fffffff; }
    for (int j = threadIdx.x; j < M_BANK; j += 128) {
        float d = g_d2[b * M_BANK + j];
        if (d < v[8] || (d == v[8] && j < id[8])) {
            int k = 8;
            while (k > 0 && (d < v[k - 1] || (d == v[k - 1] && j < id[k - 1]))) {
                v[k] = v[k - 1]; id[k] = id[k - 1]; k--;
            }
            v[k] = d; id[k] = j;
        }
    }
    __shared__ float svv[128 * 9];
    __shared__ int   sid[128 * 9];
#pragma unroll
    for (int k = 0; k < 9; k++) { svv[threadIdx.x * 9 + k] = v[k]; sid[threadIdx.x * 9 + k] = id[k]; }
    __syncthreads();
    if (threadIdx.x == 0) {
        float fv[9]; int fid[9];
#pragma unroll
        for (int k = 0; k < 9; k++) { fv[k] = __int_as_float(0x7f800000); fid[k] = 0x7fffffff; }
        for (int t = 0; t < 128; t++) {
            for (int k = 0; k < 9; k++) {
                float d = svv[t * 9 + k]; int j = sid[t * 9 + k];
                if (d > fv[8] || (d == fv[8] && j >= fid[8])) break;
                int m = 8;
                while (m > 0 && (d < fv[m - 1] || (d == fv[m - 1] && j < fid[m - 1]))) {
                    fv[m] = fv[m - 1]; fid[m] = fid[m - 1]; m--;
                }
                fv[m] = d; fid[m] = j;
            }
        }
        for (int k = 0; k < 9; k++) g_support[b * 9 + k] = fid[k];
    }
}

// ---------------- Phase D ----------------
__global__ void final_kernel(const float* __restrict__ E, const float* __restrict__ Mb,
                             float* __restrict__ out) {
    int b = blockIdx.x;
    int w = threadIdx.x >> 5, lane = threadIdx.x & 31;
    __shared__ float ds[9];
    const float4* x = (const float4*)(E + (size_t)g_maxrow[b] * DIM);
    const float4* y = (const float4*)(Mb + (size_t)g_support[b * 9 + w] * DIM);
    float s = 0.f;
    for (int i = lane; i < 384; i += 32) {
        float4 xv = x[i], yv = y[i];
        float dx = xv.x - yv.x, dy = xv.y - yv.y, dz = xv.z - yv.z, dw = xv.w - yv.w;
        s += dx * dx + dy * dy + dz * dz + dw * dw;
    }
#pragma unroll
    for (int o = 16; o; o >>= 1) s += __shfl_down_sync(0xffffffffu, s, o);
    if (lane == 0) ds[w] = sqrtf(fmaxf(s, 0.f));
    __syncthreads();
    if (threadIdx.x == 0) {
        float m = ds[0];
        for (int k = 1; k < 9; k++) m = fmaxf(m, ds[k]);
        float sum = 0.f, e0 = 0.f;
        for (int k = 0; k < 9; k++) {
            float e = expf(ds[k] - m);
            if (k == 0) e0 = e;
            sum += e;
        }
        out[b] = (1.f - e0 / sum) * g_score[b];
    }
}

// ---------------- launch ----------------
extern "C" void kernel_launch(void* const* d_in, const int* in_sizes, int n_in,
                              void* d_out, int out_size) {
    const float* E  = (const float*)d_in[0];
    const float* Mb = (const float*)d_in[1];
    float* out = (float*)d_out;

    cudaFuncSetAttribute(distmin_tc, cudaFuncAttributeMaxDynamicSharedMemorySize, SMEM_BYTES);

    norms_kernel<<<N_EMB + M_BANK, 128>>>(E, Mb);
    init_kernel<<<(N_EMB + 255) / 256, 256>>>();
    distmin_tc<<<dim3(N_EMB / BM, M_BANK / BN), 512, SMEM_BYTES>>>(E, Mb);
    rescore_kernel<<<N_EMB / 8, 256>>>(E, Mb);
    reduce_b_kernel<<<BATCH, 256>>>();
    knn_dist_kernel<<<M_BANK / 128, 128>>>(Mb);
    top9_kernel<<<BATCH, 128>>>();
    final_kernel<<<BATCH, 288>>>(E, Mb, out);
}

// round 4
// speedup vs baseline: 6.6058x; 1.5191x over previous
#include <cuda_runtime.h>
#include <cuda_bf16.h>
#include <math.h>
#include <stdint.h>

#define N_EMB 12544
#define M_BANK 16384
#define DIM 1536
#define BATCH 16
#define PPI 784
#define KNN 9

// ---- Phase A tiling (bf16 mma.m16n8k16) ----
#define BM 128
#define BN 256
#define BK 32                      // bf16 elems per k-tile (two k16 mma steps)
#define KTILES (DIM / BK)          // 48
#define NSTAGE 3
#define STRIDE 40                  // padded bf16 per row (80 B) -> conflict-free ldmatrix
#define A_BYTES (BM * STRIDE * 2)  // 10240
#define B_BYTES (BN * STRIDE * 2)  // 20480
#define STAGE_BYTES (A_BYTES + B_BYTES)   // 30720
#define SMEM_BYTES (NSTAGE * STAGE_BYTES) // 92160
#define GRIDX (N_EMB / BM)         // 98
#define GRIDY (M_BANK / BN)        // 64
#define SWG 8                      // column-band width for block swizzle

// ---------------- scratch ----------------
__device__ __nv_bfloat16 g_Eb[N_EMB * DIM];
__device__ __nv_bfloat16 g_Mb[M_BANK * DIM];
__device__ unsigned long long g_minpack[N_EMB];
__device__ unsigned long long g_nnpack[BATCH];
__device__ float g_xnorm[N_EMB];
__device__ float g_ynorm[M_BANK];
__device__ float g_pscore[N_EMB];
__device__ float g_score[BATCH];
__device__ int   g_maxrow[BATCH];
__device__ float g_d2[BATCH * M_BANK];
__device__ int   g_support[BATCH * KNN];

__device__ __forceinline__ unsigned fkey(float f) {
    unsigned u = __float_as_uint(f);
    return (u & 0x80000000u) ? ~u : (u | 0x80000000u);
}

__device__ __forceinline__ void cpasync16(uint32_t dst, const void* src) {
    asm volatile("cp.async.cg.shared.global [%0], [%1], 16;" :: "r"(dst), "l"(src));
}
__device__ __forceinline__ void ldsm4(uint32_t* r, uint32_t addr) {
    asm volatile("ldmatrix.sync.aligned.m8n8.x4.shared.b16 {%0,%1,%2,%3}, [%4];"
                 : "=r"(r[0]), "=r"(r[1]), "=r"(r[2]), "=r"(r[3]) : "r"(addr));
}
__device__ __forceinline__ void mma_bf16(float* c, const uint32_t* a, uint32_t b0, uint32_t b1) {
    asm volatile("mma.sync.aligned.m16n8k16.row.col.f32.bf16.bf16.f32 "
                 "{%0,%1,%2,%3}, {%4,%5,%6,%7}, {%8,%9}, {%0,%1,%2,%3};"
                 : "+f"(c[0]), "+f"(c[1]), "+f"(c[2]), "+f"(c[3])
                 : "r"(a[0]), "r"(a[1]), "r"(a[2]), "r"(a[3]), "r"(b0), "r"(b1));
}

// ---------------- fused convert-to-bf16 + row norms ----------------
__global__ void convert_norms_kernel(const float* __restrict__ E, const float* __restrict__ Mb) {
    int row = blockIdx.x;
    const bool isE = row < N_EMB;
    const float* p = isE ? (E + (size_t)row * DIM) : (Mb + (size_t)(row - N_EMB) * DIM);
    __nv_bfloat16* q = isE ? (g_Eb + (size_t)row * DIM) : (g_Mb + (size_t)(row - N_EMB) * DIM);
    float s = 0.f;
    for (int i = threadIdx.x; i < DIM / 4; i += blockDim.x) {
        float4 v = ((const float4*)p)[i];
        s += v.x * v.x + v.y * v.y + v.z * v.z + v.w * v.w;
        __nv_bfloat162 lo = __floats2bfloat162_rn(v.x, v.y);
        __nv_bfloat162 hi = __floats2bfloat162_rn(v.z, v.w);
        ((__nv_bfloat162*)q)[i * 2] = lo;
        ((__nv_bfloat162*)q)[i * 2 + 1] = hi;
    }
#pragma unroll
    for (int o = 16; o; o >>= 1) s += __shfl_down_sync(0xffffffffu, s, o);
    __shared__ float ws[4];
    if ((threadIdx.x & 31) == 0) ws[threadIdx.x >> 5] = s;
    __syncthreads();
    if (threadIdx.x == 0) {
        float t = ws[0] + ws[1] + ws[2] + ws[3];
        if (isE) g_xnorm[row] = t;
        else     g_ynorm[row - N_EMB] = t;
    }
}

__global__ void init_kernel() {
    int i = blockIdx.x * 256 + threadIdx.x;
    if (i < N_EMB) g_minpack[i] = 0xFFFFFFFFFFFFFFFFull;
    if (i < BATCH) g_nnpack[i] = 0xFFFFFFFFFFFFFFFFull;
}

// ---------------- Phase A: bf16 tensor-core dist-argmin GEMM ----------------
__global__ void __launch_bounds__(512) distmin_bf16() {
    extern __shared__ char dsm[];
    const int tid = threadIdx.x;
    const int lane = tid & 31, warp = tid >> 5;
    const int wr = warp & 3, wc = warp >> 2;

    // block swizzle: bands of SWG column tiles
    const int band = blockIdx.x / (GRIDX * SWG);
    const int rem  = blockIdx.x % (GRIDX * SWG);
    const int by   = band * SWG + (rem % SWG);
    const int bx   = rem / SWG;
    const int rowBase = bx * BM;
    const int colBase = by * BN;

    uint32_t sbase = (uint32_t)__cvta_generic_to_shared(dsm);

    // cp.async mapping: 3 x 16B chunks per thread per stage
    // A: 128 rows x 4 chunks = 512 ; B: 256 rows x 4 chunks = 1024
    const __nv_bfloat16* src[3];
    uint32_t dsto[3];
#pragma unroll
    for (int i = 0; i < 3; i++) {
        int idx = tid + i * 512;
        if (idx < 512) {
            int row = idx >> 2, c = idx & 3;
            src[i]  = g_Eb + (size_t)(rowBase + row) * DIM + c * 8;
            dsto[i] = row * (STRIDE * 2) + c * 16;
        } else {
            int j = idx - 512;
            int row = j >> 2, c = j & 3;
            src[i]  = g_Mb + (size_t)(colBase + row) * DIM + c * 8;
            dsto[i] = A_BYTES + row * (STRIDE * 2) + c * 16;
        }
    }

    // ldmatrix lane addressing (byte offsets within stage)
    const int arow = (lane & 7) + ((lane >> 3) & 1) * 8;   // A: m-row within 16
    const uint32_t akb = (lane >> 4) * 16;                 // A: k-halfword group
    uint32_t aAddr[2];
#pragma unroll
    for (int m = 0; m < 2; m++)
        aAddr[m] = sbase + (wr * 32 + m * 16 + arow) * (STRIDE * 2) + akb;
    const int brow = (lane & 7) + (lane >> 4) * 8;         // B: n-row within 16
    const uint32_t bkb = ((lane >> 3) & 1) * 16;
    uint32_t bAddr[4];
#pragma unroll
    for (int g = 0; g < 4; g++)
        bAddr[g] = sbase + A_BYTES + (wc * 64 + g * 16 + brow) * (STRIDE * 2) + bkb;

    float acc[2][8][4];
#pragma unroll
    for (int m = 0; m < 2; m++)
#pragma unroll
        for (int t = 0; t < 8; t++)
#pragma unroll
            for (int c = 0; c < 4; c++) acc[m][t][c] = 0.f;

    // prologue: issue stages 0,1
#pragma unroll
    for (int s = 0; s < NSTAGE - 1; s++) {
#pragma unroll
        for (int i = 0; i < 3; i++) cpasync16(sbase + s * STAGE_BYTES + dsto[i], src[i] + s * BK);
        asm volatile("cp.async.commit_group;");
    }

    for (int kt = 0; kt < KTILES; kt++) {
        const int st = kt % NSTAGE;
        asm volatile("cp.async.wait_group %0;" :: "n"(NSTAGE - 2));
        __syncthreads();
        if (kt + NSTAGE - 1 < KTILES) {
            const int ps = (kt + NSTAGE - 1) % NSTAGE;
            const int ko = (kt + NSTAGE - 1) * BK;
#pragma unroll
            for (int i = 0; i < 3; i++) cpasync16(sbase + ps * STAGE_BYTES + dsto[i], src[i] + ko);
            asm volatile("cp.async.commit_group;");
        }
        const uint32_t so = st * STAGE_BYTES;
#pragma unroll
        for (int s = 0; s < 2; s++) {            // two k16 steps per k-tile
            uint32_t af[2][4], bf[4][4];
#pragma unroll
            for (int m = 0; m < 2; m++) ldsm4(af[m], aAddr[m] + so + s * 32);
#pragma unroll
            for (int g = 0; g < 4; g++) ldsm4(bf[g], bAddr[g] + so + s * 32);
#pragma unroll
            for (int m = 0; m < 2; m++)
#pragma unroll
                for (int t = 0; t < 8; t++)
                    mma_bf16(acc[m][t], af[m], bf[t >> 1][(t & 1) * 2], bf[t >> 1][(t & 1) * 2 + 1]);
        }
        __syncthreads();
    }

    // epilogue: q = y^2 - 2*dot ; per-row argmin (ties -> lowest col)
    const int gid = lane >> 2, qid = lane & 3;
    unsigned long long* red = (unsigned long long*)dsm;   // [4][128]
#pragma unroll
    for (int m = 0; m < 2; m++)
#pragma unroll
        for (int h = 0; h < 2; h++) {
            float bv = __int_as_float(0x7f800000);
            int bj = 0x7fffffff;
#pragma unroll
            for (int t = 0; t < 8; t++)
#pragma unroll
                for (int c = 0; c < 2; c++) {
                    int col = colBase + wc * 64 + t * 8 + qid * 2 + c;
                    float q = fmaf(-2.f, acc[m][t][h * 2 + c], g_ynorm[col]);
                    if (q < bv || (q == bv && col < bj)) { bv = q; bj = col; }
                }
#pragma unroll
            for (int off = 1; off < 4; off <<= 1) {
                float ov = __shfl_xor_sync(0xffffffffu, bv, off, 4);
                int   oj = __shfl_xor_sync(0xffffffffu, bj, off, 4);
                if (ov < bv || (ov == bv && oj < bj)) { bv = ov; bj = oj; }
            }
            if (qid == 0) {
                int rloc = wr * 32 + m * 16 + h * 8 + gid;
                red[wc * 128 + rloc] = ((unsigned long long)fkey(bv) << 32) | (unsigned)bj;
            }
        }
    __syncthreads();
    if (tid < BM) {
        unsigned long long p = red[tid];
        unsigned long long q1 = red[128 + tid]; if (q1 < p) p = q1;
        unsigned long long q2 = red[256 + tid]; if (q2 < p) p = q2;
        unsigned long long q3 = red[384 + tid]; if (q3 < p) p = q3;
        atomicMin(&g_minpack[rowBase + tid], p);
    }
}

// ---------------- exact fp32 rescore of selected candidates ----------------
__global__ void rescore_kernel(const float* __restrict__ E, const float* __restrict__ Mb) {
    int warp = threadIdx.x >> 5, lane = threadIdx.x & 31;
    int row = blockIdx.x * 8 + warp;
    int col = (int)(g_minpack[row] & 0xffffffffull);
    const float4* x = (const float4*)(E + (size_t)row * DIM);
    const float4* y = (const float4*)(Mb + (size_t)col * DIM);
    float s = 0.f;
    for (int i = lane; i < DIM / 4; i += 32) {
        float4 a = x[i], b = y[i];
        s += a.x * b.x + a.y * b.y + a.z * b.z + a.w * b.w;
    }
#pragma unroll
    for (int o = 16; o; o >>= 1) s += __shfl_down_sync(0xffffffffu, s, o);
    if (lane == 0) {
        float d2 = g_xnorm[row] + g_ynorm[col] - 2.f * s;
        g_pscore[row] = sqrtf(fmaxf(d2, 0.f));
    }
}

// ---------------- Phase B: per-image argmax (exact scores) ----------------
__global__ void reduce_b_kernel() {
    int b = blockIdx.x;
    __shared__ float sv[256];
    __shared__ int   sp[256];
    float bv = -1.f; int bp = 0x7fffffff;
    for (int p = threadIdx.x; p < PPI; p += 256) {
        float sc = g_pscore[b * PPI + p];
        if (sc > bv || (sc == bv && p < bp)) { bv = sc; bp = p; }
    }
    sv[threadIdx.x] = bv; sp[threadIdx.x] = bp;
    __syncthreads();
    for (int s = 128; s; s >>= 1) {
        if (threadIdx.x < s) {
            float ov = sv[threadIdx.x + s]; int op = sp[threadIdx.x + s];
            if (ov > sv[threadIdx.x] || (ov == sv[threadIdx.x] && op < sp[threadIdx.x])) {
                sv[threadIdx.x] = ov; sp[threadIdx.x] = op;
            }
        }
        __syncthreads();
    }
    if (threadIdx.x == 0) {
        g_maxrow[b] = b * PPI + sp[0];
        g_score[b]  = sv[0];
    }
}

// ---------------- exact fp32 NN search for the 16 argmax rows ----------------
__global__ void exactnn_kernel(const float* __restrict__ E, const float* __restrict__ Mb) {
    __shared__ float Qs[16 * 384];
    __shared__ int   qr[16];
    __shared__ unsigned long long part[16];
    int tid = threadIdx.x;
    if (tid < 16) { qr[tid] = g_maxrow[tid]; part[tid] = 0xFFFFFFFFFFFFFFFFull; }
    __syncthreads();
    int col = blockIdx.x * 128 + tid;
    float acc[16];
#pragma unroll
    for (int q = 0; q < 16; q++) acc[q] = 0.f;
    for (int c = 0; c < 4; c++) {
        for (int i = tid; i < 1536; i += 128) {
            int q = i / 96, d4 = i % 96;
            *(float4*)&Qs[q * 384 + d4 * 4] =
                *(const float4*)(E + (size_t)qr[q] * DIM + c * 384 + d4 * 4);
        }
        __syncthreads();
        const float4* rp = (const float4*)(Mb + (size_t)col * DIM + c * 384);
#pragma unroll 4
        for (int d4 = 0; d4 < 96; d4++) {
            float4 v = rp[d4];
#pragma unroll
            for (int q = 0; q < 16; q++) {
                float4 u = *(const float4*)&Qs[q * 384 + d4 * 4];
                acc[q] = fmaf(v.x, u.x, fmaf(v.y, u.y, fmaf(v.z, u.z, fmaf(v.w, u.w, acc[q]))));
            }
        }
        __syncthreads();
    }
    float yn = g_ynorm[col];
#pragma unroll
    for (int q = 0; q < 16; q++) {
        float d2 = g_xnorm[qr[q]] + yn - 2.f * acc[q];
        unsigned long long pk = ((unsigned long long)fkey(d2) << 32) | (unsigned)col;
        atomicMin(&part[q], pk);
    }
    __syncthreads();
    if (tid < 16) atomicMin(&g_nnpack[tid], part[tid]);
}

// ---------------- Phase C1: d^2 from 16 nn_samples to all memory rows ----------------
__global__ void knn_dist_kernel(const float* __restrict__ Mb) {
    __shared__ float Qs[16 * 384];
    __shared__ int   nn[16];
    __shared__ float qn[16];
    int tid = threadIdx.x;
    if (tid < 16) {
        int idx = (int)(g_nnpack[tid] & 0xffffffffull);
        nn[tid] = idx; qn[tid] = g_ynorm[idx];
    }
    __syncthreads();
    int row = blockIdx.x * 128 + tid;
    float acc[16];
#pragma unroll
    for (int q = 0; q < 16; q++) acc[q] = 0.f;
    for (int c = 0; c < 4; c++) {
        for (int i = tid; i < 1536; i += 128) {
            int q = i / 96, d4 = i % 96;
            *(float4*)&Qs[q * 384 + d4 * 4] =
                *(const float4*)(Mb + (size_t)nn[q] * DIM + c * 384 + d4 * 4);
        }
        __syncthreads();
        const float4* rp = (const float4*)(Mb + (size_t)row * DIM + c * 384);
#pragma unroll 4
        for (int d4 = 0; d4 < 96; d4++) {
            float4 v = rp[d4];
#pragma unroll
            for (int q = 0; q < 16; q++) {
                float4 u = *(const float4*)&Qs[q * 384 + d4 * 4];
                acc[q] = fmaf(v.x, u.x, fmaf(v.y, u.y, fmaf(v.z, u.z, fmaf(v.w, u.w, acc[q]))));
            }
        }
        __syncthreads();
    }
    float yn = g_ynorm[row];
#pragma unroll
    for (int q = 0; q < 16; q++)
        g_d2[q * M_BANK + row] = qn[q] + yn - 2.f * acc[q];
}

// ---------------- Phase C2: stable top-9 ----------------
__global__ void top9_kernel() {
    int b = blockIdx.x;
    float v[9]; int id[9];
#pragma unroll
    for (int k = 0; k < 9; k++) { v[k] = __int_as_float(0x7f800000); id[k] = 0x7fffffff; }
    for (int j = threadIdx.x; j < M_BANK; j += 128) {
        float d = g_d2[b * M_BANK + j];
        if (d < v[8] || (d == v[8] && j < id[8])) {
            int k = 8;
            while (k > 0 && (d < v[k - 1] || (d == v[k - 1] && j < id[k - 1]))) {
                v[k] = v[k - 1]; id[k] = id[k - 1]; k--;
            }
            v[k] = d; id[k] = j;
        }
    }
    __shared__ float svv[128 * 9];
    __shared__ int   sid[128 * 9];
#pragma unroll
    for (int k = 0; k < 9; k++) { svv[threadIdx.x * 9 + k] = v[k]; sid[threadIdx.x * 9 + k] = id[k]; }
    __syncthreads();
    if (threadIdx.x == 0) {
        float fv[9]; int fid[9];
#pragma unroll
        for (int k = 0; k < 9; k++) { fv[k] = __int_as_float(0x7f800000); fid[k] = 0x7fffffff; }
        for (int t = 0; t < 128; t++) {
            for (int k = 0; k < 9; k++) {
                float d = svv[t * 9 + k]; int j = sid[t * 9 + k];
                if (d > fv[8] || (d == fv[8] && j >= fid[8])) break;
                int m = 8;
                while (m > 0 && (d < fv[m - 1] || (d == fv[m - 1] && j < fid[m - 1]))) {
                    fv[m] = fv[m - 1]; fid[m] = fid[m - 1]; m--;
                }
                fv[m] = d; fid[m] = j;
            }
        }
        for (int k = 0; k < 9; k++) g_support[b * 9 + k] = fid[k];
    }
}

// ---------------- Phase D ----------------
__global__ void final_kernel(const float* __restrict__ E, const float* __restrict__ Mb,
                             float* __restrict__ out) {
    int b = blockIdx.x;
    int w = threadIdx.x >> 5, lane = threadIdx.x & 31;
    __shared__ float ds[9];
    const float4* x = (const float4*)(E + (size_t)g_maxrow[b] * DIM);
    const float4* y = (const float4*)(Mb + (size_t)g_support[b * 9 + w] * DIM);
    float s = 0.f;
    for (int i = lane; i < 384; i += 32) {
        float4 xv = x[i], yv = y[i];
        float dx = xv.x - yv.x, dy = xv.y - yv.y, dz = xv.z - yv.z, dw = xv.w - yv.w;
        s += dx * dx + dy * dy + dz * dz + dw * dw;
    }
#pragma unroll
    for (int o = 16; o; o >>= 1) s += __shfl_down_sync(0xffffffffu, s, o);
    if (lane == 0) ds[w] = sqrtf(fmaxf(s, 0.f));
    __syncthreads();
    if (threadIdx.x == 0) {
        float m = ds[0];
        for (int k = 1; k < 9; k++) m = fmaxf(m, ds[k]);
        float sum = 0.f, e0 = 0.f;
        for (int k = 0; k < 9; k++) {
            float e = expf(ds[k] - m);
            if (k == 0) e0 = e;
            sum += e;
        }
        out[b] = (1.f - e0 / sum) * g_score[b];
    }
}

// ---------------- launch ----------------
extern "C" void kernel_launch(void* const* d_in, const int* in_sizes, int n_in,
                              void* d_out, int out_size) {
    const float* E  = (const float*)d_in[0];
    const float* Mb = (const float*)d_in[1];
    float* out = (float*)d_out;

    cudaFuncSetAttribute(distmin_bf16, cudaFuncAttributeMaxDynamicSharedMemorySize, SMEM_BYTES);

    convert_norms_kernel<<<N_EMB + M_BANK, 128>>>(E, Mb);
    init_kernel<<<(N_EMB + 255) / 256, 256>>>();
    distmin_bf16<<<GRIDX * GRIDY, 512, SMEM_BYTES>>>();
    rescore_kernel<<<N_EMB / 8, 256>>>(E, Mb);
    reduce_b_kernel<<<BATCH, 256>>>();
    exactnn_kernel<<<M_BANK / 128, 128>>>(E, Mb);
    knn_dist_kernel<<<M_BANK / 128, 128>>>(Mb);
    top9_kernel<<<BATCH, 128>>>();
    final_kernel<<<BATCH, 288>>>(E, Mb, out);
}

// round 5
// speedup vs baseline: 11.5095x; 1.7423x over previous
#include <cuda_runtime.h>
#include <cuda_bf16.h>
#include <math.h>
#include <stdint.h>

#define N_EMB 12544
#define M_BANK 16384
#define DIM 1536
#define BATCH 16
#define PPI 784
#define KNN 9

// ---- Phase A tiling (int8 mma.m16n8k32) ----
#define BM 128
#define BN 256
#define BK 64                      // int8 elems per k-tile (two k32 mma steps)
#define KTILES (DIM / BK)          // 24
#define NSTAGE 3
#define STRIDE_B 80                // padded bytes per row (64 data + 16 pad) -> conflict-free
#define A_BYTES (BM * STRIDE_B)    // 10240
#define B_BYTES (BN * STRIDE_B)    // 20480
#define STAGE_BYTES (A_BYTES + B_BYTES)   // 30720
#define SMEM_BYTES (NSTAGE * STAGE_BYTES) // 92160
#define GRIDX (N_EMB / BM)         // 98
#define GRIDY (M_BANK / BN)        // 64
#define SWG 8                      // column-band width for block swizzle

#define QSCALE 23.0f               // int8 quantization scale (covers ~±5.5 sigma)

// ---------------- scratch ----------------
__device__ char  g_E8[N_EMB * DIM];
__device__ char  g_M8[M_BANK * DIM];
__device__ int   g_ynq[M_BANK];            // integer quant-norms of memory bank
__device__ unsigned long long g_minpack[N_EMB];
__device__ unsigned long long g_nnpack[BATCH];
__device__ float g_xnorm[N_EMB];
__device__ float g_ynorm[M_BANK];
__device__ float g_pscore[N_EMB];
__device__ float g_score[BATCH];
__device__ int   g_maxrow[BATCH];
__device__ float g_d2[BATCH * M_BANK];
__device__ int   g_support[BATCH * KNN];

__device__ __forceinline__ unsigned fkey(float f) {
    unsigned u = __float_as_uint(f);
    return (u & 0x80000000u) ? ~u : (u | 0x80000000u);
}

__device__ __forceinline__ void cpasync16(uint32_t dst, const void* src) {
    asm volatile("cp.async.cg.shared.global [%0], [%1], 16;" :: "r"(dst), "l"(src));
}
__device__ __forceinline__ void ldsm4(uint32_t* r, uint32_t addr) {
    asm volatile("ldmatrix.sync.aligned.m8n8.x4.shared.b16 {%0,%1,%2,%3}, [%4];"
                 : "=r"(r[0]), "=r"(r[1]), "=r"(r[2]), "=r"(r[3]) : "r"(addr));
}
__device__ __forceinline__ void mma_s8(int* c, const uint32_t* a, uint32_t b0, uint32_t b1) {
    asm volatile("mma.sync.aligned.m16n8k32.row.col.s32.s8.s8.s32 "
                 "{%0,%1,%2,%3}, {%4,%5,%6,%7}, {%8,%9}, {%0,%1,%2,%3};"
                 : "+r"(c[0]), "+r"(c[1]), "+r"(c[2]), "+r"(c[3])
                 : "r"(a[0]), "r"(a[1]), "r"(a[2]), "r"(a[3]), "r"(b0), "r"(b1));
}

__device__ __forceinline__ int q8(float x) {
    int v = __float2int_rn(x * QSCALE);
    return max(-127, min(127, v));
}

// ---------------- fused convert-to-int8 + norms (float and integer) ----------------
__global__ void convert_norms_kernel(const float* __restrict__ E, const float* __restrict__ Mb) {
    int row = blockIdx.x;
    const bool isE = row < N_EMB;
    const float* p = isE ? (E + (size_t)row * DIM) : (Mb + (size_t)(row - N_EMB) * DIM);
    char* q = isE ? (g_E8 + (size_t)row * DIM) : (g_M8 + (size_t)(row - N_EMB) * DIM);
    float s = 0.f;
    int   sq = 0;
    for (int i = threadIdx.x; i < DIM / 4; i += blockDim.x) {
        float4 v = ((const float4*)p)[i];
        s += v.x * v.x + v.y * v.y + v.z * v.z + v.w * v.w;
        int a = q8(v.x), b = q8(v.y), c = q8(v.z), d = q8(v.w);
        sq += a * a + b * b + c * c + d * d;
        uint32_t pk = (uint32_t)(a & 0xff) | ((uint32_t)(b & 0xff) << 8) |
                      ((uint32_t)(c & 0xff) << 16) | ((uint32_t)(d & 0xff) << 24);
        ((uint32_t*)q)[i] = pk;
    }
#pragma unroll
    for (int o = 16; o; o >>= 1) {
        s  += __shfl_down_sync(0xffffffffu, s, o);
        sq += __shfl_down_sync(0xffffffffu, sq, o);
    }
    __shared__ float ws[4];
    __shared__ int   wq[4];
    if ((threadIdx.x & 31) == 0) { ws[threadIdx.x >> 5] = s; wq[threadIdx.x >> 5] = sq; }
    __syncthreads();
    if (threadIdx.x == 0) {
        float t = ws[0] + ws[1] + ws[2] + ws[3];
        int   ti = wq[0] + wq[1] + wq[2] + wq[3];
        if (isE) g_xnorm[row] = t;
        else   { g_ynorm[row - N_EMB] = t; g_ynq[row - N_EMB] = ti; }
    }
}

__global__ void init_kernel() {
    int i = blockIdx.x * 256 + threadIdx.x;
    if (i < N_EMB) g_minpack[i] = 0xFFFFFFFFFFFFFFFFull;
    if (i < BATCH) g_nnpack[i] = 0xFFFFFFFFFFFFFFFFull;
}

// ---------------- Phase A: int8 tensor-core dist-argmin GEMM ----------------
__global__ void __launch_bounds__(512) distmin_s8() {
    extern __shared__ char dsm[];
    const int tid = threadIdx.x;
    const int lane = tid & 31, warp = tid >> 5;
    const int wr = warp & 3, wc = warp >> 2;

    // block swizzle: bands of SWG column tiles
    const int band = blockIdx.x / (GRIDX * SWG);
    const int rem  = blockIdx.x % (GRIDX * SWG);
    const int by   = band * SWG + (rem % SWG);
    const int bx   = rem / SWG;
    const int rowBase = bx * BM;
    const int colBase = by * BN;

    uint32_t sbase = (uint32_t)__cvta_generic_to_shared(dsm);

    // cp.async mapping: 3 x 16B chunks per thread per stage
    // A: 128 rows x 4 chunks = 512 ; B: 256 rows x 4 chunks = 1024
    const char* src[3];
    uint32_t dsto[3];
#pragma unroll
    for (int i = 0; i < 3; i++) {
        int idx = tid + i * 512;
        if (idx < 512) {
            int row = idx >> 2, c = idx & 3;
            src[i]  = g_E8 + (size_t)(rowBase + row) * DIM + c * 16;
            dsto[i] = row * STRIDE_B + c * 16;
        } else {
            int j = idx - 512;
            int row = j >> 2, c = j & 3;
            src[i]  = g_M8 + (size_t)(colBase + row) * DIM + c * 16;
            dsto[i] = A_BYTES + row * STRIDE_B + c * 16;
        }
    }

    // ldmatrix lane addressing (byte offsets within stage); k32-step = 32B of a row
    const int arow = (lane & 7) + ((lane >> 3) & 1) * 8;
    const uint32_t akb = (lane >> 4) * 16;
    uint32_t aAddr[2];
#pragma unroll
    for (int m = 0; m < 2; m++)
        aAddr[m] = sbase + (wr * 32 + m * 16 + arow) * STRIDE_B + akb;
    const int brow = (lane & 7) + (lane >> 4) * 8;
    const uint32_t bkb = ((lane >> 3) & 1) * 16;
    uint32_t bAddr[4];
#pragma unroll
    for (int g = 0; g < 4; g++)
        bAddr[g] = sbase + A_BYTES + (wc * 64 + g * 16 + brow) * STRIDE_B + bkb;

    int acc[2][8][4];
#pragma unroll
    for (int m = 0; m < 2; m++)
#pragma unroll
        for (int t = 0; t < 8; t++)
#pragma unroll
            for (int c = 0; c < 4; c++) acc[m][t][c] = 0;

    // prologue: issue stages 0,1
#pragma unroll
    for (int s = 0; s < NSTAGE - 1; s++) {
#pragma unroll
        for (int i = 0; i < 3; i++) cpasync16(sbase + s * STAGE_BYTES + dsto[i], src[i] + s * BK);
        asm volatile("cp.async.commit_group;");
    }

    for (int kt = 0; kt < KTILES; kt++) {
        const int st = kt % NSTAGE;
        asm volatile("cp.async.wait_group %0;" :: "n"(NSTAGE - 2));
        __syncthreads();
        if (kt + NSTAGE - 1 < KTILES) {
            const int ps = (kt + NSTAGE - 1) % NSTAGE;
            const int ko = (kt + NSTAGE - 1) * BK;
#pragma unroll
            for (int i = 0; i < 3; i++) cpasync16(sbase + ps * STAGE_BYTES + dsto[i], src[i] + ko);
            asm volatile("cp.async.commit_group;");
        }
        const uint32_t so = st * STAGE_BYTES;
#pragma unroll
        for (int s = 0; s < 2; s++) {            // two k32 steps per k-tile
            uint32_t af[2][4], bf[4][4];
#pragma unroll
            for (int m = 0; m < 2; m++) ldsm4(af[m], aAddr[m] + so + s * 32);
#pragma unroll
            for (int g = 0; g < 4; g++) ldsm4(bf[g], bAddr[g] + so + s * 32);
#pragma unroll
            for (int m = 0; m < 2; m++)
#pragma unroll
                for (int t = 0; t < 8; t++)
                    mma_s8(acc[m][t], af[m], bf[t >> 1][(t & 1) * 2], bf[t >> 1][(t & 1) * 2 + 1]);
        }
        __syncthreads();
    }

    // epilogue: integer q = ynq - 2*dot ; per-row argmin (ties -> lowest col)
    const int gid = lane >> 2, qid = lane & 3;
    unsigned long long* red = (unsigned long long*)dsm;   // [4][128]
#pragma unroll
    for (int m = 0; m < 2; m++)
#pragma unroll
        for (int h = 0; h < 2; h++) {
            int bv = 0x7fffffff;
            int bj = 0x7fffffff;
#pragma unroll
            for (int t = 0; t < 8; t++)
#pragma unroll
                for (int c = 0; c < 2; c++) {
                    int col = colBase + wc * 64 + t * 8 + qid * 2 + c;
                    int q = g_ynq[col] - 2 * acc[m][t][h * 2 + c];
                    if (q < bv || (q == bv && col < bj)) { bv = q; bj = col; }
                }
#pragma unroll
            for (int off = 1; off < 4; off <<= 1) {
                int ov = __shfl_xor_sync(0xffffffffu, bv, off, 4);
                int oj = __shfl_xor_sync(0xffffffffu, bj, off, 4);
                if (ov < bv || (ov == bv && oj < bj)) { bv = ov; bj = oj; }
            }
            if (qid == 0) {
                int rloc = wr * 32 + m * 16 + h * 8 + gid;
                unsigned ku = (unsigned)bv ^ 0x80000000u;   // signed-order-preserving
                red[wc * 128 + rloc] = ((unsigned long long)ku << 32) | (unsigned)bj;
            }
        }
    __syncthreads();
    if (tid < BM) {
        unsigned long long p = red[tid];
        unsigned long long q1 = red[128 + tid]; if (q1 < p) p = q1;
        unsigned long long q2 = red[256 + tid]; if (q2 < p) p = q2;
        unsigned long long q3 = red[384 + tid]; if (q3 < p) p = q3;
        atomicMin(&g_minpack[rowBase + tid], p);
    }
}

// ---------------- exact fp32 rescore of selected candidates ----------------
__global__ void rescore_kernel(const float* __restrict__ E, const float* __restrict__ Mb) {
    int warp = threadIdx.x >> 5, lane = threadIdx.x & 31;
    int row = blockIdx.x * 8 + warp;
    int col = (int)(g_minpack[row] & 0xffffffffull);
    const float4* x = (const float4*)(E + (size_t)row * DIM);
    const float4* y = (const float4*)(Mb + (size_t)col * DIM);
    float s = 0.f;
    for (int i = lane; i < DIM / 4; i += 32) {
        float4 a = x[i], b = y[i];
        s += a.x * b.x + a.y * b.y + a.z * b.z + a.w * b.w;
    }
#pragma unroll
    for (int o = 16; o; o >>= 1) s += __shfl_down_sync(0xffffffffu, s, o);
    if (lane == 0) {
        float d2 = g_xnorm[row] + g_ynorm[col] - 2.f * s;
        g_pscore[row] = sqrtf(fmaxf(d2, 0.f));
    }
}

// ---------------- Phase B: per-image argmax (exact scores) ----------------
__global__ void reduce_b_kernel() {
    int b = blockIdx.x;
    __shared__ float sv[256];
    __shared__ int   sp[256];
    float bv = -1.f; int bp = 0x7fffffff;
    for (int p = threadIdx.x; p < PPI; p += 256) {
        float sc = g_pscore[b * PPI + p];
        if (sc > bv || (sc == bv && p < bp)) { bv = sc; bp = p; }
    }
    sv[threadIdx.x] = bv; sp[threadIdx.x] = bp;
    __syncthreads();
    for (int s = 128; s; s >>= 1) {
        if (threadIdx.x < s) {
            float ov = sv[threadIdx.x + s]; int op = sp[threadIdx.x + s];
            if (ov > sv[threadIdx.x] || (ov == sv[threadIdx.x] && op < sp[threadIdx.x])) {
                sv[threadIdx.x] = ov; sp[threadIdx.x] = op;
            }
        }
        __syncthreads();
    }
    if (threadIdx.x == 0) {
        g_maxrow[b] = b * PPI + sp[0];
        g_score[b]  = sv[0];
    }
}

// ---------------- exact fp32 NN search for the 16 argmax rows ----------------
__global__ void exactnn_kernel(const float* __restrict__ E, const float* __restrict__ Mb) {
    __shared__ float Qs[16 * 384];
    __shared__ int   qr[16];
    __shared__ unsigned long long part[16];
    int tid = threadIdx.x;
    if (tid < 16) { qr[tid] = g_maxrow[tid]; part[tid] = 0xFFFFFFFFFFFFFFFFull; }
    __syncthreads();
    int col = blockIdx.x * 128 + tid;
    float acc[16];
#pragma unroll
    for (int q = 0; q < 16; q++) acc[q] = 0.f;
    for (int c = 0; c < 4; c++) {
        for (int i = tid; i < 1536; i += 128) {
            int q = i / 96, d4 = i % 96;
            *(float4*)&Qs[q * 384 + d4 * 4] =
                *(const float4*)(E + (size_t)qr[q] * DIM + c * 384 + d4 * 4);
        }
        __syncthreads();
        const float4* rp = (const float4*)(Mb + (size_t)col * DIM + c * 384);
#pragma unroll 4
        for (int d4 = 0; d4 < 96; d4++) {
            float4 v = rp[d4];
#pragma unroll
            for (int q = 0; q < 16; q++) {
                float4 u = *(const float4*)&Qs[q * 384 + d4 * 4];
                acc[q] = fmaf(v.x, u.x, fmaf(v.y, u.y, fmaf(v.z, u.z, fmaf(v.w, u.w, acc[q]))));
            }
        }
        __syncthreads();
    }
    float yn = g_ynorm[col];
#pragma unroll
    for (int q = 0; q < 16; q++) {
        float d2 = g_xnorm[qr[q]] + yn - 2.f * acc[q];
        unsigned long long pk = ((unsigned long long)fkey(d2) << 32) | (unsigned)col;
        atomicMin(&part[q], pk);
    }
    __syncthreads();
    if (tid < 16) atomicMin(&g_nnpack[tid], part[tid]);
}

// ---------------- Phase C1: d^2 from 16 nn_samples to all memory rows ----------------
__global__ void knn_dist_kernel(const float* __restrict__ Mb) {
    __shared__ float Qs[16 * 384];
    __shared__ int   nn[16];
    __shared__ float qn[16];
    int tid = threadIdx.x;
    if (tid < 16) {
        int idx = (int)(g_nnpack[tid] & 0xffffffffull);
        nn[tid] = idx; qn[tid] = g_ynorm[idx];
    }
    __syncthreads();
    int row = blockIdx.x * 128 + tid;
    float acc[16];
#pragma unroll
    for (int q = 0; q < 16; q++) acc[q] = 0.f;
    for (int c = 0; c < 4; c++) {
        for (int i = tid; i < 1536; i += 128) {
            int q = i / 96, d4 = i % 96;
            *(float4*)&Qs[q * 384 + d4 * 4] =
                *(const float4*)(Mb + (size_t)nn[q] * DIM + c * 384 + d4 * 4);
        }
        __syncthreads();
        const float4* rp = (const float4*)(Mb + (size_t)row * DIM + c * 384);
#pragma unroll 4
        for (int d4 = 0; d4 < 96; d4++) {
            float4 v = rp[d4];
#pragma unroll
            for (int q = 0; q < 16; q++) {
                float4 u = *(const float4*)&Qs[q * 384 + d4 * 4];
                acc[q] = fmaf(v.x, u.x, fmaf(v.y, u.y, fmaf(v.z, u.z, fmaf(v.w, u.w, acc[q]))));
            }
        }
        __syncthreads();
    }
    float yn = g_ynorm[row];
#pragma unroll
    for (int q = 0; q < 16; q++)
        g_d2[q * M_BANK + row] = qn[q] + yn - 2.f * acc[q];
}

// ---------------- Phase C2: stable top-9 ----------------
__global__ void top9_kernel() {
    int b = blockIdx.x;
    float v[9]; int id[9];
#pragma unroll
    for (int k = 0; k < 9; k++) { v[k] = __int_as_float(0x7f800000); id[k] = 0x7fffffff; }
    for (int j = threadIdx.x; j < M_BANK; j += 128) {
        float d = g_d2[b * M_BANK + j];
        if (d < v[8] || (d == v[8] && j < id[8])) {
            int k = 8;
            while (k > 0 && (d < v[k - 1] || (d == v[k - 1] && j < id[k - 1]))) {
                v[k] = v[k - 1]; id[k] = id[k - 1]; k--;
            }
            v[k] = d; id[k] = j;
        }
    }
    __shared__ float svv[128 * 9];
    __shared__ int   sid[128 * 9];
#pragma unroll
    for (int k = 0; k < 9; k++) { svv[threadIdx.x * 9 + k] = v[k]; sid[threadIdx.x * 9 + k] = id[k]; }
    __syncthreads();
    if (threadIdx.x == 0) {
        float fv[9]; int fid[9];
#pragma unroll
        for (int k = 0; k < 9; k++) { fv[k] = __int_as_float(0x7f800000); fid[k] = 0x7fffffff; }
        for (int t = 0; t < 128; t++) {
            for (int k = 0; k < 9; k++) {
                float d = svv[t * 9 + k]; int j = sid[t * 9 + k];
                if (d > fv[8] || (d == fv[8] && j >= fid[8])) break;
                int m = 8;
                while (m > 0 && (d < fv[m - 1] || (d == fv[m - 1] && j < fid[m - 1]))) {
                    fv[m] = fv[m - 1]; fid[m] = fid[m - 1]; m--;
                }
                fv[m] = d; fid[m] = j;
            }
        }
        for (int k = 0; k < 9; k++) g_support[b * 9 + k] = fid[k];
    }
}

// ---------------- Phase D ----------------
__global__ void final_kernel(const float* __restrict__ E, const float* __restrict__ Mb,
                             float* __restrict__ out) {
    int b = blockIdx.x;
    int w = threadIdx.x >> 5, lane = threadIdx.x & 31;
    __shared__ float ds[9];
    const float4* x = (const float4*)(E + (size_t)g_maxrow[b] * DIM);
    const float4* y = (const float4*)(Mb + (size_t)g_support[b * 9 + w] * DIM);
    float s = 0.f;
    for (int i = lane; i < 384; i += 32) {
        float4 xv = x[i], yv = y[i];
        float dx = xv.x - yv.x, dy = xv.y - yv.y, dz = xv.z - yv.z, dw = xv.w - yv.w;
        s += dx * dx + dy * dy + dz * dz + dw * dw;
    }
#pragma unroll
    for (int o = 16; o; o >>= 1) s += __shfl_down_sync(0xffffffffu, s, o);
    if (lane == 0) ds[w] = sqrtf(fmaxf(s, 0.f));
    __syncthreads();
    if (threadIdx.x == 0) {
        float m = ds[0];
        for (int k = 1; k < 9; k++) m = fmaxf(m, ds[k]);
        float sum = 0.f, e0 = 0.f;
        for (int k = 0; k < 9; k++) {
            float e = expf(ds[k] - m);
            if (k == 0) e0 = e;
            sum += e;
        }
        out[b] = (1.f - e0 / sum) * g_score[b];
    }
}

// ---------------- launch ----------------
extern "C" void kernel_launch(void* const* d_in, const int* in_sizes, int n_in,
                              void* d_out, int out_size) {
    const float* E  = (const float*)d_in[0];
    const float* Mb = (const float*)d_in[1];
    float* out = (float*)d_out;

    cudaFuncSetAttribute(distmin_s8, cudaFuncAttributeMaxDynamicSharedMemorySize, SMEM_BYTES);

    convert_norms_kernel<<<N_EMB + M_BANK, 128>>>(E, Mb);
    init_kernel<<<(N_EMB + 255) / 256, 256>>>();
    distmin_s8<<<GRIDX * GRIDY, 512, SMEM_BYTES>>>();
    rescore_kernel<<<N_EMB / 8, 256>>>(E, Mb);
    reduce_b_kernel<<<BATCH, 256>>>();
    exactnn_kernel<<<M_BANK / 128, 128>>>(E, Mb);
    knn_dist_kernel<<<M_BANK / 128, 128>>>(Mb);
    top9_kernel<<<BATCH, 128>>>();
    final_kernel<<<BATCH, 288>>>(E, Mb, out);
}

// round 6
// speedup vs baseline: 12.7888x; 1.1112x over previous
#include <cuda_runtime.h>
#include <cuda_bf16.h>
#include <math.h>
#include <stdint.h>

#define N_EMB 12544
#define M_BANK 16384
#define DIM 1536
#define BATCH 16
#define PPI 784
#define KNN 9

// ---- Phase A tiling (int8 mma.m16n8k32), 2 CTAs/SM ----
#define BM 128
#define BN 128
#define BK 64                      // int8 elems per k-tile (two k32 mma steps)
#define KTILES (DIM / BK)          // 24
#define NSTAGE 4
#define STRIDE_B 80                // padded bytes per row -> conflict-free ldmatrix
#define A_BYTES (BM * STRIDE_B)    // 10240
#define B_BYTES (BN * STRIDE_B)    // 10240
#define STAGE_BYTES (A_BYTES + B_BYTES)   // 20480
#define SMEM_BYTES (NSTAGE * STAGE_BYTES) // 81920
#define GRIDX (N_EMB / BM)         // 98
#define GRIDY (M_BANK / BN)        // 128
#define SWG 8                      // column-band width for block swizzle

#define QSCALE 23.0f

// ---------------- scratch ----------------
__device__ char  g_E8[N_EMB * DIM];
__device__ char  g_M8[M_BANK * DIM];
__device__ int   g_ynq[M_BANK];
__device__ unsigned long long g_minpack[N_EMB];
__device__ unsigned long long g_nnpack[BATCH];
__device__ float g_xnorm[N_EMB];
__device__ float g_ynorm[M_BANK];
__device__ float g_pscore[N_EMB];
__device__ float g_score[BATCH];
__device__ int   g_maxrow[BATCH];
__device__ float g_d2[BATCH * M_BANK];
__device__ int   g_support[BATCH * KNN];

__device__ __forceinline__ unsigned fkey(float f) {
    unsigned u = __float_as_uint(f);
    return (u & 0x80000000u) ? ~u : (u | 0x80000000u);
}

__device__ __forceinline__ void cpasync16(uint32_t dst, const void* src) {
    asm volatile("cp.async.cg.shared.global [%0], [%1], 16;" :: "r"(dst), "l"(src));
}
__device__ __forceinline__ void ldsm4(uint32_t* r, uint32_t addr) {
    asm volatile("ldmatrix.sync.aligned.m8n8.x4.shared.b16 {%0,%1,%2,%3}, [%4];"
                 : "=r"(r[0]), "=r"(r[1]), "=r"(r[2]), "=r"(r[3]) : "r"(addr));
}
__device__ __forceinline__ void mma_s8(int* c, const uint32_t* a, uint32_t b0, uint32_t b1) {
    asm volatile("mma.sync.aligned.m16n8k32.row.col.s32.s8.s8.s32 "
                 "{%0,%1,%2,%3}, {%4,%5,%6,%7}, {%8,%9}, {%0,%1,%2,%3};"
                 : "+r"(c[0]), "+r"(c[1]), "+r"(c[2]), "+r"(c[3])
                 : "r"(a[0]), "r"(a[1]), "r"(a[2]), "r"(a[3]), "r"(b0), "r"(b1));
}

__device__ __forceinline__ int q8(float x) {
    int v = __float2int_rn(x * QSCALE);
    return max(-127, min(127, v));
}

// ---------------- fused convert-to-int8 + norms ----------------
__global__ void convert_norms_kernel(const float* __restrict__ E, const float* __restrict__ Mb) {
    int row = blockIdx.x;
    const bool isE = row < N_EMB;
    const float* p = isE ? (E + (size_t)row * DIM) : (Mb + (size_t)(row - N_EMB) * DIM);
    char* q = isE ? (g_E8 + (size_t)row * DIM) : (g_M8 + (size_t)(row - N_EMB) * DIM);
    float s = 0.f;
    int   sq = 0;
    for (int i = threadIdx.x; i < DIM / 4; i += blockDim.x) {
        float4 v = ((const float4*)p)[i];
        s += v.x * v.x + v.y * v.y + v.z * v.z + v.w * v.w;
        int a = q8(v.x), b = q8(v.y), c = q8(v.z), d = q8(v.w);
        sq += a * a + b * b + c * c + d * d;
        uint32_t pk = (uint32_t)(a & 0xff) | ((uint32_t)(b & 0xff) << 8) |
                      ((uint32_t)(c & 0xff) << 16) | ((uint32_t)(d & 0xff) << 24);
        ((uint32_t*)q)[i] = pk;
    }
#pragma unroll
    for (int o = 16; o; o >>= 1) {
        s  += __shfl_down_sync(0xffffffffu, s, o);
        sq += __shfl_down_sync(0xffffffffu, sq, o);
    }
    __shared__ float ws[4];
    __shared__ int   wq[4];
    if ((threadIdx.x & 31) == 0) { ws[threadIdx.x >> 5] = s; wq[threadIdx.x >> 5] = sq; }
    __syncthreads();
    if (threadIdx.x == 0) {
        float t = ws[0] + ws[1] + ws[2] + ws[3];
        int   ti = wq[0] + wq[1] + wq[2] + wq[3];
        if (isE) g_xnorm[row] = t;
        else   { g_ynorm[row - N_EMB] = t; g_ynq[row - N_EMB] = ti; }
    }
}

__global__ void init_kernel() {
    int i = blockIdx.x * 256 + threadIdx.x;
    if (i < N_EMB) g_minpack[i] = 0xFFFFFFFFFFFFFFFFull;
    if (i < BATCH) g_nnpack[i] = 0xFFFFFFFFFFFFFFFFull;
}

// ---------------- Phase A: int8 tensor-core dist-argmin GEMM ----------------
__global__ void __launch_bounds__(256, 2) distmin_s8() {
    extern __shared__ char dsm[];
    const int tid = threadIdx.x;
    const int lane = tid & 31, warp = tid >> 5;
    const int wr = warp & 3, wc = warp >> 2;       // wr: 0..3 (m), wc: 0..1 (n)

    // block swizzle: bands of SWG column tiles
    const int band = blockIdx.x / (GRIDX * SWG);
    const int rem  = blockIdx.x % (GRIDX * SWG);
    const int by   = band * SWG + (rem % SWG);
    const int bx   = rem / SWG;
    const int rowBase = bx * BM;
    const int colBase = by * BN;

    uint32_t sbase = (uint32_t)__cvta_generic_to_shared(dsm);

    // cp.async mapping: 4 x 16B chunks per thread per stage
    // A: 128 rows x 4 chunks = 512 ; B: 128 rows x 4 chunks = 512
    const char* src[4];
    uint32_t dsto[4];
#pragma unroll
    for (int i = 0; i < 4; i++) {
        int idx = tid + i * 256;
        if (idx < 512) {
            int row = idx >> 2, c = idx & 3;
            src[i]  = g_E8 + (size_t)(rowBase + row) * DIM + c * 16;
            dsto[i] = row * STRIDE_B + c * 16;
        } else {
            int j = idx - 512;
            int row = j >> 2, c = j & 3;
            src[i]  = g_M8 + (size_t)(colBase + row) * DIM + c * 16;
            dsto[i] = A_BYTES + row * STRIDE_B + c * 16;
        }
    }

    // ldmatrix lane addressing (byte offsets within stage)
    const int arow = (lane & 7) + ((lane >> 3) & 1) * 8;
    const uint32_t akb = (lane >> 4) * 16;
    uint32_t aAddr[2];
#pragma unroll
    for (int m = 0; m < 2; m++)
        aAddr[m] = sbase + (wr * 32 + m * 16 + arow) * STRIDE_B + akb;
    const int brow = (lane & 7) + (lane >> 4) * 8;
    const uint32_t bkb = ((lane >> 3) & 1) * 16;
    uint32_t bAddr[4];
#pragma unroll
    for (int g = 0; g < 4; g++)
        bAddr[g] = sbase + A_BYTES + (wc * 64 + g * 16 + brow) * STRIDE_B + bkb;

    int acc[2][8][4];
#pragma unroll
    for (int m = 0; m < 2; m++)
#pragma unroll
        for (int t = 0; t < 8; t++)
#pragma unroll
            for (int c = 0; c < 4; c++) acc[m][t][c] = 0;

    // prologue: issue stages 0..2
#pragma unroll
    for (int s = 0; s < NSTAGE - 1; s++) {
#pragma unroll
        for (int i = 0; i < 4; i++) cpasync16(sbase + s * STAGE_BYTES + dsto[i], src[i] + s * BK);
        asm volatile("cp.async.commit_group;");
    }

    for (int kt = 0; kt < KTILES; kt++) {
        const int st = kt % NSTAGE;
        asm volatile("cp.async.wait_group %0;" :: "n"(NSTAGE - 2));
        __syncthreads();                 // single barrier per k-tile
        if (kt + NSTAGE - 1 < KTILES) {
            const int ps = (kt + NSTAGE - 1) % NSTAGE;   // slot everyone just drained
            const int ko = (kt + NSTAGE - 1) * BK;
#pragma unroll
            for (int i = 0; i < 4; i++) cpasync16(sbase + ps * STAGE_BYTES + dsto[i], src[i] + ko);
            asm volatile("cp.async.commit_group;");
        }
        const uint32_t so = st * STAGE_BYTES;
#pragma unroll
        for (int s = 0; s < 2; s++) {            // two k32 steps per k-tile
            uint32_t af[2][4], bf[4][4];
#pragma unroll
            for (int m = 0; m < 2; m++) ldsm4(af[m], aAddr[m] + so + s * 32);
#pragma unroll
            for (int g = 0; g < 4; g++) ldsm4(bf[g], bAddr[g] + so + s * 32);
#pragma unroll
            for (int m = 0; m < 2; m++)
#pragma unroll
                for (int t = 0; t < 8; t++)
                    mma_s8(acc[m][t], af[m], bf[t >> 1][(t & 1) * 2], bf[t >> 1][(t & 1) * 2 + 1]);
        }
    }
    __syncthreads();   // protect smem reuse by epilogue

    // epilogue: integer q = ynq - 2*dot ; per-row argmin (ties -> lowest col)
    const int gid = lane >> 2, qid = lane & 3;
    unsigned long long* red = (unsigned long long*)dsm;   // [2][128]
#pragma unroll
    for (int m = 0; m < 2; m++)
#pragma unroll
        for (int h = 0; h < 2; h++) {
            int bv = 0x7fffffff;
            int bj = 0x7fffffff;
#pragma unroll
            for (int t = 0; t < 8; t++)
#pragma unroll
                for (int c = 0; c < 2; c++) {
                    int col = colBase + wc * 64 + t * 8 + qid * 2 + c;
                    int q = g_ynq[col] - 2 * acc[m][t][h * 2 + c];
                    if (q < bv || (q == bv && col < bj)) { bv = q; bj = col; }
                }
#pragma unroll
            for (int off = 1; off < 4; off <<= 1) {
                int ov = __shfl_xor_sync(0xffffffffu, bv, off, 4);
                int oj = __shfl_xor_sync(0xffffffffu, bj, off, 4);
                if (ov < bv || (ov == bv && oj < bj)) { bv = ov; bj = oj; }
            }
            if (qid == 0) {
                int rloc = wr * 32 + m * 16 + h * 8 + gid;
                unsigned ku = (unsigned)bv ^ 0x80000000u;   // signed-order-preserving
                red[wc * 128 + rloc] = ((unsigned long long)ku << 32) | (unsigned)bj;
            }
        }
    __syncthreads();
    if (tid < BM) {
        unsigned long long p = red[tid];
        unsigned long long q1 = red[128 + tid]; if (q1 < p) p = q1;
        atomicMin(&g_minpack[rowBase + tid], p);
    }
}

// ---------------- exact fp32 rescore of selected candidates ----------------
__global__ void rescore_kernel(const float* __restrict__ E, const float* __restrict__ Mb) {
    int warp = threadIdx.x >> 5, lane = threadIdx.x & 31;
    int row = blockIdx.x * 8 + warp;
    int col = (int)(g_minpack[row] & 0xffffffffull);
    const float4* x = (const float4*)(E + (size_t)row * DIM);
    const float4* y = (const float4*)(Mb + (size_t)col * DIM);
    float s = 0.f;
    for (int i = lane; i < DIM / 4; i += 32) {
        float4 a = x[i], b = y[i];
        s += a.x * b.x + a.y * b.y + a.z * b.z + a.w * b.w;
    }
#pragma unroll
    for (int o = 16; o; o >>= 1) s += __shfl_down_sync(0xffffffffu, s, o);
    if (lane == 0) {
        float d2 = g_xnorm[row] + g_ynorm[col] - 2.f * s;
        g_pscore[row] = sqrtf(fmaxf(d2, 0.f));
    }
}

// ---------------- Phase B: per-image argmax ----------------
__global__ void reduce_b_kernel() {
    int b = blockIdx.x;
    __shared__ float sv[256];
    __shared__ int   sp[256];
    float bv = -1.f; int bp = 0x7fffffff;
    for (int p = threadIdx.x; p < PPI; p += 256) {
        float sc = g_pscore[b * PPI + p];
        if (sc > bv || (sc == bv && p < bp)) { bv = sc; bp = p; }
    }
    sv[threadIdx.x] = bv; sp[threadIdx.x] = bp;
    __syncthreads();
    for (int s = 128; s; s >>= 1) {
        if (threadIdx.x < s) {
            float ov = sv[threadIdx.x + s]; int op = sp[threadIdx.x + s];
            if (ov > sv[threadIdx.x] || (ov == sv[threadIdx.x] && op < sp[threadIdx.x])) {
                sv[threadIdx.x] = ov; sp[threadIdx.x] = op;
            }
        }
        __syncthreads();
    }
    if (threadIdx.x == 0) {
        g_maxrow[b] = b * PPI + sp[0];
        g_score[b]  = sv[0];
    }
}

// ---------------- exact fp32 NN search for the 16 argmax rows ----------------
__global__ void exactnn_kernel(const float* __restrict__ E, const float* __restrict__ Mb) {
    __shared__ float Qs[16 * 384];
    __shared__ int   qr[16];
    __shared__ unsigned long long part[16];
    int tid = threadIdx.x;
    if (tid < 16) { qr[tid] = g_maxrow[tid]; part[tid] = 0xFFFFFFFFFFFFFFFFull; }
    __syncthreads();
    int col = blockIdx.x * 128 + tid;
    float acc[16];
#pragma unroll
    for (int q = 0; q < 16; q++) acc[q] = 0.f;
    for (int c = 0; c < 4; c++) {
        for (int i = tid; i < 1536; i += 128) {
            int q = i / 96, d4 = i % 96;
            *(float4*)&Qs[q * 384 + d4 * 4] =
                *(const float4*)(E + (size_t)qr[q] * DIM + c * 384 + d4 * 4);
        }
        __syncthreads();
        const float4* rp = (const float4*)(Mb + (size_t)col * DIM + c * 384);
#pragma unroll 4
        for (int d4 = 0; d4 < 96; d4++) {
            float4 v = rp[d4];
#pragma unroll
            for (int q = 0; q < 16; q++) {
                float4 u = *(const float4*)&Qs[q * 384 + d4 * 4];
                acc[q] = fmaf(v.x, u.x, fmaf(v.y, u.y, fmaf(v.z, u.z, fmaf(v.w, u.w, acc[q]))));
            }
        }
        __syncthreads();
    }
    float yn = g_ynorm[col];
#pragma unroll
    for (int q = 0; q < 16; q++) {
        float d2 = g_xnorm[qr[q]] + yn - 2.f * acc[q];
        unsigned long long pk = ((unsigned long long)fkey(d2) << 32) | (unsigned)col;
        atomicMin(&part[q], pk);
    }
    __syncthreads();
    if (tid < 16) atomicMin(&g_nnpack[tid], part[tid]);
}

// ---------------- Phase C1: d^2 from 16 nn_samples to all memory rows ----------------
__global__ void knn_dist_kernel(const float* __restrict__ Mb) {
    __shared__ float Qs[16 * 384];
    __shared__ int   nn[16];
    __shared__ float qn[16];
    int tid = threadIdx.x;
    if (tid < 16) {
        int idx = (int)(g_nnpack[tid] & 0xffffffffull);
        nn[tid] = idx; qn[tid] = g_ynorm[idx];
    }
    __syncthreads();
    int row = blockIdx.x * 128 + tid;
    float acc[16];
#pragma unroll
    for (int q = 0; q < 16; q++) acc[q] = 0.f;
    for (int c = 0; c < 4; c++) {
        for (int i = tid; i < 1536; i += 128) {
            int q = i / 96, d4 = i % 96;
            *(float4*)&Qs[q * 384 + d4 * 4] =
                *(const float4*)(Mb + (size_t)nn[q] * DIM + c * 384 + d4 * 4);
        }
        __syncthreads();
        const float4* rp = (const float4*)(Mb + (size_t)row * DIM + c * 384);
#pragma unroll 4
        for (int d4 = 0; d4 < 96; d4++) {
            float4 v = rp[d4];
#pragma unroll
            for (int q = 0; q < 16; q++) {
                float4 u = *(const float4*)&Qs[q * 384 + d4 * 4];
                acc[q] = fmaf(v.x, u.x, fmaf(v.y, u.y, fmaf(v.z, u.z, fmaf(v.w, u.w, acc[q]))));
            }
        }
        __syncthreads();
    }
    float yn = g_ynorm[row];
#pragma unroll
    for (int q = 0; q < 16; q++)
        g_d2[q * M_BANK + row] = qn[q] + yn - 2.f * acc[q];
}

// ---------------- Phase C2: stable top-9 ----------------
__global__ void top9_kernel() {
    int b = blockIdx.x;
    float v[9]; int id[9];
#pragma unroll
    for (int k = 0; k < 9; k++) { v[k] = __int_as_float(0x7f800000); id[k] = 0x7fffffff; }
    for (int j = threadIdx.x; j < M_BANK; j += 128) {
        float d = g_d2[b * M_BANK + j];
        if (d < v[8] || (d == v[8] && j < id[8])) {
            int k = 8;
            while (k > 0 && (d < v[k - 1] || (d == v[k - 1] && j < id[k - 1]))) {
                v[k] = v[k - 1]; id[k] = id[k - 1]; k--;
            }
            v[k] = d; id[k] = j;
        }
    }
    __shared__ float svv[128 * 9];
    __shared__ int   sid[128 * 9];
#pragma unroll
    for (int k = 0; k < 9; k++) { svv[threadIdx.x * 9 + k] = v[k]; sid[threadIdx.x * 9 + k] = id[k]; }
    __syncthreads();
    if (threadIdx.x == 0) {
        float fv[9]; int fid[9];
#pragma unroll
        for (int k = 0; k < 9; k++) { fv[k] = __int_as_float(0x7f800000); fid[k] = 0x7fffffff; }
        for (int t = 0; t < 128; t++) {
            for (int k = 0; k < 9; k++) {
                float d = svv[t * 9 + k]; int j = sid[t * 9 + k];
                if (d > fv[8] || (d == fv[8] && j >= fid[8])) break;
                int m = 8;
                while (m > 0 && (d < fv[m - 1] || (d == fv[m - 1] && j < fid[m - 1]))) {
                    fv[m] = fv[m - 1]; fid[m] = fid[m - 1]; m--;
                }
                fv[m] = d; fid[m] = j;
            }
        }
        for (int k = 0; k < 9; k++) g_support[b * 9 + k] = fid[k];
    }
}

// ---------------- Phase D ----------------
__global__ void final_kernel(const float* __restrict__ E, const float* __restrict__ Mb,
                             float* __restrict__ out) {
    int b = blockIdx.x;
    int w = threadIdx.x >> 5, lane = threadIdx.x & 31;
    __shared__ float ds[9];
    const float4* x = (const float4*)(E + (size_t)g_maxrow[b] * DIM);
    const float4* y = (const float4*)(Mb + (size_t)g_support[b * 9 + w] * DIM);
    float s = 0.f;
    for (int i = lane; i < 384; i += 32) {
        float4 xv = x[i], yv = y[i];
        float dx = xv.x - yv.x, dy = xv.y - yv.y, dz = xv.z - yv.z, dw = xv.w - yv.w;
        s += dx * dx + dy * dy + dz * dz + dw * dw;
    }
#pragma unroll
    for (int o = 16; o; o >>= 1) s += __shfl_down_sync(0xffffffffu, s, o);
    if (lane == 0) ds[w] = sqrtf(fmaxf(s, 0.f));
    __syncthreads();
    if (threadIdx.x == 0) {
        float m = ds[0];
        for (int k = 1; k < 9; k++) m = fmaxf(m, ds[k]);
        float sum = 0.f, e0 = 0.f;
        for (int k = 0; k < 9; k++) {
            float e = expf(ds[k] - m);
            if (k == 0) e0 = e;
            sum += e;
        }
        out[b] = (1.f - e0 / sum) * g_score[b];
    }
}

// ---------------- launch ----------------
extern "C" void kernel_launch(void* const* d_in, const int* in_sizes, int n_in,
                              void* d_out, int out_size) {
    const float* E  = (const float*)d_in[0];
    const float* Mb = (const float*)d_in[1];
    float* out = (float*)d_out;

    cudaFuncSetAttribute(distmin_s8, cudaFuncAttributeMaxDynamicSharedMemorySize, SMEM_BYTES);

    convert_norms_kernel<<<N_EMB + M_BANK, 128>>>(E, Mb);
    init_kernel<<<(N_EMB + 255) / 256, 256>>>();
    distmin_s8<<<GRIDX * GRIDY, 256, SMEM_BYTES>>>();
    rescore_kernel<<<N_EMB / 8, 256>>>(E, Mb);
    reduce_b_kernel<<<BATCH, 256>>>();
    exactnn_kernel<<<M_BANK / 128, 128>>>(E, Mb);
    knn_dist_kernel<<<M_BANK / 128, 128>>>(Mb);
    top9_kernel<<<BATCH, 128>>>();
    final_kernel<<<BATCH, 288>>>(E, Mb, out);
}

// round 7
// speedup vs baseline: 13.5966x; 1.0632x over previous
#include <cuda_runtime.h>
#include <cuda_bf16.h>
#include <math.h>
#include <stdint.h>

#define N_EMB 12544
#define M_BANK 16384
#define DIM 1536
#define BATCH 16
#define PPI 784
#define KNN 9

// ---- Phase A tiling (int8 mma.m16n8k32), 2 CTAs/SM, BK=128 ----
#define BM 128
#define BN 128
#define BK 128                     // int8 elems per k-tile (four k32 mma steps)
#define KTILES (DIM / BK)          // 12
#define NSTAGE 3
#define STRIDE_B 144               // 128 data + 16 pad -> conflict-free ldmatrix
#define A_BYTES (BM * STRIDE_B)    // 18432
#define B_BYTES (BN * STRIDE_B)    // 18432
#define STAGE_BYTES (A_BYTES + B_BYTES)   // 36864
#define SMEM_BYTES (NSTAGE * STAGE_BYTES) // 110592
#define GRIDX (N_EMB / BM)         // 98
#define GRIDY (M_BANK / BN)        // 128
#define SWG 8                      // column-band width for block swizzle

#define QSCALE 23.0f

// ---------------- scratch ----------------
__device__ char  g_E8[N_EMB * DIM];
__device__ char  g_M8[M_BANK * DIM];
__device__ int   g_ynq[M_BANK];
__device__ unsigned long long g_minpack[N_EMB];
__device__ unsigned long long g_nnpack[BATCH];
__device__ float g_xnorm[N_EMB];
__device__ float g_ynorm[M_BANK];
__device__ float g_pscore[N_EMB];
__device__ float g_score[BATCH];
__device__ int   g_maxrow[BATCH];
__device__ float g_d2[BATCH * M_BANK];
__device__ int   g_support[BATCH * KNN];

__device__ __forceinline__ unsigned fkey(float f) {
    unsigned u = __float_as_uint(f);
    return (u & 0x80000000u) ? ~u : (u | 0x80000000u);
}

__device__ __forceinline__ void cpasync16(uint32_t dst, const void* src) {
    asm volatile("cp.async.cg.shared.global [%0], [%1], 16;" :: "r"(dst), "l"(src));
}
__device__ __forceinline__ void ldsm4(uint32_t* r, uint32_t addr) {
    asm volatile("ldmatrix.sync.aligned.m8n8.x4.shared.b16 {%0,%1,%2,%3}, [%4];"
                 : "=r"(r[0]), "=r"(r[1]), "=r"(r[2]), "=r"(r[3]) : "r"(addr));
}
__device__ __forceinline__ void mma_s8(int* c, const uint32_t* a, uint32_t b0, uint32_t b1) {
    asm volatile("mma.sync.aligned.m16n8k32.row.col.s32.s8.s8.s32 "
                 "{%0,%1,%2,%3}, {%4,%5,%6,%7}, {%8,%9}, {%0,%1,%2,%3};"
                 : "+r"(c[0]), "+r"(c[1]), "+r"(c[2]), "+r"(c[3])
                 : "r"(a[0]), "r"(a[1]), "r"(a[2]), "r"(a[3]), "r"(b0), "r"(b1));
}

__device__ __forceinline__ int q8(float x) {
    int v = __float2int_rn(x * QSCALE);
    return max(-127, min(127, v));
}

// ---------------- fused convert-to-int8 + norms ----------------
__global__ void convert_norms_kernel(const float* __restrict__ E, const float* __restrict__ Mb) {
    int row = blockIdx.x;
    const bool isE = row < N_EMB;
    const float* p = isE ? (E + (size_t)row * DIM) : (Mb + (size_t)(row - N_EMB) * DIM);
    char* q = isE ? (g_E8 + (size_t)row * DIM) : (g_M8 + (size_t)(row - N_EMB) * DIM);
    float s = 0.f;
    int   sq = 0;
    for (int i = threadIdx.x; i < DIM / 4; i += blockDim.x) {
        float4 v = ((const float4*)p)[i];
        s += v.x * v.x + v.y * v.y + v.z * v.z + v.w * v.w;
        int a = q8(v.x), b = q8(v.y), c = q8(v.z), d = q8(v.w);
        sq += a * a + b * b + c * c + d * d;
        uint32_t pk = (uint32_t)(a & 0xff) | ((uint32_t)(b & 0xff) << 8) |
                      ((uint32_t)(c & 0xff) << 16) | ((uint32_t)(d & 0xff) << 24);
        ((uint32_t*)q)[i] = pk;
    }
#pragma unroll
    for (int o = 16; o; o >>= 1) {
        s  += __shfl_down_sync(0xffffffffu, s, o);
        sq += __shfl_down_sync(0xffffffffu, sq, o);
    }
    __shared__ float ws[4];
    __shared__ int   wq[4];
    if ((threadIdx.x & 31) == 0) { ws[threadIdx.x >> 5] = s; wq[threadIdx.x >> 5] = sq; }
    __syncthreads();
    if (threadIdx.x == 0) {
        float t = ws[0] + ws[1] + ws[2] + ws[3];
        int   ti = wq[0] + wq[1] + wq[2] + wq[3];
        if (isE) g_xnorm[row] = t;
        else   { g_ynorm[row - N_EMB] = t; g_ynq[row - N_EMB] = ti; }
    }
}

__global__ void init_kernel() {
    int i = blockIdx.x * 256 + threadIdx.x;
    if (i < N_EMB) g_minpack[i] = 0xFFFFFFFFFFFFFFFFull;
    if (i < BATCH) g_nnpack[i] = 0xFFFFFFFFFFFFFFFFull;
}

// ---------------- Phase A: int8 tensor-core dist-argmin GEMM ----------------
__global__ void __launch_bounds__(256, 2) distmin_s8() {
    extern __shared__ char dsm[];
    const int tid = threadIdx.x;
    const int lane = tid & 31, warp = tid >> 5;
    const int wr = warp & 3, wc = warp >> 2;       // wr: 0..3 (m), wc: 0..1 (n)

    // block swizzle: bands of SWG column tiles
    const int band = blockIdx.x / (GRIDX * SWG);
    const int rem  = blockIdx.x % (GRIDX * SWG);
    const int by   = band * SWG + (rem % SWG);
    const int bx   = rem / SWG;
    const int rowBase = bx * BM;
    const int colBase = by * BN;

    uint32_t sbase = (uint32_t)__cvta_generic_to_shared(dsm);

    // cp.async mapping: 8 x 16B chunks per thread per stage
    // A: 128 rows x 8 chunks = 1024 ; B: 128 rows x 8 chunks = 1024
    const char* src[8];
    uint32_t dsto[8];
#pragma unroll
    for (int i = 0; i < 8; i++) {
        int idx = tid + i * 256;
        if (idx < 1024) {
            int row = idx >> 3, c = idx & 7;
            src[i]  = g_E8 + (size_t)(rowBase + row) * DIM + c * 16;
            dsto[i] = row * STRIDE_B + c * 16;
        } else {
            int j = idx - 1024;
            int row = j >> 3, c = j & 7;
            src[i]  = g_M8 + (size_t)(colBase + row) * DIM + c * 16;
            dsto[i] = A_BYTES + row * STRIDE_B + c * 16;
        }
    }

    // ldmatrix lane addressing (byte offsets within stage); k32-step = 32B of a row
    const int arow = (lane & 7) + ((lane >> 3) & 1) * 8;
    const uint32_t akb = (lane >> 4) * 16;
    uint32_t aAddr[2];
#pragma unroll
    for (int m = 0; m < 2; m++)
        aAddr[m] = sbase + (wr * 32 + m * 16 + arow) * STRIDE_B + akb;
    const int brow = (lane & 7) + (lane >> 4) * 8;
    const uint32_t bkb = ((lane >> 3) & 1) * 16;
    uint32_t bAddr[4];
#pragma unroll
    for (int g = 0; g < 4; g++)
        bAddr[g] = sbase + A_BYTES + (wc * 64 + g * 16 + brow) * STRIDE_B + bkb;

    int acc[2][8][4];
#pragma unroll
    for (int m = 0; m < 2; m++)
#pragma unroll
        for (int t = 0; t < 8; t++)
#pragma unroll
            for (int c = 0; c < 4; c++) acc[m][t][c] = 0;

    // prologue: issue stages 0,1
#pragma unroll
    for (int s = 0; s < NSTAGE - 1; s++) {
#pragma unroll
        for (int i = 0; i < 8; i++) cpasync16(sbase + s * STAGE_BYTES + dsto[i], src[i] + s * BK);
        asm volatile("cp.async.commit_group;");
    }

    for (int kt = 0; kt < KTILES; kt++) {
        const int st = kt % NSTAGE;
        asm volatile("cp.async.wait_group %0;" :: "n"(NSTAGE - 2));
        __syncthreads();                 // single barrier per k-tile
        if (kt + NSTAGE - 1 < KTILES) {
            const int ps = (kt + NSTAGE - 1) % NSTAGE;   // slot drained at kt-1
            const int ko = (kt + NSTAGE - 1) * BK;
#pragma unroll
            for (int i = 0; i < 8; i++) cpasync16(sbase + ps * STAGE_BYTES + dsto[i], src[i] + ko);
            asm volatile("cp.async.commit_group;");
        }
        const uint32_t so = st * STAGE_BYTES;
#pragma unroll
        for (int s = 0; s < 4; s++) {            // four k32 steps per k-tile
            uint32_t af[2][4], bf[4][4];
#pragma unroll
            for (int m = 0; m < 2; m++) ldsm4(af[m], aAddr[m] + so + s * 32);
#pragma unroll
            for (int g = 0; g < 4; g++) ldsm4(bf[g], bAddr[g] + so + s * 32);
#pragma unroll
            for (int m = 0; m < 2; m++)
#pragma unroll
                for (int t = 0; t < 8; t++)
                    mma_s8(acc[m][t], af[m], bf[t >> 1][(t & 1) * 2], bf[t >> 1][(t & 1) * 2 + 1]);
        }
    }
    __syncthreads();   // protect smem reuse by epilogue

    // epilogue: integer q = ynq - 2*dot ; per-row argmin (ties -> lowest col)
    const int gid = lane >> 2, qid = lane & 3;
    unsigned long long* red = (unsigned long long*)dsm;   // [2][128]
#pragma unroll
    for (int m = 0; m < 2; m++)
#pragma unroll
        for (int h = 0; h < 2; h++) {
            int bv = 0x7fffffff;
            int bj = 0x7fffffff;
#pragma unroll
            for (int t = 0; t < 8; t++)
#pragma unroll
                for (int c = 0; c < 2; c++) {
                    int col = colBase + wc * 64 + t * 8 + qid * 2 + c;
                    int q = g_ynq[col] - 2 * acc[m][t][h * 2 + c];
                    if (q < bv || (q == bv && col < bj)) { bv = q; bj = col; }
                }
#pragma unroll
            for (int off = 1; off < 4; off <<= 1) {
                int ov = __shfl_xor_sync(0xffffffffu, bv, off, 4);
                int oj = __shfl_xor_sync(0xffffffffu, bj, off, 4);
                if (ov < bv || (ov == bv && oj < bj)) { bv = ov; bj = oj; }
            }
            if (qid == 0) {
                int rloc = wr * 32 + m * 16 + h * 8 + gid;
                unsigned ku = (unsigned)bv ^ 0x80000000u;   // signed-order-preserving
                red[wc * 128 + rloc] = ((unsigned long long)ku << 32) | (unsigned)bj;
            }
        }
    __syncthreads();
    if (tid < BM) {
        unsigned long long p = red[tid];
        unsigned long long q1 = red[128 + tid]; if (q1 < p) p = q1;
        atomicMin(&g_minpack[rowBase + tid], p);
    }
}

// ---------------- exact fp32 rescore of selected candidates ----------------
__global__ void rescore_kernel(const float* __restrict__ E, const float* __restrict__ Mb) {
    int warp = threadIdx.x >> 5, lane = threadIdx.x & 31;
    int row = blockIdx.x * 8 + warp;
    int col = (int)(g_minpack[row] & 0xffffffffull);
    const float4* x = (const float4*)(E + (size_t)row * DIM);
    const float4* y = (const float4*)(Mb + (size_t)col * DIM);
    float s = 0.f;
    for (int i = lane; i < DIM / 4; i += 32) {
        float4 a = x[i], b = y[i];
        s += a.x * b.x + a.y * b.y + a.z * b.z + a.w * b.w;
    }
#pragma unroll
    for (int o = 16; o; o >>= 1) s += __shfl_down_sync(0xffffffffu, s, o);
    if (lane == 0) {
        float d2 = g_xnorm[row] + g_ynorm[col] - 2.f * s;
        g_pscore[row] = sqrtf(fmaxf(d2, 0.f));
    }
}

// ---------------- Phase B: per-image argmax ----------------
__global__ void reduce_b_kernel() {
    int b = blockIdx.x;
    __shared__ float sv[256];
    __shared__ int   sp[256];
    float bv = -1.f; int bp = 0x7fffffff;
    for (int p = threadIdx.x; p < PPI; p += 256) {
        float sc = g_pscore[b * PPI + p];
        if (sc > bv || (sc == bv && p < bp)) { bv = sc; bp = p; }
    }
    sv[threadIdx.x] = bv; sp[threadIdx.x] = bp;
    __syncthreads();
    for (int s = 128; s; s >>= 1) {
        if (threadIdx.x < s) {
            float ov = sv[threadIdx.x + s]; int op = sp[threadIdx.x + s];
            if (ov > sv[threadIdx.x] || (ov == sv[threadIdx.x] && op < sp[threadIdx.x])) {
                sv[threadIdx.x] = ov; sp[threadIdx.x] = op;
            }
        }
        __syncthreads();
    }
    if (threadIdx.x == 0) {
        g_maxrow[b] = b * PPI + sp[0];
        g_score[b]  = sv[0];
    }
}

// ---------------- exact fp32 NN search for the 16 argmax rows ----------------
__global__ void exactnn_kernel(const float* __restrict__ E, const float* __restrict__ Mb) {
    __shared__ float Qs[16 * 384];
    __shared__ int   qr[16];
    __shared__ unsigned long long part[16];
    int tid = threadIdx.x;
    if (tid < 16) { qr[tid] = g_maxrow[tid]; part[tid] = 0xFFFFFFFFFFFFFFFFull; }
    __syncthreads();
    int col = blockIdx.x * 128 + tid;
    float acc[16];
#pragma unroll
    for (int q = 0; q < 16; q++) acc[q] = 0.f;
    for (int c = 0; c < 4; c++) {
        for (int i = tid; i < 1536; i += 128) {
            int q = i / 96, d4 = i % 96;
            *(float4*)&Qs[q * 384 + d4 * 4] =
                *(const float4*)(E + (size_t)qr[q] * DIM + c * 384 + d4 * 4);
        }
        __syncthreads();
        const float4* rp = (const float4*)(Mb + (size_t)col * DIM + c * 384);
#pragma unroll 4
        for (int d4 = 0; d4 < 96; d4++) {
            float4 v = rp[d4];
#pragma unroll
            for (int q = 0; q < 16; q++) {
                float4 u = *(const float4*)&Qs[q * 384 + d4 * 4];
                acc[q] = fmaf(v.x, u.x, fmaf(v.y, u.y, fmaf(v.z, u.z, fmaf(v.w, u.w, acc[q]))));
            }
        }
        __syncthreads();
    }
    float yn = g_ynorm[col];
#pragma unroll
    for (int q = 0; q < 16; q++) {
        float d2 = g_xnorm[qr[q]] + yn - 2.f * acc[q];
        unsigned long long pk = ((unsigned long long)fkey(d2) << 32) | (unsigned)col;
        atomicMin(&part[q], pk);
    }
    __syncthreads();
    if (tid < 16) atomicMin(&g_nnpack[tid], part[tid]);
}

// ---------------- Phase C1: d^2 from 16 nn_samples to all memory rows ----------------
__global__ void knn_dist_kernel(const float* __restrict__ Mb) {
    __shared__ float Qs[16 * 384];
    __shared__ int   nn[16];
    __shared__ float qn[16];
    int tid = threadIdx.x;
    if (tid < 16) {
        int idx = (int)(g_nnpack[tid] & 0xffffffffull);
        nn[tid] = idx; qn[tid] = g_ynorm[idx];
    }
    __syncthreads();
    int row = blockIdx.x * 128 + tid;
    float acc[16];
#pragma unroll
    for (int q = 0; q < 16; q++) acc[q] = 0.f;
    for (int c = 0; c < 4; c++) {
        for (int i = tid; i < 1536; i += 128) {
            int q = i / 96, d4 = i % 96;
            *(float4*)&Qs[q * 384 + d4 * 4] =
                *(const float4*)(Mb + (size_t)nn[q] * DIM + c * 384 + d4 * 4);
        }
        __syncthreads();
        const float4* rp = (const float4*)(Mb + (size_t)row * DIM + c * 384);
#pragma unroll 4
        for (int d4 = 0; d4 < 96; d4++) {
            float4 v = rp[d4];
#pragma unroll
            for (int q = 0; q < 16; q++) {
                float4 u = *(const float4*)&Qs[q * 384 + d4 * 4];
                acc[q] = fmaf(v.x, u.x, fmaf(v.y, u.y, fmaf(v.z, u.z, fmaf(v.w, u.w, acc[q]))));
            }
        }
        __syncthreads();
    }
    float yn = g_ynorm[row];
#pragma unroll
    for (int q = 0; q < 16; q++)
        g_d2[q * M_BANK + row] = qn[q] + yn - 2.f * acc[q];
}

// ---------------- Phase C2: stable top-9 ----------------
__global__ void top9_kernel() {
    int b = blockIdx.x;
    float v[9]; int id[9];
#pragma unroll
    for (int k = 0; k < 9; k++) { v[k] = __int_as_float(0x7f800000); id[k] = 0x7fffffff; }
    for (int j = threadIdx.x; j < M_BANK; j += 128) {
        float d = g_d2[b * M_BANK + j];
        if (d < v[8] || (d == v[8] && j < id[8])) {
            int k = 8;
            while (k > 0 && (d < v[k - 1] || (d == v[k - 1] && j < id[k - 1]))) {
                v[k] = v[k - 1]; id[k] = id[k - 1]; k--;
            }
            v[k] = d; id[k] = j;
        }
    }
    __shared__ float svv[128 * 9];
    __shared__ int   sid[128 * 9];
#pragma unroll
    for (int k = 0; k < 9; k++) { svv[threadIdx.x * 9 + k] = v[k]; sid[threadIdx.x * 9 + k] = id[k]; }
    __syncthreads();
    if (threadIdx.x == 0) {
        float fv[9]; int fid[9];
#pragma unroll
        for (int k = 0; k < 9; k++) { fv[k] = __int_as_float(0x7f800000); fid[k] = 0x7fffffff; }
        for (int t = 0; t < 128; t++) {
            for (int k = 0; k < 9; k++) {
                float d = svv[t * 9 + k]; int j = sid[t * 9 + k];
                if (d > fv[8] || (d == fv[8] && j >= fid[8])) break;
                int m = 8;
                while (m > 0 && (d < fv[m - 1] || (d == fv[m - 1] && j < fid[m - 1]))) {
                    fv[m] = fv[m - 1]; fid[m] = fid[m - 1]; m--;
                }
                fv[m] = d; fid[m] = j;
            }
        }
        for (int k = 0; k < 9; k++) g_support[b * 9 + k] = fid[k];
    }
}

// ---------------- Phase D ----------------
__global__ void final_kernel(const float* __restrict__ E, const float* __restrict__ Mb,
                             float* __restrict__ out) {
    int b = blockIdx.x;
    int w = threadIdx.x >> 5, lane = threadIdx.x & 31;
    __shared__ float ds[9];
    const float4* x = (const float4*)(E + (size_t)g_maxrow[b] * DIM);
    const float4* y = (const float4*)(Mb + (size_t)g_support[b * 9 + w] * DIM);
    float s = 0.f;
    for (int i = lane; i < 384; i += 32) {
        float4 xv = x[i], yv = y[i];
        float dx = xv.x - yv.x, dy = xv.y - yv.y, dz = xv.z - yv.z, dw = xv.w - yv.w;
        s += dx * dx + dy * dy + dz * dz + dw * dw;
    }
#pragma unroll
    for (int o = 16; o; o >>= 1) s += __shfl_down_sync(0xffffffffu, s, o);
    if (lane == 0) ds[w] = sqrtf(fmaxf(s, 0.f));
    __syncthreads();
    if (threadIdx.x == 0) {
        float m = ds[0];
        for (int k = 1; k < 9; k++) m = fmaxf(m, ds[k]);
        float sum = 0.f, e0 = 0.f;
        for (int k = 0; k < 9; k++) {
            float e = expf(ds[k] - m);
            if (k == 0) e0 = e;
            sum += e;
        }
        out[b] = (1.f - e0 / sum) * g_score[b];
    }
}

// ---------------- launch ----------------
extern "C" void kernel_launch(void* const* d_in, const int* in_sizes, int n_in,
                              void* d_out, int out_size) {
    const float* E  = (const float*)d_in[0];
    const float* Mb = (const float*)d_in[1];
    float* out = (float*)d_out;

    cudaFuncSetAttribute(distmin_s8, cudaFuncAttributeMaxDynamicSharedMemorySize, SMEM_BYTES);

    convert_norms_kernel<<<N_EMB + M_BANK, 128>>>(E, Mb);
    init_kernel<<<(N_EMB + 255) / 256, 256>>>();
    distmin_s8<<<GRIDX * GRIDY, 256, SMEM_BYTES>>>();
    rescore_kernel<<<N_EMB / 8, 256>>>(E, Mb);
    reduce_b_kernel<<<BATCH, 256>>>();
    exactnn_kernel<<<M_BANK / 128, 128>>>(E, Mb);
    knn_dist_kernel<<<M_BANK / 128, 128>>>(Mb);
    top9_kernel<<<BATCH, 128>>>();
    final_kernel<<<BATCH, 288>>>(E, Mb, out);
}

// round 8
// speedup vs baseline: 15.0785x; 1.1090x over previous
#include <cuda_runtime.h>
#include <cuda_bf16.h>
#include <math.h>
#include <stdint.h>

#define N_EMB 12544
#define M_BANK 16384
#define DIM 1536
#define BATCH 16
#define PPI 784
#define KNN 9

// ---- Phase A tiling (int8 mma.m16n8k32), 2 CTAs/SM, BK=128 ----
#define BM 128
#define BN 128
#define BK 128
#define KTILES (DIM / BK)          // 12
#define NSTAGE 3
#define STRIDE_B 144               // 128 data + 16 pad -> conflict-free ldmatrix
#define A_BYTES (BM * STRIDE_B)
#define B_BYTES (BN * STRIDE_B)
#define STAGE_BYTES (A_BYTES + B_BYTES)   // 36864
#define SMEM_BYTES (NSTAGE * STAGE_BYTES) // 110592
#define GRIDX (N_EMB / BM)         // 98
#define GRIDY (M_BANK / BN)        // 128
#define SWG 8

#define QSCALE 23.0f

// ---------------- scratch ----------------
__device__ char  g_E8[N_EMB * DIM];
__device__ char  g_M8[M_BANK * DIM];
__device__ int   g_ynq[M_BANK];
__device__ unsigned long long g_minpack[N_EMB];
__device__ unsigned long long g_nnpack[BATCH];
__device__ unsigned long long g_maxpack[BATCH];   // (fkey(score) << 32) | (PPI-1-p)
__device__ float g_xnorm[N_EMB];
__device__ float g_ynorm[M_BANK];
__device__ float g_d2[BATCH * M_BANK];

__device__ __forceinline__ unsigned fkey(float f) {
    unsigned u = __float_as_uint(f);
    return (u & 0x80000000u) ? ~u : (u | 0x80000000u);
}
__device__ __forceinline__ float unkey(unsigned k) {
    unsigned u = (k & 0x80000000u) ? (k ^ 0x80000000u) : ~k;
    return __uint_as_float(u);
}

__device__ __forceinline__ void cpasync16(uint32_t dst, const void* src) {
    asm volatile("cp.async.cg.shared.global [%0], [%1], 16;" :: "r"(dst), "l"(src));
}
__device__ __forceinline__ void ldsm4(uint32_t* r, uint32_t addr) {
    asm volatile("ldmatrix.sync.aligned.m8n8.x4.shared.b16 {%0,%1,%2,%3}, [%4];"
                 : "=r"(r[0]), "=r"(r[1]), "=r"(r[2]), "=r"(r[3]) : "r"(addr));
}
__device__ __forceinline__ void mma_s8(int* c, const uint32_t* a, uint32_t b0, uint32_t b1) {
    asm volatile("mma.sync.aligned.m16n8k32.row.col.s32.s8.s8.s32 "
                 "{%0,%1,%2,%3}, {%4,%5,%6,%7}, {%8,%9}, {%0,%1,%2,%3};"
                 : "+r"(c[0]), "+r"(c[1]), "+r"(c[2]), "+r"(c[3])
                 : "r"(a[0]), "r"(a[1]), "r"(a[2]), "r"(a[3]), "r"(b0), "r"(b1));
}

__device__ __forceinline__ int q8(float x) {
    int v = __float2int_rn(x * QSCALE);
    return max(-127, min(127, v));
}

// ---------------- fused convert-to-int8 + norms + scratch init ----------------
__global__ void convert_norms_kernel(const float* __restrict__ E, const float* __restrict__ Mb) {
    int row = blockIdx.x;
    const bool isE = row < N_EMB;
    const float* p = isE ? (E + (size_t)row * DIM) : (Mb + (size_t)(row - N_EMB) * DIM);
    char* q = isE ? (g_E8 + (size_t)row * DIM) : (g_M8 + (size_t)(row - N_EMB) * DIM);
    float s = 0.f;
    int   sq = 0;
    for (int i = threadIdx.x; i < DIM / 4; i += blockDim.x) {
        float4 v = ((const float4*)p)[i];
        s += v.x * v.x + v.y * v.y + v.z * v.z + v.w * v.w;
        int a = q8(v.x), b = q8(v.y), c = q8(v.z), d = q8(v.w);
        sq += a * a + b * b + c * c + d * d;
        uint32_t pk = (uint32_t)(a & 0xff) | ((uint32_t)(b & 0xff) << 8) |
                      ((uint32_t)(c & 0xff) << 16) | ((uint32_t)(d & 0xff) << 24);
        ((uint32_t*)q)[i] = pk;
    }
#pragma unroll
    for (int o = 16; o; o >>= 1) {
        s  += __shfl_down_sync(0xffffffffu, s, o);
        sq += __shfl_down_sync(0xffffffffu, sq, o);
    }
    __shared__ float ws[4];
    __shared__ int   wq[4];
    if ((threadIdx.x & 31) == 0) { ws[threadIdx.x >> 5] = s; wq[threadIdx.x >> 5] = sq; }
    __syncthreads();
    if (threadIdx.x == 0) {
        float t = ws[0] + ws[1] + ws[2] + ws[3];
        int   ti = wq[0] + wq[1] + wq[2] + wq[3];
        if (isE) {
            g_xnorm[row] = t;
            g_minpack[row] = 0xFFFFFFFFFFFFFFFFull;
            if (row < BATCH) { g_nnpack[row] = 0xFFFFFFFFFFFFFFFFull; g_maxpack[row] = 0ull; }
        } else {
            g_ynorm[row - N_EMB] = t; g_ynq[row - N_EMB] = ti;
        }
    }
}

// ---------------- Phase A: int8 tensor-core dist-argmin GEMM ----------------
__global__ void __launch_bounds__(256, 2) distmin_s8() {
    extern __shared__ char dsm[];
    const int tid = threadIdx.x;
    const int lane = tid & 31, warp = tid >> 5;
    const int wr = warp & 3, wc = warp >> 2;

    const int band = blockIdx.x / (GRIDX * SWG);
    const int rem  = blockIdx.x % (GRIDX * SWG);
    const int by   = band * SWG + (rem % SWG);
    const int bx   = rem / SWG;
    const int rowBase = bx * BM;
    const int colBase = by * BN;

    uint32_t sbase = (uint32_t)__cvta_generic_to_shared(dsm);

    const char* src[8];
    uint32_t dsto[8];
#pragma unroll
    for (int i = 0; i < 8; i++) {
        int idx = tid + i * 256;
        if (idx < 1024) {
            int row = idx >> 3, c = idx & 7;
            src[i]  = g_E8 + (size_t)(rowBase + row) * DIM + c * 16;
            dsto[i] = row * STRIDE_B + c * 16;
        } else {
            int j = idx - 1024;
            int row = j >> 3, c = j & 7;
            src[i]  = g_M8 + (size_t)(colBase + row) * DIM + c * 16;
            dsto[i] = A_BYTES + row * STRIDE_B + c * 16;
        }
    }

    const int arow = (lane & 7) + ((lane >> 3) & 1) * 8;
    const uint32_t akb = (lane >> 4) * 16;
    uint32_t aAddr[2];
#pragma unroll
    for (int m = 0; m < 2; m++)
        aAddr[m] = sbase + (wr * 32 + m * 16 + arow) * STRIDE_B + akb;
    const int brow = (lane & 7) + (lane >> 4) * 8;
    const uint32_t bkb = ((lane >> 3) & 1) * 16;
    uint32_t bAddr[4];
#pragma unroll
    for (int g = 0; g < 4; g++)
        bAddr[g] = sbase + A_BYTES + (wc * 64 + g * 16 + brow) * STRIDE_B + bkb;

    int acc[2][8][4];
#pragma unroll
    for (int m = 0; m < 2; m++)
#pragma unroll
        for (int t = 0; t < 8; t++)
#pragma unroll
            for (int c = 0; c < 4; c++) acc[m][t][c] = 0;

#pragma unroll
    for (int s = 0; s < NSTAGE - 1; s++) {
#pragma unroll
        for (int i = 0; i < 8; i++) cpasync16(sbase + s * STAGE_BYTES + dsto[i], src[i] + s * BK);
        asm volatile("cp.async.commit_group;");
    }

#pragma unroll
    for (int kt = 0; kt < KTILES; kt++) {
        const int st = kt % NSTAGE;
        asm volatile("cp.async.wait_group %0;" :: "n"(NSTAGE - 2));
        __syncthreads();
        if (kt + NSTAGE - 1 < KTILES) {
            const int ps = (kt + NSTAGE - 1) % NSTAGE;
            const int ko = (kt + NSTAGE - 1) * BK;
#pragma unroll
            for (int i = 0; i < 8; i++) cpasync16(sbase + ps * STAGE_BYTES + dsto[i], src[i] + ko);
            asm volatile("cp.async.commit_group;");
        }
        const uint32_t so = st * STAGE_BYTES;
#pragma unroll
        for (int s = 0; s < 4; s++) {
            uint32_t af[2][4], bf[4][4];
#pragma unroll
            for (int m = 0; m < 2; m++) ldsm4(af[m], aAddr[m] + so + s * 32);
#pragma unroll
            for (int g = 0; g < 4; g++) ldsm4(bf[g], bAddr[g] + so + s * 32);
#pragma unroll
            for (int m = 0; m < 2; m++)
#pragma unroll
                for (int t = 0; t < 8; t++)
                    mma_s8(acc[m][t], af[m], bf[t >> 1][(t & 1) * 2], bf[t >> 1][(t & 1) * 2 + 1]);
        }
    }
    __syncthreads();

    // epilogue: integer q = ynq - 2*dot ; per-row argmin (ties -> lowest col)
    const int gid = lane >> 2, qid = lane & 3;
    unsigned long long* red = (unsigned long long*)dsm;
#pragma unroll
    for (int m = 0; m < 2; m++)
#pragma unroll
        for (int h = 0; h < 2; h++) {
            int bv = 0x7fffffff;
            int bj = 0x7fffffff;
#pragma unroll
            for (int t = 0; t < 8; t++)
#pragma unroll
                for (int c = 0; c < 2; c++) {
                    int col = colBase + wc * 64 + t * 8 + qid * 2 + c;
                    int q = g_ynq[col] - 2 * acc[m][t][h * 2 + c];
                    if (q < bv || (q == bv && col < bj)) { bv = q; bj = col; }
                }
#pragma unroll
            for (int off = 1; off < 4; off <<= 1) {
                int ov = __shfl_xor_sync(0xffffffffu, bv, off, 4);
                int oj = __shfl_xor_sync(0xffffffffu, bj, off, 4);
                if (ov < bv || (ov == bv && oj < bj)) { bv = ov; bj = oj; }
            }
            if (qid == 0) {
                int rloc = wr * 32 + m * 16 + h * 8 + gid;
                unsigned ku = (unsigned)bv ^ 0x80000000u;
                red[wc * 128 + rloc] = ((unsigned long long)ku << 32) | (unsigned)bj;
            }
        }
    __syncthreads();
    if (tid < BM) {
        unsigned long long p = red[tid];
        unsigned long long q1 = red[128 + tid]; if (q1 < p) p = q1;
        atomicMin(&g_minpack[rowBase + tid], p);
    }
}

// ---------------- exact fp32 rescore + fused per-image argmax ----------------
__global__ void rescore_kernel(const float* __restrict__ E, const float* __restrict__ Mb) {
    int warp = threadIdx.x >> 5, lane = threadIdx.x & 31;
    int row = blockIdx.x * 8 + warp;
    int col = (int)(g_minpack[row] & 0xffffffffull);
    const float4* x = (const float4*)(E + (size_t)row * DIM);
    const float4* y = (const float4*)(Mb + (size_t)col * DIM);
    float s = 0.f;
    for (int i = lane; i < DIM / 4; i += 32) {
        float4 a = x[i], b = y[i];
        s += a.x * b.x + a.y * b.y + a.z * b.z + a.w * b.w;
    }
#pragma unroll
    for (int o = 16; o; o >>= 1) s += __shfl_down_sync(0xffffffffu, s, o);
    if (lane == 0) {
        float d2 = g_xnorm[row] + g_ynorm[col] - 2.f * s;
        float sc = sqrtf(fmaxf(d2, 0.f));
        int b = row / PPI, p = row % PPI;
        unsigned long long pk = ((unsigned long long)fkey(sc) << 32) | (unsigned)(PPI - 1 - p);
        atomicMax(&g_maxpack[b], pk);
    }
}

// ---------------- exact fp32 NN search for the 16 argmax rows ----------------
__global__ void exactnn_kernel(const float* __restrict__ E, const float* __restrict__ Mb) {
    __shared__ float Qs[16 * 384];
    __shared__ int   qr[16];
    __shared__ unsigned long long part[16];
    int tid = threadIdx.x;
    if (tid < 16) {
        int p = PPI - 1 - (int)(g_maxpack[tid] & 0xffffffffull);
        qr[tid] = tid * PPI + p;
        part[tid] = 0xFFFFFFFFFFFFFFFFull;
    }
    __syncthreads();
    int col = blockIdx.x * 128 + tid;
    float acc[16];
#pragma unroll
    for (int q = 0; q < 16; q++) acc[q] = 0.f;
    for (int c = 0; c < 4; c++) {
        for (int i = tid; i < 1536; i += 128) {
            int q = i / 96, d4 = i % 96;
            *(float4*)&Qs[q * 384 + d4 * 4] =
                *(const float4*)(E + (size_t)qr[q] * DIM + c * 384 + d4 * 4);
        }
        __syncthreads();
        const float4* rp = (const float4*)(Mb + (size_t)col * DIM + c * 384);
#pragma unroll 4
        for (int d4 = 0; d4 < 96; d4++) {
            float4 v = rp[d4];
#pragma unroll
            for (int q = 0; q < 16; q++) {
                float4 u = *(const float4*)&Qs[q * 384 + d4 * 4];
                acc[q] = fmaf(v.x, u.x, fmaf(v.y, u.y, fmaf(v.z, u.z, fmaf(v.w, u.w, acc[q]))));
            }
        }
        __syncthreads();
    }
    float yn = g_ynorm[col];
#pragma unroll
    for (int q = 0; q < 16; q++) {
        float d2 = g_xnorm[qr[q]] + yn - 2.f * acc[q];
        unsigned long long pk = ((unsigned long long)fkey(d2) << 32) | (unsigned)col;
        atomicMin(&part[q], pk);
    }
    __syncthreads();
    if (tid < 16) atomicMin(&g_nnpack[tid], part[tid]);
}

// ---------------- Phase C1: d^2 from 16 nn_samples to all memory rows ----------------
__global__ void knn_dist_kernel(const float* __restrict__ Mb) {
    __shared__ float Qs[16 * 384];
    __shared__ int   nn[16];
    __shared__ float qn[16];
    int tid = threadIdx.x;
    if (tid < 16) {
        int idx = (int)(g_nnpack[tid] & 0xffffffffull);
        nn[tid] = idx; qn[tid] = g_ynorm[idx];
    }
    __syncthreads();
    int row = blockIdx.x * 128 + tid;
    float acc[16];
#pragma unroll
    for (int q = 0; q < 16; q++) acc[q] = 0.f;
    for (int c = 0; c < 4; c++) {
        for (int i = tid; i < 1536; i += 128) {
            int q = i / 96, d4 = i % 96;
            *(float4*)&Qs[q * 384 + d4 * 4] =
                *(const float4*)(Mb + (size_t)nn[q] * DIM + c * 384 + d4 * 4);
        }
        __syncthreads();
        const float4* rp = (const float4*)(Mb + (size_t)row * DIM + c * 384);
#pragma unroll 4
        for (int d4 = 0; d4 < 96; d4++) {
            float4 v = rp[d4];
#pragma unroll
            for (int q = 0; q < 16; q++) {
                float4 u = *(const float4*)&Qs[q * 384 + d4 * 4];
                acc[q] = fmaf(v.x, u.x, fmaf(v.y, u.y, fmaf(v.z, u.z, fmaf(v.w, u.w, acc[q]))));
            }
        }
        __syncthreads();
    }
    float yn = g_ynorm[row];
#pragma unroll
    for (int q = 0; q < 16; q++)
        g_d2[q * M_BANK + row] = qn[q] + yn - 2.f * acc[q];
}

// ---------------- Phase C2 + D: stable top-9, distances, softmax, output ----------------
__global__ void top9_final_kernel(const float* __restrict__ E, const float* __restrict__ Mb,
                                  float* __restrict__ out) {
    int b = blockIdx.x;
    int tid = threadIdx.x;
    float v[9]; int id[9];
#pragma unroll
    for (int k = 0; k < 9; k++) { v[k] = __int_as_float(0x7f800000); id[k] = 0x7fffffff; }
    for (int j = tid; j < M_BANK; j += 128) {
        float d = g_d2[b * M_BANK + j];
        if (d < v[8] || (d == v[8] && j < id[8])) {
            int k = 8;
            while (k > 0 && (d < v[k - 1] || (d == v[k - 1] && j < id[k - 1]))) {
                v[k] = v[k - 1]; id[k] = id[k - 1]; k--;
            }
            v[k] = d; id[k] = j;
        }
    }
    __shared__ float svv[128 * 9];
    __shared__ int   sid[128 * 9];
    __shared__ int   s_sup[9];
    __shared__ float s_ds[9];
    __shared__ float s_red[4];
#pragma unroll
    for (int k = 0; k < 9; k++) { svv[tid * 9 + k] = v[k]; sid[tid * 9 + k] = id[k]; }
    __syncthreads();
    if (tid == 0) {
        float fv[9]; int fid[9];
#pragma unroll
        for (int k = 0; k < 9; k++) { fv[k] = __int_as_float(0x7f800000); fid[k] = 0x7fffffff; }
        for (int t = 0; t < 128; t++) {
            for (int k = 0; k < 9; k++) {
                float d = svv[t * 9 + k]; int j = sid[t * 9 + k];
                if (d > fv[8] || (d == fv[8] && j >= fid[8])) break;
                int m = 8;
                while (m > 0 && (d < fv[m - 1] || (d == fv[m - 1] && j < fid[m - 1]))) {
                    fv[m] = fv[m - 1]; fid[m] = fid[m - 1]; m--;
                }
                fv[m] = d; fid[m] = j;
            }
        }
        for (int k = 0; k < 9; k++) s_sup[k] = fid[k];
    }
    __syncthreads();

    // fused Phase D: exact distances max_patch_feat -> 9 support rows, softmax weight
    unsigned long long mp = g_maxpack[b];
    int maxrow = b * PPI + (PPI - 1 - (int)(mp & 0xffffffffull));
    const float4* x = (const float4*)(E + (size_t)maxrow * DIM);
    for (int k = 0; k < 9; k++) {
        const float4* y = (const float4*)(Mb + (size_t)s_sup[k] * DIM);
        float s = 0.f;
        for (int i = tid; i < 384; i += 128) {
            float4 xv = x[i], yv = y[i];
            float dx = xv.x - yv.x, dy = xv.y - yv.y, dz = xv.z - yv.z, dw = xv.w - yv.w;
            s += dx * dx + dy * dy + dz * dz + dw * dw;
        }
#pragma unroll
        for (int o = 16; o; o >>= 1) s += __shfl_down_sync(0xffffffffu, s, o);
        if ((tid & 31) == 0) s_red[tid >> 5] = s;
        __syncthreads();
        if (tid == 0) s_ds[k] = sqrtf(fmaxf(s_red[0] + s_red[1] + s_red[2] + s_red[3], 0.f));
        __syncthreads();
    }
    if (tid == 0) {
        float m = s_ds[0];
        for (int k = 1; k < 9; k++) m = fmaxf(m, s_ds[k]);
        float sum = 0.f, e0 = 0.f;
        for (int k = 0; k < 9; k++) {
            float e = expf(s_ds[k] - m);
            if (k == 0) e0 = e;
            sum += e;
        }
        out[b] = (1.f - e0 / sum) * unkey((unsigned)(mp >> 32));
    }
}

// ---------------- launch ----------------
extern "C" void kernel_launch(void* const* d_in, const int* in_sizes, int n_in,
                              void* d_out, int out_size) {
    const float* E  = (const float*)d_in[0];
    const float* Mb = (const float*)d_in[1];
    float* out = (float*)d_out;

    cudaFuncSetAttribute(distmin_s8, cudaFuncAttributeMaxDynamicSharedMemorySize, SMEM_BYTES);

    convert_norms_kernel<<<N_EMB + M_BANK, 128>>>(E, Mb);
    distmin_s8<<<GRIDX * GRIDY, 256, SMEM_BYTES>>>();
    rescore_kernel<<<N_EMB / 8, 256>>>(E, Mb);
    exactnn_kernel<<<M_BANK / 128, 128>>>(E, Mb);
    knn_dist_kernel<<<M_BANK / 128, 128>>>(Mb);
    top9_final_kernel<<<BATCH, 128>>>(E, Mb, out);
}

// round 11
// speedup vs baseline: 16.8482x; 1.1174x over previous
#include <cuda_runtime.h>
#include <cuda_bf16.h>
#include <math.h>
#include <stdint.h>

#define N_EMB 12544
#define M_BANK 16384
#define DIM 1536
#define BATCH 16
#define PPI 784
#define KNN 9

// ---- Phase A tiling (int8 mma.m16n8k32), 2 CTAs/SM, BK=128 ----
#define BM 128
#define BN 128
#define BK 128
#define KTILES (DIM / BK)          // 12
#define NSTAGE 3
#define STRIDE_B 144               // 128 data + 16 pad -> conflict-free ldmatrix
#define A_BYTES (BM * STRIDE_B)
#define B_BYTES (BN * STRIDE_B)
#define STAGE_BYTES (A_BYTES + B_BYTES)   // 36864
#define SMEM_BYTES (NSTAGE * STAGE_BYTES) // 110592
#define GRIDX (N_EMB / BM)         // 98
#define GRIDY (M_BANK / BN)        // 128
#define SWG 8

#define QSCALE 23.0f
#define QS_BYTES (16 * DIM * 4)    // 98304 B dynamic smem for the 16-query scan kernels

// ---------------- scratch ----------------
__device__ char  g_E8[N_EMB * DIM];
__device__ char  g_M8[M_BANK * DIM];
__device__ int   g_ynq[M_BANK];
__device__ unsigned long long g_minpack[N_EMB];
__device__ unsigned long long g_nnpack[BATCH];
__device__ unsigned long long g_maxpack[BATCH];   // (fkey(score) << 32) | (PPI-1-p)
__device__ float g_xnorm[N_EMB];
__device__ float g_ynorm[M_BANK];
__device__ float g_d2[BATCH * M_BANK];

__device__ __forceinline__ unsigned fkey(float f) {
    unsigned u = __float_as_uint(f);
    return (u & 0x80000000u) ? ~u : (u | 0x80000000u);
}
__device__ __forceinline__ float unkey(unsigned k) {
    unsigned u = (k & 0x80000000u) ? (k ^ 0x80000000u) : ~k;
    return __uint_as_float(u);
}

__device__ __forceinline__ void cpasync16(uint32_t dst, const void* src) {
    asm volatile("cp.async.cg.shared.global [%0], [%1], 16;" :: "r"(dst), "l"(src));
}
__device__ __forceinline__ void ldsm4(uint32_t* r, uint32_t addr) {
    asm volatile("ldmatrix.sync.aligned.m8n8.x4.shared.b16 {%0,%1,%2,%3}, [%4];"
                 : "=r"(r[0]), "=r"(r[1]), "=r"(r[2]), "=r"(r[3]) : "r"(addr));
}
__device__ __forceinline__ void mma_s8(int* c, const uint32_t* a, uint32_t b0, uint32_t b1) {
    asm volatile("mma.sync.aligned.m16n8k32.row.col.s32.s8.s8.s32 "
                 "{%0,%1,%2,%3}, {%4,%5,%6,%7}, {%8,%9}, {%0,%1,%2,%3};"
                 : "+r"(c[0]), "+r"(c[1]), "+r"(c[2]), "+r"(c[3])
                 : "r"(a[0]), "r"(a[1]), "r"(a[2]), "r"(a[3]), "r"(b0), "r"(b1));
}

__device__ __forceinline__ int q8(float x) {
    int v = __float2int_rn(x * QSCALE);
    return max(-127, min(127, v));
}

// ---------------- fused convert-to-int8 + norms + scratch init ----------------
__global__ void convert_norms_kernel(const float* __restrict__ E, const float* __restrict__ Mb) {
    int row = blockIdx.x;
    const bool isE = row < N_EMB;
    const float* p = isE ? (E + (size_t)row * DIM) : (Mb + (size_t)(row - N_EMB) * DIM);
    char* q = isE ? (g_E8 + (size_t)row * DIM) : (g_M8 + (size_t)(row - N_EMB) * DIM);
    float s = 0.f;
    int   sq = 0;
    for (int i = threadIdx.x; i < DIM / 4; i += blockDim.x) {
        float4 v = ((const float4*)p)[i];
        s += v.x * v.x + v.y * v.y + v.z * v.z + v.w * v.w;
        int a = q8(v.x), b = q8(v.y), c = q8(v.z), d = q8(v.w);
        sq += a * a + b * b + c * c + d * d;
        uint32_t pk = (uint32_t)(a & 0xff) | ((uint32_t)(b & 0xff) << 8) |
                      ((uint32_t)(c & 0xff) << 16) | ((uint32_t)(d & 0xff) << 24);
        ((uint32_t*)q)[i] = pk;
    }
#pragma unroll
    for (int o = 16; o; o >>= 1) {
        s  += __shfl_down_sync(0xffffffffu, s, o);
        sq += __shfl_down_sync(0xffffffffu, sq, o);
    }
    __shared__ float ws[4];
    __shared__ int   wq[4];
    if ((threadIdx.x & 31) == 0) { ws[threadIdx.x >> 5] = s; wq[threadIdx.x >> 5] = sq; }
    __syncthreads();
    if (threadIdx.x == 0) {
        float t = ws[0] + ws[1] + ws[2] + ws[3];
        int   ti = wq[0] + wq[1] + wq[2] + wq[3];
        if (isE) {
            g_xnorm[row] = t;
            g_minpack[row] = 0xFFFFFFFFFFFFFFFFull;
            if (row < BATCH) { g_nnpack[row] = 0xFFFFFFFFFFFFFFFFull; g_maxpack[row] = 0ull; }
        } else {
            g_ynorm[row - N_EMB] = t; g_ynq[row - N_EMB] = ti;
        }
    }
}

// ---------------- Phase A: int8 tensor-core dist-argmin GEMM ----------------
__global__ void __launch_bounds__(256, 2) distmin_s8() {
    extern __shared__ char dsm[];
    const int tid = threadIdx.x;
    const int lane = tid & 31, warp = tid >> 5;
    const int wr = warp & 3, wc = warp >> 2;

    const int band = blockIdx.x / (GRIDX * SWG);
    const int rem  = blockIdx.x % (GRIDX * SWG);
    const int by   = band * SWG + (rem % SWG);
    const int bx   = rem / SWG;
    const int rowBase = bx * BM;
    const int colBase = by * BN;

    uint32_t sbase = (uint32_t)__cvta_generic_to_shared(dsm);

    const char* src[8];
    uint32_t dsto[8];
#pragma unroll
    for (int i = 0; i < 8; i++) {
        int idx = tid + i * 256;
        if (idx < 1024) {
            int row = idx >> 3, c = idx & 7;
            src[i]  = g_E8 + (size_t)(rowBase + row) * DIM + c * 16;
            dsto[i] = row * STRIDE_B + c * 16;
        } else {
            int j = idx - 1024;
            int row = j >> 3, c = j & 7;
            src[i]  = g_M8 + (size_t)(colBase + row) * DIM + c * 16;
            dsto[i] = A_BYTES + row * STRIDE_B + c * 16;
        }
    }

    const int arow = (lane & 7) + ((lane >> 3) & 1) * 8;
    const uint32_t akb = (lane >> 4) * 16;
    uint32_t aAddr[2];
#pragma unroll
    for (int m = 0; m < 2; m++)
        aAddr[m] = sbase + (wr * 32 + m * 16 + arow) * STRIDE_B + akb;
    const int brow = (lane & 7) + (lane >> 4) * 8;
    const uint32_t bkb = ((lane >> 3) & 1) * 16;
    uint32_t bAddr[4];
#pragma unroll
    for (int g = 0; g < 4; g++)
        bAddr[g] = sbase + A_BYTES + (wc * 64 + g * 16 + brow) * STRIDE_B + bkb;

    int acc[2][8][4];
#pragma unroll
    for (int m = 0; m < 2; m++)
#pragma unroll
        for (int t = 0; t < 8; t++)
#pragma unroll
            for (int c = 0; c < 4; c++) acc[m][t][c] = 0;

#pragma unroll
    for (int s = 0; s < NSTAGE - 1; s++) {
#pragma unroll
        for (int i = 0; i < 8; i++) cpasync16(sbase + s * STAGE_BYTES + dsto[i], src[i] + s * BK);
        asm volatile("cp.async.commit_group;");
    }

#pragma unroll
    for (int kt = 0; kt < KTILES; kt++) {
        const int st = kt % NSTAGE;
        asm volatile("cp.async.wait_group %0;" :: "n"(NSTAGE - 2));
        __syncthreads();
        if (kt + NSTAGE - 1 < KTILES) {
            const int ps = (kt + NSTAGE - 1) % NSTAGE;
            const int ko = (kt + NSTAGE - 1) * BK;
#pragma unroll
            for (int i = 0; i < 8; i++) cpasync16(sbase + ps * STAGE_BYTES + dsto[i], src[i] + ko);
            asm volatile("cp.async.commit_group;");
        }
        const uint32_t so = st * STAGE_BYTES;
#pragma unroll
        for (int s = 0; s < 4; s++) {
            uint32_t af[2][4], bf[4][4];
#pragma unroll
            for (int m = 0; m < 2; m++) ldsm4(af[m], aAddr[m] + so + s * 32);
#pragma unroll
            for (int g = 0; g < 4; g++) ldsm4(bf[g], bAddr[g] + so + s * 32);
#pragma unroll
            for (int m = 0; m < 2; m++)
#pragma unroll
                for (int t = 0; t < 8; t++)
                    mma_s8(acc[m][t], af[m], bf[t >> 1][(t & 1) * 2], bf[t >> 1][(t & 1) * 2 + 1]);
        }
    }
    __syncthreads();

    const int gid = lane >> 2, qid = lane & 3;
    unsigned long long* red = (unsigned long long*)dsm;
#pragma unroll
    for (int m = 0; m < 2; m++)
#pragma unroll
        for (int h = 0; h < 2; h++) {
            int bv = 0x7fffffff;
            int bj = 0x7fffffff;
#pragma unroll
            for (int t = 0; t < 8; t++)
#pragma unroll
                for (int c = 0; c < 2; c++) {
                    int col = colBase + wc * 64 + t * 8 + qid * 2 + c;
                    int q = g_ynq[col] - 2 * acc[m][t][h * 2 + c];
                    if (q < bv || (q == bv && col < bj)) { bv = q; bj = col; }
                }
#pragma unroll
            for (int off = 1; off < 4; off <<= 1) {
                int ov = __shfl_xor_sync(0xffffffffu, bv, off, 4);
                int oj = __shfl_xor_sync(0xffffffffu, bj, off, 4);
                if (ov < bv || (ov == bv && oj < bj)) { bv = ov; bj = oj; }
            }
            if (qid == 0) {
                int rloc = wr * 32 + m * 16 + h * 8 + gid;
                unsigned ku = (unsigned)bv ^ 0x80000000u;
                red[wc * 128 + rloc] = ((unsigned long long)ku << 32) | (unsigned)bj;
            }
        }
    __syncthreads();
    if (tid < BM) {
        unsigned long long p = red[tid];
        unsigned long long q1 = red[128 + tid]; if (q1 < p) p = q1;
        atomicMin(&g_minpack[rowBase + tid], p);
    }
}

// ---------------- exact fp32 rescore + fused per-image argmax ----------------
__global__ void rescore_kernel(const float* __restrict__ E, const float* __restrict__ Mb) {
    int warp = threadIdx.x >> 5, lane = threadIdx.x & 31;
    int row = blockIdx.x * 8 + warp;
    int col = (int)(g_minpack[row] & 0xffffffffull);
    const float4* x = (const float4*)(E + (size_t)row * DIM);
    const float4* y = (const float4*)(Mb + (size_t)col * DIM);
    float s = 0.f;
    for (int i = lane; i < DIM / 4; i += 32) {
        float4 a = x[i], b = y[i];
        s += a.x * b.x + a.y * b.y + a.z * b.z + a.w * b.w;
    }
#pragma unroll
    for (int o = 16; o; o >>= 1) s += __shfl_down_sync(0xffffffffu, s, o);
    if (lane == 0) {
        float d2 = g_xnorm[row] + g_ynorm[col] - 2.f * s;
        float sc = sqrtf(fmaxf(d2, 0.f));
        int b = row / PPI, p = row % PPI;
        unsigned long long pk = ((unsigned long long)fkey(sc) << 32) | (unsigned)(PPI - 1 - p);
        atomicMax(&g_maxpack[b], pk);
    }
}

// ---------------- exact fp32 NN search for the 16 argmax rows ----------------
// block = 256 threads = 64 col-slots x 4 D-quarters; each slot owns cols (c0, c0+64)
__global__ void __launch_bounds__(256) exactnn_kernel(const float* __restrict__ E,
                                                      const float* __restrict__ Mb) {
    extern __shared__ float Qs[];          // 16 x 1536 floats = 96 KB
    __shared__ int qr[16];
    __shared__ unsigned long long part[16];
    const int tid = threadIdx.x;
    const int s = tid & 63, g = tid >> 6;
    if (tid < 16) {
        int p = PPI - 1 - (int)(g_maxpack[tid] & 0xffffffffull);
        qr[tid] = tid * PPI + p;
        part[tid] = 0xFFFFFFFFFFFFFFFFull;
    }
    __syncthreads();
    for (int i = tid; i < 16 * 384; i += 256) {
        int q = i / 384, d4 = i % 384;
        ((float4*)Qs)[i] = ((const float4*)(E + (size_t)qr[q] * DIM))[d4];
    }
    __syncthreads();

    const int col0 = blockIdx.x * 128 + s;
    const int col1 = col0 + 64;
    float acc0[16], acc1[16];
#pragma unroll
    for (int q = 0; q < 16; q++) { acc0[q] = 0.f; acc1[q] = 0.f; }
    const float4* r0 = (const float4*)(Mb + (size_t)col0 * DIM) + g * 96;
    const float4* r1 = (const float4*)(Mb + (size_t)col1 * DIM) + g * 96;
    const float4* Qb = ((const float4*)Qs) + g * 96;
#pragma unroll 2
    for (int d4 = 0; d4 < 96; d4++) {
        float4 v0 = r0[d4], v1 = r1[d4];
#pragma unroll
        for (int q = 0; q < 16; q++) {
            float4 u = Qb[q * 384 + d4];
            acc0[q] = fmaf(v0.x, u.x, fmaf(v0.y, u.y, fmaf(v0.z, u.z, fmaf(v0.w, u.w, acc0[q]))));
            acc1[q] = fmaf(v1.x, u.x, fmaf(v1.y, u.y, fmaf(v1.z, u.z, fmaf(v1.w, u.w, acc1[q]))));
        }
    }
    __syncthreads();                       // Qs reads done; reuse as reduction buffer
    float* red = Qs;                       // red[k*256 + g*64 + s], k = 0..31
#pragma unroll
    for (int q = 0; q < 16; q++) {
        red[q * 256 + g * 64 + s]        = acc0[q];
        red[(16 + q) * 256 + g * 64 + s] = acc1[q];
    }
    __syncthreads();
    if (g == 0) {
        float yn0 = g_ynorm[col0], yn1 = g_ynorm[col1];
#pragma unroll
        for (int q = 0; q < 16; q++) {
            float d0 = red[q * 256 + s] + red[q * 256 + 64 + s] +
                       red[q * 256 + 128 + s] + red[q * 256 + 192 + s];
            float d1 = red[(16 + q) * 256 + s] + red[(16 + q) * 256 + 64 + s] +
                       red[(16 + q) * 256 + 128 + s] + red[(16 + q) * 256 + 192 + s];
            float xn = g_xnorm[qr[q]];
            float e0 = xn + yn0 - 2.f * d0;
            float e1 = xn + yn1 - 2.f * d1;
            atomicMin(&part[q], ((unsigned long long)fkey(e0) << 32) | (unsigned)col0);
            atomicMin(&part[q], ((unsigned long long)fkey(e1) << 32) | (unsigned)col1);
        }
    }
    __syncthreads();
    if (tid < 16) atomicMin(&g_nnpack[tid], part[tid]);
}

// ---------------- Phase C1: d^2 from 16 nn_samples to all memory rows ----------------
__global__ void __launch_bounds__(256) knn_dist_kernel(const float* __restrict__ Mb) {
    extern __shared__ float Qs[];          // 16 x 1536 floats = 96 KB
    __shared__ int nn[16];
    __shared__ float qn[16];
    const int tid = threadIdx.x;
    const int s = tid & 63, g = tid >> 6;
    if (tid < 16) {
        int idx = (int)(g_nnpack[tid] & 0xffffffffull);
        nn[tid] = idx; qn[tid] = g_ynorm[idx];
    }
    __syncthreads();
    for (int i = tid; i < 16 * 384; i += 256) {
        int q = i / 384, d4 = i % 384;
        ((float4*)Qs)[i] = ((const float4*)(Mb + (size_t)nn[q] * DIM))[d4];
    }
    __syncthreads();

    const int col0 = blockIdx.x * 128 + s;
    const int col1 = col0 + 64;
    float acc0[16], acc1[16];
#pragma unroll
    for (int q = 0; q < 16; q++) { acc0[q] = 0.f; acc1[q] = 0.f; }
    const float4* r0 = (const float4*)(Mb + (size_t)col0 * DIM) + g * 96;
    const float4* r1 = (const float4*)(Mb + (size_t)col1 * DIM) + g * 96;
    const float4* Qb = ((const float4*)Qs) + g * 96;
#pragma unroll 2
    for (int d4 = 0; d4 < 96; d4++) {
        float4 v0 = r0[d4], v1 = r1[d4];
#pragma unroll
        for (int q = 0; q < 16; q++) {
            float4 u = Qb[q * 384 + d4];
            acc0[q] = fmaf(v0.x, u.x, fmaf(v0.y, u.y, fmaf(v0.z, u.z, fmaf(v0.w, u.w, acc0[q]))));
            acc1[q] = fmaf(v1.x, u.x, fmaf(v1.y, u.y, fmaf(v1.z, u.z, fmaf(v1.w, u.w, acc1[q]))));
        }
    }
    __syncthreads();
    float* red = Qs;
#pragma unroll
    for (int q = 0; q < 16; q++) {
        red[q * 256 + g * 64 + s]        = acc0[q];
        red[(16 + q) * 256 + g * 64 + s] = acc1[q];
    }
    __syncthreads();
    if (g == 0) {
        float yn0 = g_ynorm[col0], yn1 = g_ynorm[col1];
#pragma unroll
        for (int q = 0; q < 16; q++) {
            float d0 = red[q * 256 + s] + red[q * 256 + 64 + s] +
                       red[q * 256 + 128 + s] + red[q * 256 + 192 + s];
            float d1 = red[(16 + q) * 256 + s] + red[(16 + q) * 256 + 64 + s] +
                       red[(16 + q) * 256 + 128 + s] + red[(16 + q) * 256 + 192 + s];
            g_d2[q * M_BANK + col0] = qn[q] + yn0 - 2.f * d0;
            g_d2[q * M_BANK + col1] = qn[q] + yn1 - 2.f * d1;
        }
    }
}

// ---------------- Phase C2 + D: stable top-9, distances, softmax, output ----------------
__global__ void top9_final_kernel(const float* __restrict__ E, const float* __restrict__ Mb,
                                  float* __restrict__ out) {
    int b = blockIdx.x;
    int tid = threadIdx.x;
    float v[9]; int id[9];
#pragma unroll
    for (int k = 0; k < 9; k++) { v[k] = __int_as_float(0x7f800000); id[k] = 0x7fffffff; }
    for (int j = tid; j < M_BANK; j += 128) {
        float d = g_d2[b * M_BANK + j];
        if (d < v[8] || (d == v[8] && j < id[8])) {
            int k = 8;
            while (k > 0 && (d < v[k - 1] || (d == v[k - 1] && j < id[k - 1]))) {
                v[k] = v[k - 1]; id[k] = id[k - 1]; k--;
            }
            v[k] = d; id[k] = j;
        }
    }
    __shared__ float svv[128 * 9];
    __shared__ int   sid[128 * 9];
    __shared__ int   s_sup[9];
    __shared__ float s_ds[9];
    __shared__ float s_red[4];
#pragma unroll
    for (int k = 0; k < 9; k++) { svv[tid * 9 + k] = v[k]; sid[tid * 9 + k] = id[k]; }
    __syncthreads();
    if (tid == 0) {
        float fv[9]; int fid[9];
#pragma unroll
        for (int k = 0; k < 9; k++) { fv[k] = __int_as_float(0x7f800000); fid[k] = 0x7fffffff; }
        for (int t = 0; t < 128; t++) {
            for (int k = 0; k < 9; k++) {
                float d = svv[t * 9 + k]; int j = sid[t * 9 + k];
                if (d > fv[8] || (d == fv[8] && j >= fid[8])) break;
                int m = 8;
                while (m > 0 && (d < fv[m - 1] || (d == fv[m - 1] && j < fid[m - 1]))) {
                    fv[m] = fv[m - 1]; fid[m] = fid[m - 1]; m--;
                }
                fv[m] = d; fid[m] = j;
            }
        }
        for (int k = 0; k < 9; k++) s_sup[k] = fid[k];
    }
    __syncthreads();

    unsigned long long mp = g_maxpack[b];
    int maxrow = b * PPI + (PPI - 1 - (int)(mp & 0xffffffffull));
    const float4* x = (const float4*)(E + (size_t)maxrow * DIM);
    for (int k = 0; k < 9; k++) {
        const float4* y = (const float4*)(Mb + (size_t)s_sup[k] * DIM);
        float s = 0.f;
        for (int i = tid; i < 384; i += 128) {
            float4 xv = x[i], yv = y[i];
            float dx = xv.x - yv.x, dy = xv.y - yv.y, dz = xv.z - yv.z, dw = xv.w - yv.w;
            s += dx * dx + dy * dy + dz * dz + dw * dw;
        }
#pragma unroll
        for (int o = 16; o; o >>= 1) s += __shfl_down_sync(0xffffffffu, s, o);
        if ((tid & 31) == 0) s_red[tid >> 5] = s;
        __syncthreads();
        if (tid == 0) s_ds[k] = sqrtf(fmaxf(s_red[0] + s_red[1] + s_red[2] + s_red[3], 0.f));
        __syncthreads();
    }
    if (tid == 0) {
        float m = s_ds[0];
        for (int k = 1; k < 9; k++) m = fmaxf(m, s_ds[k]);
        float sum = 0.f, e0 = 0.f;
        for (int k = 0; k < 9; k++) {
            float e = expf(s_ds[k] - m);
            if (k == 0) e0 = e;
            sum += e;
        }
        out[b] = (1.f - e0 / sum) * unkey((unsigned)(mp >> 32));
    }
}

// ---------------- launch ----------------
extern "C" void kernel_launch(void* const* d_in, const int* in_sizes, int n_in,
                              void* d_out, int out_size) {
    const float* E  = (const float*)d_in[0];
    const float* Mb = (const float*)d_in[1];
    float* out = (float*)d_out;

    cudaFuncSetAttribute(distmin_s8, cudaFuncAttributeMaxDynamicSharedMemorySize, SMEM_BYTES);
    cudaFuncSetAttribute(exactnn_kernel, cudaFuncAttributeMaxDynamicSharedMemorySize, QS_BYTES);
    cudaFuncSetAttribute(knn_dist_kernel, cudaFuncAttributeMaxDynamicSharedMemorySize, QS_BYTES);

    convert_norms_kernel<<<N_EMB + M_BANK, 128>>>(E, Mb);
    distmin_s8<<<GRIDX * GRIDY, 256, SMEM_BYTES>>>();
    rescore_kernel<<<N_EMB / 8, 256>>>(E, Mb);
    exactnn_kernel<<<M_BANK / 128, 256, QS_BYTES>>>(E, Mb);
    knn_dist_kernel<<<M_BANK / 128, 256, QS_BYTES>>>(Mb);
    top9_final_kernel<<<BATCH, 128>>>(E, Mb, out);
}

// round 13
// speedup vs baseline: 17.2363x; 1.0230x over previous
#include <cuda_runtime.h>
#include <cuda_bf16.h>
#include <math.h>
#include <stdint.h>

#define N_EMB 12544
#define M_BANK 16384
#define DIM 1536
#define BATCH 16
#define PPI 784
#define KNN 9

// ---- Phase A tiling (int8 mma.m16n8k32), 2 CTAs/SM, BK=128 ----
#define BM 128
#define BN 128
#define BK 128
#define KTILES (DIM / BK)          // 12
#define NSTAGE 3
#define STRIDE_B 144               // 128 data + 16 pad -> conflict-free ldmatrix
#define A_BYTES (BM * STRIDE_B)
#define B_BYTES (BN * STRIDE_B)
#define STAGE_BYTES (A_BYTES + B_BYTES)   // 36864
#define SMEM_BYTES (NSTAGE * STAGE_BYTES) // 110592
#define GRIDX (N_EMB / BM)         // 98
#define GRIDY (M_BANK / BN)        // 128
#define SWG 8

#define QSCALE 23.0f
#define QS_BYTES (16 * DIM * 4)    // 98304 B dynamic smem for the 16-query scan kernels

// ---------------- scratch ----------------
__device__ char  g_E8[N_EMB * DIM];
__device__ char  g_M8[M_BANK * DIM];
__device__ int   g_ynq[M_BANK];
__device__ unsigned long long g_minpack[N_EMB];
__device__ unsigned long long g_nnpack[BATCH];
__device__ unsigned long long g_maxpack[BATCH];   // (fkey(score) << 32) | (PPI-1-p)
__device__ float g_xnorm[N_EMB];
__device__ float g_ynorm[M_BANK];
__device__ float g_d2[BATCH * M_BANK];

__device__ __forceinline__ unsigned fkey(float f) {
    unsigned u = __float_as_uint(f);
    return (u & 0x80000000u) ? ~u : (u | 0x80000000u);
}
__device__ __forceinline__ float unkey(unsigned k) {
    unsigned u = (k & 0x80000000u) ? (k ^ 0x80000000u) : ~k;
    return __uint_as_float(u);
}

__device__ __forceinline__ void cpasync16(uint32_t dst, const void* src) {
    asm volatile("cp.async.cg.shared.global [%0], [%1], 16;" :: "r"(dst), "l"(src));
}
__device__ __forceinline__ void ldsm4(uint32_t* r, uint32_t addr) {
    asm volatile("ldmatrix.sync.aligned.m8n8.x4.shared.b16 {%0,%1,%2,%3}, [%4];"
                 : "=r"(r[0]), "=r"(r[1]), "=r"(r[2]), "=r"(r[3]) : "r"(addr));
}
__device__ __forceinline__ void mma_s8(int* c, const uint32_t* a, uint32_t b0, uint32_t b1) {
    asm volatile("mma.sync.aligned.m16n8k32.row.col.s32.s8.s8.s32 "
                 "{%0,%1,%2,%3}, {%4,%5,%6,%7}, {%8,%9}, {%0,%1,%2,%3};"
                 : "+r"(c[0]), "+r"(c[1]), "+r"(c[2]), "+r"(c[3])
                 : "r"(a[0]), "r"(a[1]), "r"(a[2]), "r"(a[3]), "r"(b0), "r"(b1));
}

__device__ __forceinline__ int q8(float x) {
    int v = __float2int_rn(x * QSCALE);
    return max(-127, min(127, v));
}

// ---------------- fused convert-to-int8 + norms + scratch init ----------------
__global__ void convert_norms_kernel(const float* __restrict__ E, const float* __restrict__ Mb) {
    int row = blockIdx.x;
    const bool isE = row < N_EMB;
    const float* p = isE ? (E + (size_t)row * DIM) : (Mb + (size_t)(row - N_EMB) * DIM);
    char* q = isE ? (g_E8 + (size_t)row * DIM) : (g_M8 + (size_t)(row - N_EMB) * DIM);
    float s = 0.f;
    int   sq = 0;
    for (int i = threadIdx.x; i < DIM / 4; i += blockDim.x) {
        float4 v = ((const float4*)p)[i];
        s += v.x * v.x + v.y * v.y + v.z * v.z + v.w * v.w;
        int a = q8(v.x), b = q8(v.y), c = q8(v.z), d = q8(v.w);
        sq += a * a + b * b + c * c + d * d;
        uint32_t pk = (uint32_t)(a & 0xff) | ((uint32_t)(b & 0xff) << 8) |
                      ((uint32_t)(c & 0xff) << 16) | ((uint32_t)(d & 0xff) << 24);
        ((uint32_t*)q)[i] = pk;
    }
#pragma unroll
    for (int o = 16; o; o >>= 1) {
        s  += __shfl_down_sync(0xffffffffu, s, o);
        sq += __shfl_down_sync(0xffffffffu, sq, o);
    }
    __shared__ float ws[4];
    __shared__ int   wq[4];
    if ((threadIdx.x & 31) == 0) { ws[threadIdx.x >> 5] = s; wq[threadIdx.x >> 5] = sq; }
    __syncthreads();
    if (threadIdx.x == 0) {
        float t = ws[0] + ws[1] + ws[2] + ws[3];
        int   ti = wq[0] + wq[1] + wq[2] + wq[3];
        if (isE) {
            g_xnorm[row] = t;
            g_minpack[row] = 0xFFFFFFFFFFFFFFFFull;
            if (row < BATCH) { g_nnpack[row] = 0xFFFFFFFFFFFFFFFFull; g_maxpack[row] = 0ull; }
        } else {
            g_ynorm[row - N_EMB] = t; g_ynq[row - N_EMB] = ti;
        }
    }
}

// ---------------- Phase A: int8 tensor-core dist-argmin GEMM ----------------
__global__ void __launch_bounds__(256, 2) distmin_s8() {
    extern __shared__ char dsm[];
    const int tid = threadIdx.x;
    const int lane = tid & 31, warp = tid >> 5;
    const int wr = warp & 3, wc = warp >> 2;

    const int band = blockIdx.x / (GRIDX * SWG);
    const int rem  = blockIdx.x % (GRIDX * SWG);
    const int by   = band * SWG + (rem % SWG);
    const int bx   = rem / SWG;
    const int rowBase = bx * BM;
    const int colBase = by * BN;

    uint32_t sbase = (uint32_t)__cvta_generic_to_shared(dsm);

    const char* src[8];
    uint32_t dsto[8];
#pragma unroll
    for (int i = 0; i < 8; i++) {
        int idx = tid + i * 256;
        if (idx < 1024) {
            int row = idx >> 3, c = idx & 7;
            src[i]  = g_E8 + (size_t)(rowBase + row) * DIM + c * 16;
            dsto[i] = row * STRIDE_B + c * 16;
        } else {
            int j = idx - 1024;
            int row = j >> 3, c = j & 7;
            src[i]  = g_M8 + (size_t)(colBase + row) * DIM + c * 16;
            dsto[i] = A_BYTES + row * STRIDE_B + c * 16;
        }
    }

    const int arow = (lane & 7) + ((lane >> 3) & 1) * 8;
    const uint32_t akb = (lane >> 4) * 16;
    uint32_t aAddr[2];
#pragma unroll
    for (int m = 0; m < 2; m++)
        aAddr[m] = sbase + (wr * 32 + m * 16 + arow) * STRIDE_B + akb;
    const int brow = (lane & 7) + (lane >> 4) * 8;
    const uint32_t bkb = ((lane >> 3) & 1) * 16;
    uint32_t bAddr[4];
#pragma unroll
    for (int g = 0; g < 4; g++)
        bAddr[g] = sbase + A_BYTES + (wc * 64 + g * 16 + brow) * STRIDE_B + bkb;

    int acc[2][8][4];
#pragma unroll
    for (int m = 0; m < 2; m++)
#pragma unroll
        for (int t = 0; t < 8; t++)
#pragma unroll
            for (int c = 0; c < 4; c++) acc[m][t][c] = 0;

#pragma unroll
    for (int s = 0; s < NSTAGE - 1; s++) {
#pragma unroll
        for (int i = 0; i < 8; i++) cpasync16(sbase + s * STAGE_BYTES + dsto[i], src[i] + s * BK);
        asm volatile("cp.async.commit_group;");
    }

#pragma unroll
    for (int kt = 0; kt < KTILES; kt++) {
        const int st = kt % NSTAGE;
        asm volatile("cp.async.wait_group %0;" :: "n"(NSTAGE - 2));
        __syncthreads();
        if (kt + NSTAGE - 1 < KTILES) {
            const int ps = (kt + NSTAGE - 1) % NSTAGE;
            const int ko = (kt + NSTAGE - 1) * BK;
#pragma unroll
            for (int i = 0; i < 8; i++) cpasync16(sbase + ps * STAGE_BYTES + dsto[i], src[i] + ko);
            asm volatile("cp.async.commit_group;");
        }
        const uint32_t so = st * STAGE_BYTES;
#pragma unroll
        for (int s = 0; s < 4; s++) {
            uint32_t af[2][4], bf[4][4];
#pragma unroll
            for (int m = 0; m < 2; m++) ldsm4(af[m], aAddr[m] + so + s * 32);
#pragma unroll
            for (int g = 0; g < 4; g++) ldsm4(bf[g], bAddr[g] + so + s * 32);
#pragma unroll
            for (int m = 0; m < 2; m++)
#pragma unroll
                for (int t = 0; t < 8; t++)
                    mma_s8(acc[m][t], af[m], bf[t >> 1][(t & 1) * 2], bf[t >> 1][(t & 1) * 2 + 1]);
        }
    }
    __syncthreads();

    const int gid = lane >> 2, qid = lane & 3;
    unsigned long long* red = (unsigned long long*)dsm;
#pragma unroll
    for (int m = 0; m < 2; m++)
#pragma unroll
        for (int h = 0; h < 2; h++) {
            int bv = 0x7fffffff;
            int bj = 0x7fffffff;
#pragma unroll
            for (int t = 0; t < 8; t++)
#pragma unroll
                for (int c = 0; c < 2; c++) {
                    int col = colBase + wc * 64 + t * 8 + qid * 2 + c;
                    int q = g_ynq[col] - 2 * acc[m][t][h * 2 + c];
                    if (q < bv || (q == bv && col < bj)) { bv = q; bj = col; }
                }
#pragma unroll
            for (int off = 1; off < 4; off <<= 1) {
                int ov = __shfl_xor_sync(0xffffffffu, bv, off, 4);
                int oj = __shfl_xor_sync(0xffffffffu, bj, off, 4);
                if (ov < bv || (ov == bv && oj < bj)) { bv = ov; bj = oj; }
            }
            if (qid == 0) {
                int rloc = wr * 32 + m * 16 + h * 8 + gid;
                unsigned ku = (unsigned)bv ^ 0x80000000u;
                red[wc * 128 + rloc] = ((unsigned long long)ku << 32) | (unsigned)bj;
            }
        }
    __syncthreads();
    if (tid < BM) {
        unsigned long long p = red[tid];
        unsigned long long q1 = red[128 + tid]; if (q1 < p) p = q1;
        atomicMin(&g_minpack[rowBase + tid], p);
    }
}

// ---------------- exact fp32 rescore + fused per-image argmax ----------------
__global__ void rescore_kernel(const float* __restrict__ E, const float* __restrict__ Mb) {
    int warp = threadIdx.x >> 5, lane = threadIdx.x & 31;
    int row = blockIdx.x * 8 + warp;
    int col = (int)(g_minpack[row] & 0xffffffffull);
    const float4* x = (const float4*)(E + (size_t)row * DIM);
    const float4* y = (const float4*)(Mb + (size_t)col * DIM);
    float s = 0.f;
    for (int i = lane; i < DIM / 4; i += 32) {
        float4 a = x[i], b = y[i];
        s += a.x * b.x + a.y * b.y + a.z * b.z + a.w * b.w;
    }
#pragma unroll
    for (int o = 16; o; o >>= 1) s += __shfl_down_sync(0xffffffffu, s, o);
    if (lane == 0) {
        float d2 = g_xnorm[row] + g_ynorm[col] - 2.f * s;
        float sc = sqrtf(fmaxf(d2, 0.f));
        int b = row / PPI, p = row % PPI;
        unsigned long long pk = ((unsigned long long)fkey(sc) << 32) | (unsigned)(PPI - 1 - p);
        atomicMax(&g_maxpack[b], pk);
    }
}

// ---------------- exact fp32 NN search for the 16 argmax rows ----------------
// block = 512 threads = 64 col-slots x 8 D-groups (192 dims each); slot owns cols (c0, c0+64)
__global__ void __launch_bounds__(512) exactnn_kernel(const float* __restrict__ E,
                                                      const float* __restrict__ Mb) {
    extern __shared__ float Qs[];          // 16 x 1536 floats = 96 KB
    __shared__ int qr[16];
    __shared__ unsigned long long part[16];
    const int tid = threadIdx.x;
    const int s = tid & 63, g = tid >> 6;  // slot 0..63, group 0..7
    if (tid < 16) {
        int p = PPI - 1 - (int)(g_maxpack[tid] & 0xffffffffull);
        qr[tid] = tid * PPI + p;
        part[tid] = 0xFFFFFFFFFFFFFFFFull;
    }
    __syncthreads();
    for (int i = tid; i < 16 * 384; i += 512) {
        int q = i / 384, d4 = i % 384;
        ((float4*)Qs)[i] = ((const float4*)(E + (size_t)qr[q] * DIM))[d4];
    }
    __syncthreads();

    const int col0 = blockIdx.x * 128 + s;
    const int col1 = col0 + 64;
    float acc0[16], acc1[16];
#pragma unroll
    for (int q = 0; q < 16; q++) { acc0[q] = 0.f; acc1[q] = 0.f; }
    const float4* r0 = (const float4*)(Mb + (size_t)col0 * DIM) + g * 48;
    const float4* r1 = (const float4*)(Mb + (size_t)col1 * DIM) + g * 48;
    const float4* Qb = ((const float4*)Qs) + g * 48;
#pragma unroll 2
    for (int d4 = 0; d4 < 48; d4++) {
        float4 v0 = r0[d4], v1 = r1[d4];
#pragma unroll
        for (int q = 0; q < 16; q++) {
            float4 u = Qb[q * 384 + d4];
            acc0[q] = fmaf(v0.x, u.x, fmaf(v0.y, u.y, fmaf(v0.z, u.z, fmaf(v0.w, u.w, acc0[q]))));
            acc1[q] = fmaf(v1.x, u.x, fmaf(v1.y, u.y, fmaf(v1.z, u.z, fmaf(v1.w, u.w, acc1[q]))));
        }
    }
    __syncthreads();                       // Qs reads done; reuse as reduction buffer
    float* red = Qs;                       // red[qc*512 + g*64 + s], qc = 0..31 -> 64 KB
#pragma unroll
    for (int q = 0; q < 16; q++) {
        red[q * 512 + g * 64 + s]        = acc0[q];
        red[(16 + q) * 512 + g * 64 + s] = acc1[q];
    }
    __syncthreads();
    if (g == 0) {
        float yn0 = g_ynorm[col0], yn1 = g_ynorm[col1];
#pragma unroll
        for (int q = 0; q < 16; q++) {
            float d0 = 0.f, d1 = 0.f;
#pragma unroll
            for (int gg = 0; gg < 8; gg++) {
                d0 += red[q * 512 + gg * 64 + s];
                d1 += red[(16 + q) * 512 + gg * 64 + s];
            }
            float xn = g_xnorm[qr[q]];
            float e0 = xn + yn0 - 2.f * d0;
            float e1 = xn + yn1 - 2.f * d1;
            atomicMin(&part[q], ((unsigned long long)fkey(e0) << 32) | (unsigned)col0);
            atomicMin(&part[q], ((unsigned long long)fkey(e1) << 32) | (unsigned)col1);
        }
    }
    __syncthreads();
    if (tid < 16) atomicMin(&g_nnpack[tid], part[tid]);
}

// ---------------- Phase C1: d^2 from 16 nn_samples to all memory rows ----------------
__global__ void __launch_bounds__(512) knn_dist_kernel(const float* __restrict__ Mb) {
    extern __shared__ float Qs[];          // 16 x 1536 floats = 96 KB
    __shared__ int nn[16];
    __shared__ float qn[16];
    const int tid = threadIdx.x;
    const int s = tid & 63, g = tid >> 6;
    if (tid < 16) {
        int idx = (int)(g_nnpack[tid] & 0xffffffffull);
        nn[tid] = idx; qn[tid] = g_ynorm[idx];
    }
    __syncthreads();
    for (int i = tid; i < 16 * 384; i += 512) {
        int q = i / 384, d4 = i % 384;
        ((float4*)Qs)[i] = ((const float4*)(Mb + (size_t)nn[q] * DIM))[d4];
    }
    __syncthreads();

    const int col0 = blockIdx.x * 128 + s;
    const int col1 = col0 + 64;
    float acc0[16], acc1[16];
#pragma unroll
    for (int q = 0; q < 16; q++) { acc0[q] = 0.f; acc1[q] = 0.f; }
    const float4* r0 = (const float4*)(Mb + (size_t)col0 * DIM) + g * 48;
    const float4* r1 = (const float4*)(Mb + (size_t)col1 * DIM) + g * 48;
    const float4* Qb = ((const float4*)Qs) + g * 48;
#pragma unroll 2
    for (int d4 = 0; d4 < 48; d4++) {
        float4 v0 = r0[d4], v1 = r1[d4];
#pragma unroll
        for (int q = 0; q < 16; q++) {
            float4 u = Qb[q * 384 + d4];
            acc0[q] = fmaf(v0.x, u.x, fmaf(v0.y, u.y, fmaf(v0.z, u.z, fmaf(v0.w, u.w, acc0[q]))));
            acc1[q] = fmaf(v1.x, u.x, fmaf(v1.y, u.y, fmaf(v1.z, u.z, fmaf(v1.w, u.w, acc1[q]))));
        }
    }
    __syncthreads();
    float* red = Qs;                       // red[qc*512 + g*64 + s], 64 KB
#pragma unroll
    for (int q = 0; q < 16; q++) {
        red[q * 512 + g * 64 + s]        = acc0[q];
        red[(16 + q) * 512 + g * 64 + s] = acc1[q];
    }
    __syncthreads();
    if (g == 0) {
        float yn0 = g_ynorm[col0], yn1 = g_ynorm[col1];
#pragma unroll
        for (int q = 0; q < 16; q++) {
            float d0 = 0.f, d1 = 0.f;
#pragma unroll
            for (int gg = 0; gg < 8; gg++) {
                d0 += red[q * 512 + gg * 64 + s];
                d1 += red[(16 + q) * 512 + gg * 64 + s];
            }
            g_d2[q * M_BANK + col0] = qn[q] + yn0 - 2.f * d0;
            g_d2[q * M_BANK + col1] = qn[q] + yn1 - 2.f * d1;
        }
    }
}

// ---------------- Phase C2 + D: stable top-9, distances, softmax, output ----------------
__global__ void top9_final_kernel(const float* __restrict__ E, const float* __restrict__ Mb,
                                  float* __restrict__ out) {
    int b = blockIdx.x;
    int tid = threadIdx.x;
    float v[9]; int id[9];
#pragma unroll
    for (int k = 0; k < 9; k++) { v[k] = __int_as_float(0x7f800000); id[k] = 0x7fffffff; }
    for (int j = tid; j < M_BANK; j += 128) {
        float d = g_d2[b * M_BANK + j];
        if (d < v[8] || (d == v[8] && j < id[8])) {
            int k = 8;
            while (k > 0 && (d < v[k - 1] || (d == v[k - 1] && j < id[k - 1]))) {
                v[k] = v[k - 1]; id[k] = id[k - 1]; k--;
            }
            v[k] = d; id[k] = j;
        }
    }
    __shared__ float svv[128 * 9];
    __shared__ int   sid[128 * 9];
    __shared__ int   s_sup[9];
    __shared__ float s_ds[9];
    __shared__ float s_red[4];
#pragma unroll
    for (int k = 0; k < 9; k++) { svv[tid * 9 + k] = v[k]; sid[tid * 9 + k] = id[k]; }
    __syncthreads();
    if (tid == 0) {
        float fv[9]; int fid[9];
#pragma unroll
        for (int k = 0; k < 9; k++) { fv[k] = __int_as_float(0x7f800000); fid[k] = 0x7fffffff; }
        for (int t = 0; t < 128; t++) {
            for (int k = 0; k < 9; k++) {
                float d = svv[t * 9 + k]; int j = sid[t * 9 + k];
                if (d > fv[8] || (d == fv[8] && j >= fid[8])) break;
                int m = 8;
                while (m > 0 && (d < fv[m - 1] || (d == fv[m - 1] && j < fid[m - 1]))) {
                    fv[m] = fv[m - 1]; fid[m] = fid[m - 1]; m--;
                }
                fv[m] = d; fid[m] = j;
            }
        }
        for (int k = 0; k < 9; k++) s_sup[k] = fid[k];
    }
    __syncthreads();

    unsigned long long mp = g_maxpack[b];
    int maxrow = b * PPI + (PPI - 1 - (int)(mp & 0xffffffffull));
    const float4* x = (const float4*)(E + (size_t)maxrow * DIM);
    for (int k = 0; k < 9; k++) {
        const float4* y = (const float4*)(Mb + (size_t)s_sup[k] * DIM);
        float s = 0.f;
        for (int i = tid; i < 384; i += 128) {
            float4 xv = x[i], yv = y[i];
            float dx = xv.x - yv.x, dy = xv.y - yv.y, dz = xv.z - yv.z, dw = xv.w - yv.w;
            s += dx * dx + dy * dy + dz * dz + dw * dw;
        }
#pragma unroll
        for (int o = 16; o; o >>= 1) s += __shfl_down_sync(0xffffffffu, s, o);
        if ((tid & 31) == 0) s_red[tid >> 5] = s;
        __syncthreads();
        if (tid == 0) s_ds[k] = sqrtf(fmaxf(s_red[0] + s_red[1] + s_red[2] + s_red[3], 0.f));
        __syncthreads();
    }
    if (tid == 0) {
        float m = s_ds[0];
        for (int k = 1; k < 9; k++) m = fmaxf(m, s_ds[k]);
        float sum = 0.f, e0 = 0.f;
        for (int k = 0; k < 9; k++) {
            float e = expf(s_ds[k] - m);
            if (k == 0) e0 = e;
            sum += e;
        }
        out[b] = (1.f - e0 / sum) * unkey((unsigned)(mp >> 32));
    }
}

// ---------------- launch ----------------
extern "C" void kernel_launch(void* const* d_in, const int* in_sizes, int n_in,
                              void* d_out, int out_size) {
    const float* E  = (const float*)d_in[0];
    const float* Mb = (const float*)d_in[1];
    float* out = (float*)d_out;

    cudaFuncSetAttribute(distmin_s8, cudaFuncAttributeMaxDynamicSharedMemorySize, SMEM_BYTES);
    cudaFuncSetAttribute(exactnn_kernel, cudaFuncAttributeMaxDynamicSharedMemorySize, QS_BYTES);
    cudaFuncSetAttribute(knn_dist_kernel, cudaFuncAttributeMaxDynamicSharedMemorySize, QS_BYTES);

    convert_norms_kernel<<<N_EMB + M_BANK, 128>>>(E, Mb);
    distmin_s8<<<GRIDX * GRIDY, 256, SMEM_BYTES>>>();
    rescore_kernel<<<N_EMB / 8, 256>>>(E, Mb);
    exactnn_kernel<<<M_BANK / 128, 512, QS_BYTES>>>(E, Mb);
    knn_dist_kernel<<<M_BANK / 128, 512, QS_BYTES>>>(Mb);
    top9_final_kernel<<<BATCH, 128>>>(E, Mb, out);
}

// round 14
// speedup vs baseline: 17.3961x; 1.0093x over previous
#include <cuda_runtime.h>
#include <cuda_bf16.h>
#include <math.h>
#include <stdint.h>

#define N_EMB 12544
#define M_BANK 16384
#define DIM 1536
#define BATCH 16
#define PPI 784
#define KNN 9

// ---- Phase A tiling (int8 mma.m16n8k32), 2 CTAs/SM, BK=128 ----
#define BM 128
#define BN 128
#define BK 128
#define KTILES (DIM / BK)          // 12
#define NSTAGE 3
#define STRIDE_B 144               // 128 data + 16 pad -> conflict-free ldmatrix
#define A_BYTES (BM * STRIDE_B)
#define B_BYTES (BN * STRIDE_B)
#define STAGE_BYTES (A_BYTES + B_BYTES)   // 36864
#define SMEM_BYTES (NSTAGE * STAGE_BYTES) // 110592
#define GRIDX (N_EMB / BM)         // 98
#define GRIDY (M_BANK / BN)        // 128
#define SWG 8

#define QSCALE 23.0f

// ---- scan kernels: staged layout ----
#define QS_FLOATS (16 * DIM)             // 24576 floats = 96 KB
#define CH_FLOATS 4096                   // 128 cols x 32 dims = 16 KB
#define NCHUNK (DIM / 32)                // 48
#define QS2_BYTES ((QS_FLOATS + 2 * CH_FLOATS) * 4)   // 131072

// ---------------- scratch ----------------
__device__ char  g_E8[N_EMB * DIM];
__device__ char  g_M8[M_BANK * DIM];
__device__ int   g_ynq[M_BANK];
__device__ unsigned long long g_minpack[N_EMB];
__device__ unsigned long long g_nnpack[BATCH];
__device__ unsigned long long g_maxpack[BATCH];   // (fkey(score) << 32) | (PPI-1-p)
__device__ float g_xnorm[N_EMB];
__device__ float g_ynorm[M_BANK];
__device__ float g_d2[BATCH * M_BANK];

__device__ __forceinline__ unsigned fkey(float f) {
    unsigned u = __float_as_uint(f);
    return (u & 0x80000000u) ? ~u : (u | 0x80000000u);
}
__device__ __forceinline__ float unkey(unsigned k) {
    unsigned u = (k & 0x80000000u) ? (k ^ 0x80000000u) : ~k;
    return __uint_as_float(u);
}

__device__ __forceinline__ void cpasync16(uint32_t dst, const void* src) {
    asm volatile("cp.async.cg.shared.global [%0], [%1], 16;" :: "r"(dst), "l"(src));
}
__device__ __forceinline__ void ldsm4(uint32_t* r, uint32_t addr) {
    asm volatile("ldmatrix.sync.aligned.m8n8.x4.shared.b16 {%0,%1,%2,%3}, [%4];"
                 : "=r"(r[0]), "=r"(r[1]), "=r"(r[2]), "=r"(r[3]) : "r"(addr));
}
__device__ __forceinline__ void mma_s8(int* c, const uint32_t* a, uint32_t b0, uint32_t b1) {
    asm volatile("mma.sync.aligned.m16n8k32.row.col.s32.s8.s8.s32 "
                 "{%0,%1,%2,%3}, {%4,%5,%6,%7}, {%8,%9}, {%0,%1,%2,%3};"
                 : "+r"(c[0]), "+r"(c[1]), "+r"(c[2]), "+r"(c[3])
                 : "r"(a[0]), "r"(a[1]), "r"(a[2]), "r"(a[3]), "r"(b0), "r"(b1));
}

__device__ __forceinline__ int q8(float x) {
    int v = __float2int_rn(x * QSCALE);
    return max(-127, min(127, v));
}

// ---------------- fused convert-to-int8 + norms + scratch init ----------------
__global__ void convert_norms_kernel(const float* __restrict__ E, const float* __restrict__ Mb) {
    int row = blockIdx.x;
    const bool isE = row < N_EMB;
    const float* p = isE ? (E + (size_t)row * DIM) : (Mb + (size_t)(row - N_EMB) * DIM);
    char* q = isE ? (g_E8 + (size_t)row * DIM) : (g_M8 + (size_t)(row - N_EMB) * DIM);
    float s = 0.f;
    int   sq = 0;
    for (int i = threadIdx.x; i < DIM / 4; i += blockDim.x) {
        float4 v = ((const float4*)p)[i];
        s += v.x * v.x + v.y * v.y + v.z * v.z + v.w * v.w;
        int a = q8(v.x), b = q8(v.y), c = q8(v.z), d = q8(v.w);
        sq += a * a + b * b + c * c + d * d;
        uint32_t pk = (uint32_t)(a & 0xff) | ((uint32_t)(b & 0xff) << 8) |
                      ((uint32_t)(c & 0xff) << 16) | ((uint32_t)(d & 0xff) << 24);
        ((uint32_t*)q)[i] = pk;
    }
#pragma unroll
    for (int o = 16; o; o >>= 1) {
        s  += __shfl_down_sync(0xffffffffu, s, o);
        sq += __shfl_down_sync(0xffffffffu, sq, o);
    }
    __shared__ float ws[4];
    __shared__ int   wq[4];
    if ((threadIdx.x & 31) == 0) { ws[threadIdx.x >> 5] = s; wq[threadIdx.x >> 5] = sq; }
    __syncthreads();
    if (threadIdx.x == 0) {
        float t = ws[0] + ws[1] + ws[2] + ws[3];
        int   ti = wq[0] + wq[1] + wq[2] + wq[3];
        if (isE) {
            g_xnorm[row] = t;
            g_minpack[row] = 0xFFFFFFFFFFFFFFFFull;
            if (row < BATCH) { g_nnpack[row] = 0xFFFFFFFFFFFFFFFFull; g_maxpack[row] = 0ull; }
        } else {
            g_ynorm[row - N_EMB] = t; g_ynq[row - N_EMB] = ti;
        }
    }
}

// ---------------- Phase A: int8 tensor-core dist-argmin GEMM ----------------
__global__ void __launch_bounds__(256, 2) distmin_s8() {
    extern __shared__ char dsm[];
    const int tid = threadIdx.x;
    const int lane = tid & 31, warp = tid >> 5;
    const int wr = warp & 3, wc = warp >> 2;

    const int band = blockIdx.x / (GRIDX * SWG);
    const int rem  = blockIdx.x % (GRIDX * SWG);
    const int by   = band * SWG + (rem % SWG);
    const int bx   = rem / SWG;
    const int rowBase = bx * BM;
    const int colBase = by * BN;

    uint32_t sbase = (uint32_t)__cvta_generic_to_shared(dsm);

    const char* src[8];
    uint32_t dsto[8];
#pragma unroll
    for (int i = 0; i < 8; i++) {
        int idx = tid + i * 256;
        if (idx < 1024) {
            int row = idx >> 3, c = idx & 7;
            src[i]  = g_E8 + (size_t)(rowBase + row) * DIM + c * 16;
            dsto[i] = row * STRIDE_B + c * 16;
        } else {
            int j = idx - 1024;
            int row = j >> 3, c = j & 7;
            src[i]  = g_M8 + (size_t)(colBase + row) * DIM + c * 16;
            dsto[i] = A_BYTES + row * STRIDE_B + c * 16;
        }
    }

    const int arow = (lane & 7) + ((lane >> 3) & 1) * 8;
    const uint32_t akb = (lane >> 4) * 16;
    uint32_t aAddr[2];
#pragma unroll
    for (int m = 0; m < 2; m++)
        aAddr[m] = sbase + (wr * 32 + m * 16 + arow) * STRIDE_B + akb;
    const int brow = (lane & 7) + (lane >> 4) * 8;
    const uint32_t bkb = ((lane >> 3) & 1) * 16;
    uint32_t bAddr[4];
#pragma unroll
    for (int g = 0; g < 4; g++)
        bAddr[g] = sbase + A_BYTES + (wc * 64 + g * 16 + brow) * STRIDE_B + bkb;

    int acc[2][8][4];
#pragma unroll
    for (int m = 0; m < 2; m++)
#pragma unroll
        for (int t = 0; t < 8; t++)
#pragma unroll
            for (int c = 0; c < 4; c++) acc[m][t][c] = 0;

#pragma unroll
    for (int s = 0; s < NSTAGE - 1; s++) {
#pragma unroll
        for (int i = 0; i < 8; i++) cpasync16(sbase + s * STAGE_BYTES + dsto[i], src[i] + s * BK);
        asm volatile("cp.async.commit_group;");
    }

#pragma unroll
    for (int kt = 0; kt < KTILES; kt++) {
        const int st = kt % NSTAGE;
        asm volatile("cp.async.wait_group %0;" :: "n"(NSTAGE - 2));
        __syncthreads();
        if (kt + NSTAGE - 1 < KTILES) {
            const int ps = (kt + NSTAGE - 1) % NSTAGE;
            const int ko = (kt + NSTAGE - 1) * BK;
#pragma unroll
            for (int i = 0; i < 8; i++) cpasync16(sbase + ps * STAGE_BYTES + dsto[i], src[i] + ko);
            asm volatile("cp.async.commit_group;");
        }
        const uint32_t so = st * STAGE_BYTES;
#pragma unroll
        for (int s = 0; s < 4; s++) {
            uint32_t af[2][4], bf[4][4];
#pragma unroll
            for (int m = 0; m < 2; m++) ldsm4(af[m], aAddr[m] + so + s * 32);
#pragma unroll
            for (int g = 0; g < 4; g++) ldsm4(bf[g], bAddr[g] + so + s * 32);
#pragma unroll
            for (int m = 0; m < 2; m++)
#pragma unroll
                for (int t = 0; t < 8; t++)
                    mma_s8(acc[m][t], af[m], bf[t >> 1][(t & 1) * 2], bf[t >> 1][(t & 1) * 2 + 1]);
        }
    }
    __syncthreads();

    const int gid = lane >> 2, qid = lane & 3;
    unsigned long long* red = (unsigned long long*)dsm;
#pragma unroll
    for (int m = 0; m < 2; m++)
#pragma unroll
        for (int h = 0; h < 2; h++) {
            int bv = 0x7fffffff;
            int bj = 0x7fffffff;
#pragma unroll
            for (int t = 0; t < 8; t++)
#pragma unroll
                for (int c = 0; c < 2; c++) {
                    int col = colBase + wc * 64 + t * 8 + qid * 2 + c;
                    int q = g_ynq[col] - 2 * acc[m][t][h * 2 + c];
                    if (q < bv || (q == bv && col < bj)) { bv = q; bj = col; }
                }
#pragma unroll
            for (int off = 1; off < 4; off <<= 1) {
                int ov = __shfl_xor_sync(0xffffffffu, bv, off, 4);
                int oj = __shfl_xor_sync(0xffffffffu, bj, off, 4);
                if (ov < bv || (ov == bv && oj < bj)) { bv = ov; bj = oj; }
            }
            if (qid == 0) {
                int rloc = wr * 32 + m * 16 + h * 8 + gid;
                unsigned ku = (unsigned)bv ^ 0x80000000u;
                red[wc * 128 + rloc] = ((unsigned long long)ku << 32) | (unsigned)bj;
            }
        }
    __syncthreads();
    if (tid < BM) {
        unsigned long long p = red[tid];
        unsigned long long q1 = red[128 + tid]; if (q1 < p) p = q1;
        atomicMin(&g_minpack[rowBase + tid], p);
    }
}

// ---------------- exact fp32 rescore + fused per-image argmax ----------------
__global__ void rescore_kernel(const float* __restrict__ E, const float* __restrict__ Mb) {
    int warp = threadIdx.x >> 5, lane = threadIdx.x & 31;
    int row = blockIdx.x * 8 + warp;
    int col = (int)(g_minpack[row] & 0xffffffffull);
    const float4* x = (const float4*)(E + (size_t)row * DIM);
    const float4* y = (const float4*)(Mb + (size_t)col * DIM);
    float s = 0.f;
    for (int i = lane; i < DIM / 4; i += 32) {
        float4 a = x[i], b = y[i];
        s += a.x * b.x + a.y * b.y + a.z * b.z + a.w * b.w;
    }
#pragma unroll
    for (int o = 16; o; o >>= 1) s += __shfl_down_sync(0xffffffffu, s, o);
    if (lane == 0) {
        float d2 = g_xnorm[row] + g_ynorm[col] - 2.f * s;
        float sc = sqrtf(fmaxf(d2, 0.f));
        int b = row / PPI, p = row % PPI;
        unsigned long long pk = ((unsigned long long)fkey(sc) << 32) | (unsigned)(PPI - 1 - p);
        atomicMax(&g_maxpack[b], pk);
    }
}

// ---------------- exact fp32 NN search for the 16 argmax rows (cp.async staged) ----
// block = 512 = 64 col-slots x 8 D-groups; Mb streamed via double-buffered 16KB chunks
__global__ void __launch_bounds__(512) exactnn_kernel(const float* __restrict__ E,
                                                      const float* __restrict__ Mb) {
    extern __shared__ float Qs[];          // [QS_FLOATS] queries + 2 x CH_FLOATS chunk bufs
    float* CS = Qs + QS_FLOATS;
    __shared__ int qr[16];
    __shared__ unsigned long long part[16];
    const int tid = threadIdx.x;
    const int s = tid & 63, g = tid >> 6;
    const int colBase0 = blockIdx.x * 128;
    const uint32_t csBase = (uint32_t)__cvta_generic_to_shared(CS);
    const int c0 = tid >> 3, j0 = tid & 7;             // cp.async mapping (2 pieces/thread)
    const int c1 = (tid + 512) >> 3, j1 = tid & 7;

    if (tid < 16) {
        int p = PPI - 1 - (int)(g_maxpack[tid] & 0xffffffffull);
        qr[tid] = tid * PPI + p;
        part[tid] = 0xFFFFFFFFFFFFFFFFull;
    }
    // prologue: stage chunk 0 (independent of qr)
    {
        cpasync16(csBase + c0 * 128 + (((j0 + c0) & 7) << 4),
                  Mb + (size_t)(colBase0 + c0) * DIM + j0 * 4);
        cpasync16(csBase + c1 * 128 + (((j1 + c1) & 7) << 4),
                  Mb + (size_t)(colBase0 + c1) * DIM + j1 * 4);
        asm volatile("cp.async.commit_group;");
    }
    __syncthreads();
    for (int i = tid; i < QS_FLOATS / 4; i += 512) {
        int q = i / 384, d4 = i % 384;
        ((float4*)Qs)[i] = ((const float4*)(E + (size_t)qr[q] * DIM))[d4];
    }

    float acc0[16], acc1[16];
#pragma unroll
    for (int q = 0; q < 16; q++) { acc0[q] = 0.f; acc1[q] = 0.f; }
    const uint32_t sw = ((g + s) & 7) << 4;            // swizzled float4 slot (bytes)
    const float* p0 = CS + s * 32;                     // col s row base (floats)
    const float* p1 = CS + (s + 64) * 32;

    for (int ch = 0; ch < NCHUNK; ch++) {
        const int buf = ch & 1;
        if (ch + 1 < NCHUNK) {
            const int nb = buf ^ 1;
            cpasync16(csBase + nb * 16384 + c0 * 128 + (((j0 + c0) & 7) << 4),
                      Mb + (size_t)(colBase0 + c0) * DIM + (ch + 1) * 32 + j0 * 4);
            cpasync16(csBase + nb * 16384 + c1 * 128 + (((j1 + c1) & 7) << 4),
                      Mb + (size_t)(colBase0 + c1) * DIM + (ch + 1) * 32 + j1 * 4);
            asm volatile("cp.async.commit_group;");
            asm volatile("cp.async.wait_group 1;");
        } else {
            asm volatile("cp.async.wait_group 0;");
        }
        __syncthreads();
        float4 v0 = *(const float4*)((const char*)(p0 + buf * CH_FLOATS) + sw);
        float4 v1 = *(const float4*)((const char*)(p1 + buf * CH_FLOATS) + sw);
        const float4* Qb = ((const float4*)Qs) + ch * 8 + g;
#pragma unroll
        for (int q = 0; q < 16; q++) {
            float4 u = Qb[q * 384];
            acc0[q] = fmaf(v0.x, u.x, fmaf(v0.y, u.y, fmaf(v0.z, u.z, fmaf(v0.w, u.w, acc0[q]))));
            acc1[q] = fmaf(v1.x, u.x, fmaf(v1.y, u.y, fmaf(v1.z, u.z, fmaf(v1.w, u.w, acc1[q]))));
        }
        __syncthreads();
    }

    // reduce across 8 D-groups via smem (reuse Qs)
    float* red = Qs;                       // red[qc*512 + g*64 + s], 64 KB
#pragma unroll
    for (int q = 0; q < 16; q++) {
        red[q * 512 + g * 64 + s]        = acc0[q];
        red[(16 + q) * 512 + g * 64 + s] = acc1[q];
    }
    __syncthreads();
    if (g == 0) {
        const int col0 = colBase0 + s, col1 = col0 + 64;
        float yn0 = g_ynorm[col0], yn1 = g_ynorm[col1];
#pragma unroll
        for (int q = 0; q < 16; q++) {
            float d0 = 0.f, d1 = 0.f;
#pragma unroll
            for (int gg = 0; gg < 8; gg++) {
                d0 += red[q * 512 + gg * 64 + s];
                d1 += red[(16 + q) * 512 + gg * 64 + s];
            }
            float xn = g_xnorm[qr[q]];
            float e0 = xn + yn0 - 2.f * d0;
            float e1 = xn + yn1 - 2.f * d1;
            atomicMin(&part[q], ((unsigned long long)fkey(e0) << 32) | (unsigned)col0);
            atomicMin(&part[q], ((unsigned long long)fkey(e1) << 32) | (unsigned)col1);
        }
    }
    __syncthreads();
    if (tid < 16) atomicMin(&g_nnpack[tid], part[tid]);
}

// ---------------- Phase C1: d^2 from 16 nn_samples to all memory rows (staged) -----
__global__ void __launch_bounds__(512) knn_dist_kernel(const float* __restrict__ Mb) {
    extern __shared__ float Qs[];
    float* CS = Qs + QS_FLOATS;
    __shared__ int nn[16];
    __shared__ float qn[16];
    const int tid = threadIdx.x;
    const int s = tid & 63, g = tid >> 6;
    const int colBase0 = blockIdx.x * 128;
    const uint32_t csBase = (uint32_t)__cvta_generic_to_shared(CS);
    const int c0 = tid >> 3, j0 = tid & 7;
    const int c1 = (tid + 512) >> 3, j1 = tid & 7;

    if (tid < 16) {
        int idx = (int)(g_nnpack[tid] & 0xffffffffull);
        nn[tid] = idx; qn[tid] = g_ynorm[idx];
    }
    {
        cpasync16(csBase + c0 * 128 + (((j0 + c0) & 7) << 4),
                  Mb + (size_t)(colBase0 + c0) * DIM + j0 * 4);
        cpasync16(csBase + c1 * 128 + (((j1 + c1) & 7) << 4),
                  Mb + (size_t)(colBase0 + c1) * DIM + j1 * 4);
        asm volatile("cp.async.commit_group;");
    }
    __syncthreads();
    for (int i = tid; i < QS_FLOATS / 4; i += 512) {
        int q = i / 384, d4 = i % 384;
        ((float4*)Qs)[i] = ((const float4*)(Mb + (size_t)nn[q] * DIM))[d4];
    }

    float acc0[16], acc1[16];
#pragma unroll
    for (int q = 0; q < 16; q++) { acc0[q] = 0.f; acc1[q] = 0.f; }
    const uint32_t sw = ((g + s) & 7) << 4;
    const float* p0 = CS + s * 32;
    const float* p1 = CS + (s + 64) * 32;

    for (int ch = 0; ch < NCHUNK; ch++) {
        const int buf = ch & 1;
        if (ch + 1 < NCHUNK) {
            const int nb = buf ^ 1;
            cpasync16(csBase + nb * 16384 + c0 * 128 + (((j0 + c0) & 7) << 4),
                      Mb + (size_t)(colBase0 + c0) * DIM + (ch + 1) * 32 + j0 * 4);
            cpasync16(csBase + nb * 16384 + c1 * 128 + (((j1 + c1) & 7) << 4),
                      Mb + (size_t)(colBase0 + c1) * DIM + (ch + 1) * 32 + j1 * 4);
            asm volatile("cp.async.commit_group;");
            asm volatile("cp.async.wait_group 1;");
        } else {
            asm volatile("cp.async.wait_group 0;");
        }
        __syncthreads();
        float4 v0 = *(const float4*)((const char*)(p0 + buf * CH_FLOATS) + sw);
        float4 v1 = *(const float4*)((const char*)(p1 + buf * CH_FLOATS) + sw);
        const float4* Qb = ((const float4*)Qs) + ch * 8 + g;
#pragma unroll
        for (int q = 0; q < 16; q++) {
            float4 u = Qb[q * 384];
            acc0[q] = fmaf(v0.x, u.x, fmaf(v0.y, u.y, fmaf(v0.z, u.z, fmaf(v0.w, u.w, acc0[q]))));
            acc1[q] = fmaf(v1.x, u.x, fmaf(v1.y, u.y, fmaf(v1.z, u.z, fmaf(v1.w, u.w, acc1[q]))));
        }
        __syncthreads();
    }

    float* red = Qs;
#pragma unroll
    for (int q = 0; q < 16; q++) {
        red[q * 512 + g * 64 + s]        = acc0[q];
        red[(16 + q) * 512 + g * 64 + s] = acc1[q];
    }
    __syncthreads();
    if (g == 0) {
        const int col0 = colBase0 + s, col1 = col0 + 64;
        float yn0 = g_ynorm[col0], yn1 = g_ynorm[col1];
#pragma unroll
        for (int q = 0; q < 16; q++) {
            float d0 = 0.f, d1 = 0.f;
#pragma unroll
            for (int gg = 0; gg < 8; gg++) {
                d0 += red[q * 512 + gg * 64 + s];
                d1 += red[(16 + q) * 512 + gg * 64 + s];
            }
            g_d2[q * M_BANK + col0] = qn[q] + yn0 - 2.f * d0;
            g_d2[q * M_BANK + col1] = qn[q] + yn1 - 2.f * d1;
        }
    }
}

// ---------------- Phase C2 + D: stable top-9, distances, softmax, output ----------------
__global__ void top9_final_kernel(const float* __restrict__ E, const float* __restrict__ Mb,
                                  float* __restrict__ out) {
    int b = blockIdx.x;
    int tid = threadIdx.x;
    float v[9]; int id[9];
#pragma unroll
    for (int k = 0; k < 9; k++) { v[k] = __int_as_float(0x7f800000); id[k] = 0x7fffffff; }
    for (int j = tid; j < M_BANK; j += 128) {
        float d = g_d2[b * M_BANK + j];
        if (d < v[8] || (d == v[8] && j < id[8])) {
            int k = 8;
            while (k > 0 && (d < v[k - 1] || (d == v[k - 1] && j < id[k - 1]))) {
                v[k] = v[k - 1]; id[k] = id[k - 1]; k--;
            }
            v[k] = d; id[k] = j;
        }
    }
    __shared__ float svv[128 * 9];
    __shared__ int   sid[128 * 9];
    __shared__ int   s_sup[9];
    __shared__ float s_ds[9];
    __shared__ float s_red[4];
#pragma unroll
    for (int k = 0; k < 9; k++) { svv[tid * 9 + k] = v[k]; sid[tid * 9 + k] = id[k]; }
    __syncthreads();
    if (tid == 0) {
        float fv[9]; int fid[9];
#pragma unroll
        for (int k = 0; k < 9; k++) { fv[k] = __int_as_float(0x7f800000); fid[k] = 0x7fffffff; }
        for (int t = 0; t < 128; t++) {
            for (int k = 0; k < 9; k++) {
                float d = svv[t * 9 + k]; int j = sid[t * 9 + k];
                if (d > fv[8] || (d == fv[8] && j >= fid[8])) break;
                int m = 8;
                while (m > 0 && (d < fv[m - 1] || (d == fv[m - 1] && j < fid[m - 1]))) {
                    fv[m] = fv[m - 1]; fid[m] = fid[m - 1]; m--;
                }
                fv[m] = d; fid[m] = j;
            }
        }
        for (int k = 0; k < 9; k++) s_sup[k] = fid[k];
    }
    __syncthreads();

    unsigned long long mp = g_maxpack[b];
    int maxrow = b * PPI + (PPI - 1 - (int)(mp & 0xffffffffull));
    const float4* x = (const float4*)(E + (size_t)maxrow * DIM);
    for (int k = 0; k < 9; k++) {
        const float4* y = (const float4*)(Mb + (size_t)s_sup[k] * DIM);
        float s = 0.f;
        for (int i = tid; i < 384; i += 128) {
            float4 xv = x[i], yv = y[i];
            float dx = xv.x - yv.x, dy = xv.y - yv.y, dz = xv.z - yv.z, dw = xv.w - yv.w;
            s += dx * dx + dy * dy + dz * dz + dw * dw;
        }
#pragma unroll
        for (int o = 16; o; o >>= 1) s += __shfl_down_sync(0xffffffffu, s, o);
        if ((tid & 31) == 0) s_red[tid >> 5] = s;
        __syncthreads();
        if (tid == 0) s_ds[k] = sqrtf(fmaxf(s_red[0] + s_red[1] + s_red[2] + s_red[3], 0.f));
        __syncthreads();
    }
    if (tid == 0) {
        float m = s_ds[0];
        for (int k = 1; k < 9; k++) m = fmaxf(m, s_ds[k]);
        float sum = 0.f, e0 = 0.f;
        for (int k = 0; k < 9; k++) {
            float e = expf(s_ds[k] - m);
            if (k == 0) e0 = e;
            sum += e;
        }
        out[b] = (1.f - e0 / sum) * unkey((unsigned)(mp >> 32));
    }
}

// ---------------- launch ----------------
extern "C" void kernel_launch(void* const* d_in, const int* in_sizes, int n_in,
                              void* d_out, int out_size) {
    const float* E  = (const float*)d_in[0];
    const float* Mb = (const float*)d_in[1];
    float* out = (float*)d_out;

    cudaFuncSetAttribute(distmin_s8, cudaFuncAttributeMaxDynamicSharedMemorySize, SMEM_BYTES);
    cudaFuncSetAttribute(exactnn_kernel, cudaFuncAttributeMaxDynamicSharedMemorySize, QS2_BYTES);
    cudaFuncSetAttribute(knn_dist_kernel, cudaFuncAttributeMaxDynamicSharedMemorySize, QS2_BYTES);

    convert_norms_kernel<<<N_EMB + M_BANK, 128>>>(E, Mb);
    distmin_s8<<<GRIDX * GRIDY, 256, SMEM_BYTES>>>();
    rescore_kernel<<<N_EMB / 8, 256>>>(E, Mb);
    exactnn_kernel<<<M_BANK / 128, 512, QS2_BYTES>>>(E, Mb);
    knn_dist_kernel<<<M_BANK / 128, 512, QS2_BYTES>>>(Mb);
    top9_final_kernel<<<BATCH, 128>>>(E, Mb, out);
}

// round 15
// speedup vs baseline: 17.4346x; 1.0022x over previous
#include <cuda_runtime.h>
#include <cuda_bf16.h>
#include <math.h>
#include <stdint.h>

#define N_EMB 12544
#define M_BANK 16384
#define DIM 1536
#define BATCH 16
#define PPI 784
#define KNN 9

// ---- Phase A tiling (int8 mma.m16n8k32), 2 CTAs/SM, BK=128 ----
#define BM 128
#define BN 128
#define BK 128
#define KTILES (DIM / BK)          // 12
#define NSTAGE 3
#define STRIDE_B 144               // 128 data + 16 pad -> conflict-free ldmatrix
#define A_BYTES (BM * STRIDE_B)
#define B_BYTES (BN * STRIDE_B)
#define STAGE_BYTES (A_BYTES + B_BYTES)   // 36864
#define SMEM_BYTES (NSTAGE * STAGE_BYTES) // 110592
#define GRIDX (N_EMB / BM)         // 98
#define GRIDY (M_BANK / BN)        // 128
#define SWG 8

#define QSCALE 23.0f

// ---- scan kernels: staged layout, 3 chunk buffers ----
#define QS_FLOATS (16 * DIM)             // 24576 floats = 96 KB
#define CH_FLOATS 4096                   // 128 cols x 32 dims = 16 KB
#define CH_BYTES  16384
#define NCHUNK (DIM / 32)                // 48
#define QS2_BYTES ((QS_FLOATS + 3 * CH_FLOATS) * 4)   // 147456

// ---------------- scratch ----------------
__device__ char  g_E8[N_EMB * DIM];
__device__ char  g_M8[M_BANK * DIM];
__device__ int   g_ynq[M_BANK];
__device__ unsigned long long g_minpack[N_EMB];
__device__ unsigned long long g_nnpack[BATCH];
__device__ unsigned long long g_maxpack[BATCH];   // (fkey(score) << 32) | (PPI-1-p)
__device__ float g_xnorm[N_EMB];
__device__ float g_ynorm[M_BANK];
__device__ float g_d2[BATCH * M_BANK];

__device__ __forceinline__ unsigned fkey(float f) {
    unsigned u = __float_as_uint(f);
    return (u & 0x80000000u) ? ~u : (u | 0x80000000u);
}
__device__ __forceinline__ float unkey(unsigned k) {
    unsigned u = (k & 0x80000000u) ? (k ^ 0x80000000u) : ~k;
    return __uint_as_float(u);
}

__device__ __forceinline__ void cpasync16(uint32_t dst, const void* src) {
    asm volatile("cp.async.cg.shared.global [%0], [%1], 16;" :: "r"(dst), "l"(src));
}
__device__ __forceinline__ void ldsm4(uint32_t* r, uint32_t addr) {
    asm volatile("ldmatrix.sync.aligned.m8n8.x4.shared.b16 {%0,%1,%2,%3}, [%4];"
                 : "=r"(r[0]), "=r"(r[1]), "=r"(r[2]), "=r"(r[3]) : "r"(addr));
}
__device__ __forceinline__ void mma_s8(int* c, const uint32_t* a, uint32_t b0, uint32_t b1) {
    asm volatile("mma.sync.aligned.m16n8k32.row.col.s32.s8.s8.s32 "
                 "{%0,%1,%2,%3}, {%4,%5,%6,%7}, {%8,%9}, {%0,%1,%2,%3};"
                 : "+r"(c[0]), "+r"(c[1]), "+r"(c[2]), "+r"(c[3])
                 : "r"(a[0]), "r"(a[1]), "r"(a[2]), "r"(a[3]), "r"(b0), "r"(b1));
}

// packed f32x2 helpers (baseline sm_100 PTX, not an 'a'-accelerated feature)
__device__ __forceinline__ void lds_v2b64(uint64_t& a, uint64_t& b, uint32_t addr) {
    asm volatile("ld.shared.v2.b64 {%0,%1}, [%2];" : "=l"(a), "=l"(b) : "r"(addr));
}
__device__ __forceinline__ uint64_t fma2(uint64_t a, uint64_t b, uint64_t c) {
    uint64_t d;
    asm("fma.rn.f32x2 %0, %1, %2, %3;" : "=l"(d) : "l"(a), "l"(b), "l"(c));
    return d;
}
__device__ __forceinline__ float upsum(uint64_t p) {
    uint32_t lo, hi;
    asm("mov.b64 {%0,%1}, %2;" : "=r"(lo), "=r"(hi) : "l"(p));
    return __uint_as_float(lo) + __uint_as_float(hi);
}

__device__ __forceinline__ int q8(float x) {
    int v = __float2int_rn(x * QSCALE);
    return max(-127, min(127, v));
}

// ---------------- fused convert-to-int8 + norms + scratch init ----------------
__global__ void convert_norms_kernel(const float* __restrict__ E, const float* __restrict__ Mb) {
    int row = blockIdx.x;
    const bool isE = row < N_EMB;
    const float* p = isE ? (E + (size_t)row * DIM) : (Mb + (size_t)(row - N_EMB) * DIM);
    char* q = isE ? (g_E8 + (size_t)row * DIM) : (g_M8 + (size_t)(row - N_EMB) * DIM);
    float s = 0.f;
    int   sq = 0;
    for (int i = threadIdx.x; i < DIM / 4; i += blockDim.x) {
        float4 v = ((const float4*)p)[i];
        s += v.x * v.x + v.y * v.y + v.z * v.z + v.w * v.w;
        int a = q8(v.x), b = q8(v.y), c = q8(v.z), d = q8(v.w);
        sq += a * a + b * b + c * c + d * d;
        uint32_t pk = (uint32_t)(a & 0xff) | ((uint32_t)(b & 0xff) << 8) |
                      ((uint32_t)(c & 0xff) << 16) | ((uint32_t)(d & 0xff) << 24);
        ((uint32_t*)q)[i] = pk;
    }
#pragma unroll
    for (int o = 16; o; o >>= 1) {
        s  += __shfl_down_sync(0xffffffffu, s, o);
        sq += __shfl_down_sync(0xffffffffu, sq, o);
    }
    __shared__ float ws[4];
    __shared__ int   wq[4];
    if ((threadIdx.x & 31) == 0) { ws[threadIdx.x >> 5] = s; wq[threadIdx.x >> 5] = sq; }
    __syncthreads();
    if (threadIdx.x == 0) {
        float t = ws[0] + ws[1] + ws[2] + ws[3];
        int   ti = wq[0] + wq[1] + wq[2] + wq[3];
        if (isE) {
            g_xnorm[row] = t;
            g_minpack[row] = 0xFFFFFFFFFFFFFFFFull;
            if (row < BATCH) { g_nnpack[row] = 0xFFFFFFFFFFFFFFFFull; g_maxpack[row] = 0ull; }
        } else {
            g_ynorm[row - N_EMB] = t; g_ynq[row - N_EMB] = ti;
        }
    }
}

// ---------------- Phase A: int8 tensor-core dist-argmin GEMM ----------------
__global__ void __launch_bounds__(256, 2) distmin_s8() {
    extern __shared__ char dsm[];
    const int tid = threadIdx.x;
    const int lane = tid & 31, warp = tid >> 5;
    const int wr = warp & 3, wc = warp >> 2;

    const int band = blockIdx.x / (GRIDX * SWG);
    const int rem  = blockIdx.x % (GRIDX * SWG);
    const int by   = band * SWG + (rem % SWG);
    const int bx   = rem / SWG;
    const int rowBase = bx * BM;
    const int colBase = by * BN;

    uint32_t sbase = (uint32_t)__cvta_generic_to_shared(dsm);

    const char* src[8];
    uint32_t dsto[8];
#pragma unroll
    for (int i = 0; i < 8; i++) {
        int idx = tid + i * 256;
        if (idx < 1024) {
            int row = idx >> 3, c = idx & 7;
            src[i]  = g_E8 + (size_t)(rowBase + row) * DIM + c * 16;
            dsto[i] = row * STRIDE_B + c * 16;
        } else {
            int j = idx - 1024;
            int row = j >> 3, c = j & 7;
            src[i]  = g_M8 + (size_t)(colBase + row) * DIM + c * 16;
            dsto[i] = A_BYTES + row * STRIDE_B + c * 16;
        }
    }

    const int arow = (lane & 7) + ((lane >> 3) & 1) * 8;
    const uint32_t akb = (lane >> 4) * 16;
    uint32_t aAddr[2];
#pragma unroll
    for (int m = 0; m < 2; m++)
        aAddr[m] = sbase + (wr * 32 + m * 16 + arow) * STRIDE_B + akb;
    const int brow = (lane & 7) + (lane >> 4) * 8;
    const uint32_t bkb = ((lane >> 3) & 1) * 16;
    uint32_t bAddr[4];
#pragma unroll
    for (int g = 0; g < 4; g++)
        bAddr[g] = sbase + A_BYTES + (wc * 64 + g * 16 + brow) * STRIDE_B + bkb;

    int acc[2][8][4];
#pragma unroll
    for (int m = 0; m < 2; m++)
#pragma unroll
        for (int t = 0; t < 8; t++)
#pragma unroll
            for (int c = 0; c < 4; c++) acc[m][t][c] = 0;

#pragma unroll
    for (int s = 0; s < NSTAGE - 1; s++) {
#pragma unroll
        for (int i = 0; i < 8; i++) cpasync16(sbase + s * STAGE_BYTES + dsto[i], src[i] + s * BK);
        asm volatile("cp.async.commit_group;");
    }

#pragma unroll
    for (int kt = 0; kt < KTILES; kt++) {
        const int st = kt % NSTAGE;
        asm volatile("cp.async.wait_group %0;" :: "n"(NSTAGE - 2));
        __syncthreads();
        if (kt + NSTAGE - 1 < KTILES) {
            const int ps = (kt + NSTAGE - 1) % NSTAGE;
            const int ko = (kt + NSTAGE - 1) * BK;
#pragma unroll
            for (int i = 0; i < 8; i++) cpasync16(sbase + ps * STAGE_BYTES + dsto[i], src[i] + ko);
            asm volatile("cp.async.commit_group;");
        }
        const uint32_t so = st * STAGE_BYTES;
#pragma unroll
        for (int s = 0; s < 4; s++) {
            uint32_t af[2][4], bf[4][4];
#pragma unroll
            for (int m = 0; m < 2; m++) ldsm4(af[m], aAddr[m] + so + s * 32);
#pragma unroll
            for (int g = 0; g < 4; g++) ldsm4(bf[g], bAddr[g] + so + s * 32);
#pragma unroll
            for (int m = 0; m < 2; m++)
#pragma unroll
                for (int t = 0; t < 8; t++)
                    mma_s8(acc[m][t], af[m], bf[t >> 1][(t & 1) * 2], bf[t >> 1][(t & 1) * 2 + 1]);
        }
    }
    __syncthreads();

    const int gid = lane >> 2, qid = lane & 3;
    unsigned long long* red = (unsigned long long*)dsm;
#pragma unroll
    for (int m = 0; m < 2; m++)
#pragma unroll
        for (int h = 0; h < 2; h++) {
            int bv = 0x7fffffff;
            int bj = 0x7fffffff;
#pragma unroll
            for (int t = 0; t < 8; t++)
#pragma unroll
                for (int c = 0; c < 2; c++) {
                    int col = colBase + wc * 64 + t * 8 + qid * 2 + c;
                    int q = g_ynq[col] - 2 * acc[m][t][h * 2 + c];
                    if (q < bv || (q == bv && col < bj)) { bv = q; bj = col; }
                }
#pragma unroll
            for (int off = 1; off < 4; off <<= 1) {
                int ov = __shfl_xor_sync(0xffffffffu, bv, off, 4);
                int oj = __shfl_xor_sync(0xffffffffu, bj, off, 4);
                if (ov < bv || (ov == bv && oj < bj)) { bv = ov; bj = oj; }
            }
            if (qid == 0) {
                int rloc = wr * 32 + m * 16 + h * 8 + gid;
                unsigned ku = (unsigned)bv ^ 0x80000000u;
                red[wc * 128 + rloc] = ((unsigned long long)ku << 32) | (unsigned)bj;
            }
        }
    __syncthreads();
    if (tid < BM) {
        unsigned long long p = red[tid];
        unsigned long long q1 = red[128 + tid]; if (q1 < p) p = q1;
        atomicMin(&g_minpack[rowBase + tid], p);
    }
}

// ---------------- exact fp32 rescore + fused per-image argmax ----------------
__global__ void rescore_kernel(const float* __restrict__ E, const float* __restrict__ Mb) {
    int warp = threadIdx.x >> 5, lane = threadIdx.x & 31;
    int row = blockIdx.x * 8 + warp;
    int col = (int)(g_minpack[row] & 0xffffffffull);
    const float4* x = (const float4*)(E + (size_t)row * DIM);
    const float4* y = (const float4*)(Mb + (size_t)col * DIM);
    float s = 0.f;
    for (int i = lane; i < DIM / 4; i += 32) {
        float4 a = x[i], b = y[i];
        s += a.x * b.x + a.y * b.y + a.z * b.z + a.w * b.w;
    }
#pragma unroll
    for (int o = 16; o; o >>= 1) s += __shfl_down_sync(0xffffffffu, s, o);
    if (lane == 0) {
        float d2 = g_xnorm[row] + g_ynorm[col] - 2.f * s;
        float sc = sqrtf(fmaxf(d2, 0.f));
        int b = row / PPI, p = row % PPI;
        unsigned long long pk = ((unsigned long long)fkey(sc) << 32) | (unsigned)(PPI - 1 - p);
        atomicMax(&g_maxpack[b], pk);
    }
}

// ---------------- exact fp32 NN search for the 16 argmax rows ----------------
// 512 = 64 col-slots x 8 D-groups; Mb streamed via 3-buffered 16KB chunks; f32x2 FMA
__global__ void __launch_bounds__(512) exactnn_kernel(const float* __restrict__ E,
                                                      const float* __restrict__ Mb) {
    extern __shared__ float Qs[];          // queries + 3 chunk bufs
    float* CS = Qs + QS_FLOATS;
    __shared__ int qr[16];
    __shared__ unsigned long long part[16];
    const int tid = threadIdx.x;
    const int s = tid & 63, g = tid >> 6;
    const int colBase0 = blockIdx.x * 128;
    const uint32_t csBase = (uint32_t)__cvta_generic_to_shared(CS);
    const uint32_t qsBase = (uint32_t)__cvta_generic_to_shared(Qs);
    const int c0 = tid >> 3, j0 = tid & 7;
    const int c1 = (tid + 512) >> 3, j1 = tid & 7;
    const uint32_t d0off = c0 * 128 + (((j0 + c0) & 7) << 4);
    const uint32_t d1off = c1 * 128 + (((j1 + c1) & 7) << 4);
    const float* s0 = Mb + (size_t)(colBase0 + c0) * DIM + j0 * 4;
    const float* s1 = Mb + (size_t)(colBase0 + c1) * DIM + j1 * 4;

    if (tid < 16) {
        int p = PPI - 1 - (int)(g_maxpack[tid] & 0xffffffffull);
        qr[tid] = tid * PPI + p;
        part[tid] = 0xFFFFFFFFFFFFFFFFull;
    }
    // prologue: stage chunks 0,1
#pragma unroll
    for (int pc = 0; pc < 2; pc++) {
        cpasync16(csBase + pc * CH_BYTES + d0off, s0 + pc * 32);
        cpasync16(csBase + pc * CH_BYTES + d1off, s1 + pc * 32);
        asm volatile("cp.async.commit_group;");
    }
    __syncthreads();   // qr visible for Q staging
    for (int i = tid; i < QS_FLOATS / 4; i += 512) {
        int q = i / 384, d4 = i % 384;
        ((float4*)Qs)[i] = ((const float4*)(E + (size_t)qr[q] * DIM))[d4];
    }

    uint64_t a0[16], a1[16];
#pragma unroll
    for (int q = 0; q < 16; q++) { a0[q] = 0ull; a1[q] = 0ull; }
    const uint32_t sw = ((g + s) & 7) << 4;
    const uint32_t v0base = csBase + s * 128 + sw;
    const uint32_t v1base = csBase + (s + 64) * 128 + sw;

    for (int ch = 0; ch < NCHUNK; ch++) {
        const int buf = ch % 3;
        if (ch + 1 < NCHUNK) asm volatile("cp.async.wait_group 1;");
        else                 asm volatile("cp.async.wait_group 0;");
        __syncthreads();     // chunk ch visible; buffer (ch+2)%3 fully drained
        if (ch + 2 < NCHUNK) {
            const int nb = (ch + 2) % 3;
            cpasync16(csBase + nb * CH_BYTES + d0off, s0 + (ch + 2) * 32);
            cpasync16(csBase + nb * CH_BYTES + d1off, s1 + (ch + 2) * 32);
            asm volatile("cp.async.commit_group;");
        }
        uint64_t vA0, vB0, vA1, vB1;
        lds_v2b64(vA0, vB0, v0base + buf * CH_BYTES);
        lds_v2b64(vA1, vB1, v1base + buf * CH_BYTES);
        const uint32_t qaddr = qsBase + (ch * 8 + g) * 16;
#pragma unroll
        for (int q = 0; q < 16; q++) {
            uint64_t uA, uB;
            lds_v2b64(uA, uB, qaddr + q * 6144);
            a0[q] = fma2(vA0, uA, fma2(vB0, uB, a0[q]));
            a1[q] = fma2(vA1, uA, fma2(vB1, uB, a1[q]));
        }
    }
    __syncthreads();   // all Q reads done; reuse Qs as reduction buffer

    float* red = Qs;                       // red[qc*512 + g*64 + s], 64 KB
#pragma unroll
    for (int q = 0; q < 16; q++) {
        red[q * 512 + g * 64 + s]        = upsum(a0[q]);
        red[(16 + q) * 512 + g * 64 + s] = upsum(a1[q]);
    }
    __syncthreads();
    if (g == 0) {
        const int col0 = colBase0 + s, col1 = col0 + 64;
        float yn0 = g_ynorm[col0], yn1 = g_ynorm[col1];
#pragma unroll
        for (int q = 0; q < 16; q++) {
            float d0 = 0.f, d1 = 0.f;
#pragma unroll
            for (int gg = 0; gg < 8; gg++) {
                d0 += red[q * 512 + gg * 64 + s];
                d1 += red[(16 + q) * 512 + gg * 64 + s];
            }
            float xn = g_xnorm[qr[q]];
            float e0 = xn + yn0 - 2.f * d0;
            float e1 = xn + yn1 - 2.f * d1;
            atomicMin(&part[q], ((unsigned long long)fkey(e0) << 32) | (unsigned)col0);
            atomicMin(&part[q], ((unsigned long long)fkey(e1) << 32) | (unsigned)col1);
        }
    }
    __syncthreads();
    if (tid < 16) atomicMin(&g_nnpack[tid], part[tid]);
}

// ---------------- Phase C1: d^2 from 16 nn_samples to all memory rows ----------------
__global__ void __launch_bounds__(512) knn_dist_kernel(const float* __restrict__ Mb) {
    extern __shared__ float Qs[];
    float* CS = Qs + QS_FLOATS;
    __shared__ int nn[16];
    __shared__ float qn[16];
    const int tid = threadIdx.x;
    const int s = tid & 63, g = tid >> 6;
    const int colBase0 = blockIdx.x * 128;
    const uint32_t csBase = (uint32_t)__cvta_generic_to_shared(CS);
    const uint32_t qsBase = (uint32_t)__cvta_generic_to_shared(Qs);
    const int c0 = tid >> 3, j0 = tid & 7;
    const int c1 = (tid + 512) >> 3, j1 = tid & 7;
    const uint32_t d0off = c0 * 128 + (((j0 + c0) & 7) << 4);
    const uint32_t d1off = c1 * 128 + (((j1 + c1) & 7) << 4);
    const float* s0 = Mb + (size_t)(colBase0 + c0) * DIM + j0 * 4;
    const float* s1 = Mb + (size_t)(colBase0 + c1) * DIM + j1 * 4;

    if (tid < 16) {
        int idx = (int)(g_nnpack[tid] & 0xffffffffull);
        nn[tid] = idx; qn[tid] = g_ynorm[idx];
    }
#pragma unroll
    for (int pc = 0; pc < 2; pc++) {
        cpasync16(csBase + pc * CH_BYTES + d0off, s0 + pc * 32);
        cpasync16(csBase + pc * CH_BYTES + d1off, s1 + pc * 32);
        asm volatile("cp.async.commit_group;");
    }
    __syncthreads();
    for (int i = tid; i < QS_FLOATS / 4; i += 512) {
        int q = i / 384, d4 = i % 384;
        ((float4*)Qs)[i] = ((const float4*)(Mb + (size_t)nn[q] * DIM))[d4];
    }

    uint64_t a0[16], a1[16];
#pragma unroll
    for (int q = 0; q < 16; q++) { a0[q] = 0ull; a1[q] = 0ull; }
    const uint32_t sw = ((g + s) & 7) << 4;
    const uint32_t v0base = csBase + s * 128 + sw;
    const uint32_t v1base = csBase + (s + 64) * 128 + sw;

    for (int ch = 0; ch < NCHUNK; ch++) {
        const int buf = ch % 3;
        if (ch + 1 < NCHUNK) asm volatile("cp.async.wait_group 1;");
        else                 asm volatile("cp.async.wait_group 0;");
        __syncthreads();
        if (ch + 2 < NCHUNK) {
            const int nb = (ch + 2) % 3;
            cpasync16(csBase + nb * CH_BYTES + d0off, s0 + (ch + 2) * 32);
            cpasync16(csBase + nb * CH_BYTES + d1off, s1 + (ch + 2) * 32);
            asm volatile("cp.async.commit_group;");
        }
        uint64_t vA0, vB0, vA1, vB1;
        lds_v2b64(vA0, vB0, v0base + buf * CH_BYTES);
        lds_v2b64(vA1, vB1, v1base + buf * CH_BYTES);
        const uint32_t qaddr = qsBase + (ch * 8 + g) * 16;
#pragma unroll
        for (int q = 0; q < 16; q++) {
            uint64_t uA, uB;
            lds_v2b64(uA, uB, qaddr + q * 6144);
            a0[q] = fma2(vA0, uA, fma2(vB0, uB, a0[q]));
            a1[q] = fma2(vA1, uA, fma2(vB1, uB, a1[q]));
        }
    }
    __syncthreads();

    float* red = Qs;
#pragma unroll
    for (int q = 0; q < 16; q++) {
        red[q * 512 + g * 64 + s]        = upsum(a0[q]);
        red[(16 + q) * 512 + g * 64 + s] = upsum(a1[q]);
    }
    __syncthreads();
    if (g == 0) {
        const int col0 = colBase0 + s, col1 = col0 + 64;
        float yn0 = g_ynorm[col0], yn1 = g_ynorm[col1];
#pragma unroll
        for (int q = 0; q < 16; q++) {
            float d0 = 0.f, d1 = 0.f;
#pragma unroll
            for (int gg = 0; gg < 8; gg++) {
                d0 += red[q * 512 + gg * 64 + s];
                d1 += red[(16 + q) * 512 + gg * 64 + s];
            }
            g_d2[q * M_BANK + col0] = qn[q] + yn0 - 2.f * d0;
            g_d2[q * M_BANK + col1] = qn[q] + yn1 - 2.f * d1;
        }
    }
}

// ---------------- Phase C2 + D: stable top-9, distances, softmax, output ----------------
__global__ void top9_final_kernel(const float* __restrict__ E, const float* __restrict__ Mb,
                                  float* __restrict__ out) {
    int b = blockIdx.x;
    int tid = threadIdx.x;
    float v[9]; int id[9];
#pragma unroll
    for (int k = 0; k < 9; k++) { v[k] = __int_as_float(0x7f800000); id[k] = 0x7fffffff; }
    for (int j = tid; j < M_BANK; j += 128) {
        float d = g_d2[b * M_BANK + j];
        if (d < v[8] || (d == v[8] && j < id[8])) {
            int k = 8;
            while (k > 0 && (d < v[k - 1] || (d == v[k - 1] && j < id[k - 1]))) {
                v[k] = v[k - 1]; id[k] = id[k - 1]; k--;
            }
            v[k] = d; id[k] = j;
        }
    }
    __shared__ float svv[128 * 9];
    __shared__ int   sid[128 * 9];
    __shared__ int   s_sup[9];
    __shared__ float s_ds[9];
    __shared__ float s_red[4];
#pragma unroll
    for (int k = 0; k < 9; k++) { svv[tid * 9 + k] = v[k]; sid[tid * 9 + k] = id[k]; }
    __syncthreads();
    if (tid == 0) {
        float fv[9]; int fid[9];
#pragma unroll
        for (int k = 0; k < 9; k++) { fv[k] = __int_as_float(0x7f800000); fid[k] = 0x7fffffff; }
        for (int t = 0; t < 128; t++) {
            for (int k = 0; k < 9; k++) {
                float d = svv[t * 9 + k]; int j = sid[t * 9 + k];
                if (d > fv[8] || (d == fv[8] && j >= fid[8])) break;
                int m = 8;
                while (m > 0 && (d < fv[m - 1] || (d == fv[m - 1] && j < fid[m - 1]))) {
                    fv[m] = fv[m - 1]; fid[m] = fid[m - 1]; m--;
                }
                fv[m] = d; fid[m] = j;
            }
        }
        for (int k = 0; k < 9; k++) s_sup[k] = fid[k];
    }
    __syncthreads();

    unsigned long long mp = g_maxpack[b];
    int maxrow = b * PPI + (PPI - 1 - (int)(mp & 0xffffffffull));
    const float4* x = (const float4*)(E + (size_t)maxrow * DIM);
    for (int k = 0; k < 9; k++) {
        const float4* y = (const float4*)(Mb + (size_t)s_sup[k] * DIM);
        float s = 0.f;
        for (int i = tid; i < 384; i += 128) {
            float4 xv = x[i], yv = y[i];
            float dx = xv.x - yv.x, dy = xv.y - yv.y, dz = xv.z - yv.z, dw = xv.w - yv.w;
            s += dx * dx + dy * dy + dz * dz + dw * dw;
        }
#pragma unroll
        for (int o = 16; o; o >>= 1) s += __shfl_down_sync(0xffffffffu, s, o);
        if ((tid & 31) == 0) s_red[tid >> 5] = s;
        __syncthreads();
        if (tid == 0) s_ds[k] = sqrtf(fmaxf(s_red[0] + s_red[1] + s_red[2] + s_red[3], 0.f));
        __syncthreads();
    }
    if (tid == 0) {
        float m = s_ds[0];
        for (int k = 1; k < 9; k++) m = fmaxf(m, s_ds[k]);
        float sum = 0.f, e0 = 0.f;
        for (int k = 0; k < 9; k++) {
            float e = expf(s_ds[k] - m);
            if (k == 0) e0 = e;
            sum += e;
        }
        out[b] = (1.f - e0 / sum) * unkey((unsigned)(mp >> 32));
    }
}

// ---------------- launch ----------------
extern "C" void kernel_launch(void* const* d_in, const int* in_sizes, int n_in,
                              void* d_out, int out_size) {
    const float* E  = (const float*)d_in[0];
    const float* Mb = (const float*)d_in[1];
    float* out = (float*)d_out;

    cudaFuncSetAttribute(distmin_s8, cudaFuncAttributeMaxDynamicSharedMemorySize, SMEM_BYTES);
    cudaFuncSetAttribute(exactnn_kernel, cudaFuncAttributeMaxDynamicSharedMemorySize, QS2_BYTES);
    cudaFuncSetAttribute(knn_dist_kernel, cudaFuncAttributeMaxDynamicSharedMemorySize, QS2_BYTES);

    convert_norms_kernel<<<N_EMB + M_BANK, 128>>>(E, Mb);
    distmin_s8<<<GRIDX * GRIDY, 256, SMEM_BYTES>>>();
    rescore_kernel<<<N_EMB / 8, 256>>>(E, Mb);
    exactnn_kernel<<<M_BANK / 128, 512, QS2_BYTES>>>(E, Mb);
    knn_dist_kernel<<<M_BANK / 128, 512, QS2_BYTES>>>(Mb);
    top9_final_kernel<<<BATCH, 128>>>(E, Mb, out);
}